// round 9
// baseline (speedup 1.0000x reference)
#include <cuda_runtime.h>
#include <math.h>
#include <stdint.h>

#define DD   1024
#define HH   16
#define DHH  64
#define BB   4
#define LL   512
#define TT   2048
#define EE   8
#define KKE  2
#define DFFN 4096
#define NL   (BB*LL)
#define NT   (BB*TT)
#define BHN  (BB*HH)
#define LN_EPS 1e-5f

// ---------------- scratch ----------------
__device__ float g_lnq[(size_t)NL*DD];
__device__ float g_lnr[(size_t)NL*DD];
__device__ float g_lnt[(size_t)NT*DD];
__device__ float g_qkv[(size_t)NL*3*DD];
__device__ float g_q2 [(size_t)NL*DD];
__device__ float g_kv [(size_t)NT*2*DD];
__device__ float g_attn[(size_t)NL*DD];
__device__ float g_x1 [(size_t)NL*DD];
__device__ float g_x2 [(size_t)NL*DD];
__device__ float g_h1 [(size_t)NL*KKE*DFFN];
__device__ float g_eo [(size_t)NL*KKE*DD];
__device__ int   g_idx [NL*KKE];
__device__ float g_gate[NL*KKE];
__device__ int   g_cnt[EE];
__device__ int   g_off[EE];
__device__ int   g_cur[EE];
__device__ int   g_rowlist[NL*KKE];
__device__ int   g_pairslot[NL*KKE];

// ---------------- helpers ----------------
__device__ __forceinline__ float blk_sum(float v) {
    __shared__ float sh[32];
    int lane = threadIdx.x & 31, w = threadIdx.x >> 5;
    #pragma unroll
    for (int o = 16; o; o >>= 1) v += __shfl_xor_sync(0xffffffffu, v, o);
    if (lane == 0) sh[w] = v;
    __syncthreads();
    if (w == 0) {
        float x = (lane < (int)(blockDim.x >> 5)) ? sh[lane] : 0.f;
        #pragma unroll
        for (int o = 16; o; o >>= 1) x += __shfl_xor_sync(0xffffffffu, x, o);
        if (lane == 0) sh[0] = x;
    }
    __syncthreads();
    float r = sh[0];
    __syncthreads();
    return r;
}

__device__ __forceinline__ float gelu_exact(float x) {
    return 0.5f * x * (1.f + erff(x * 0.70710678118654752f));
}

// ---------------- tf32 mma primitives ----------------
__device__ __forceinline__ uint32_t f2tf(float f) {
    uint32_t u;
    asm("cvt.rna.tf32.f32 %0, %1;" : "=r"(u) : "f"(f));
    return u;
}
__device__ __forceinline__ float rnd_tf(float f) { return __uint_as_float(f2tf(f)); }

__device__ __forceinline__ void mma8(float* cr, const uint32_t* a, const uint32_t* b) {
    asm volatile(
        "mma.sync.aligned.m16n8k8.row.col.f32.tf32.tf32.f32 "
        "{%0,%1,%2,%3}, {%4,%5,%6,%7}, {%8,%9}, {%0,%1,%2,%3};"
        : "+f"(cr[0]), "+f"(cr[1]), "+f"(cr[2]), "+f"(cr[3])
        : "r"(a[0]), "r"(a[1]), "r"(a[2]), "r"(a[3]), "r"(b[0]), "r"(b[1]));
}

__device__ __forceinline__ void ldsm4(uint32_t* r, uint32_t addr) {
    asm volatile("ldmatrix.sync.aligned.m8n8.x4.shared.b16 {%0,%1,%2,%3}, [%4];"
        : "=r"(r[0]), "=r"(r[1]), "=r"(r[2]), "=r"(r[3]) : "r"(addr));
}

__device__ __forceinline__ void cp16(uint32_t dst, const void* src) {
    asm volatile("cp.async.cg.shared.global [%0], [%1], 16;" :: "r"(dst), "l"(src));
}
__device__ __forceinline__ void cp16p(uint32_t dst, const void* src, bool valid) {
    int sz = valid ? 16 : 0;
    asm volatile("cp.async.cg.shared.global [%0], [%1], 16, %2;" :: "r"(dst), "l"(src), "r"(sz));
}
__device__ __forceinline__ void cpcommit() { asm volatile("cp.async.commit_group;"); }
__device__ __forceinline__ void cpwait1() { asm volatile("cp.async.wait_group 1;"); }
__device__ __forceinline__ void cpwait0() { asm volatile("cp.async.wait_group 0;"); }

// 3-stage ring: per stage [A 128x36 | B 128x36]
#define TILE_AB (128*36)
#define STAGE_F (2*TILE_AB)
#define NST 3
#define GEMM_SMEM (NST*STAGE_F*4)   /* 110592 B */

// one 32-k slab via ldmatrix, software-pipelined: LDSM(kk+1) issued BEFORE HMMA(kk)
// so tensor work covers shared-load latency despite volatile ordering.
__device__ __forceinline__ void mma_slab(uint32_t a_base, uint32_t b_base,
                                         float (&acc)[4][4][4]) {
    uint32_t af[2][4][4];
    uint32_t bq[2][2][4];
    #pragma unroll
    for (int mi = 0; mi < 4; mi++) ldsm4(af[0][mi], a_base + (mi * 16 * 36) * 4);
    #pragma unroll
    for (int np = 0; np < 2; np++) ldsm4(bq[0][np], b_base + (np * 16 * 36) * 4);
    #pragma unroll
    for (int kk = 0; kk < 4; kk++) {
        const int cur = kk & 1, nxt = cur ^ 1;
        if (kk < 3) {
            #pragma unroll
            for (int mi = 0; mi < 4; mi++)
                ldsm4(af[nxt][mi], a_base + (mi * 16 * 36 + (kk + 1) * 8) * 4);
            #pragma unroll
            for (int np = 0; np < 2; np++)
                ldsm4(bq[nxt][np], b_base + (np * 16 * 36 + (kk + 1) * 8) * 4);
        }
        // cvt B in place (A pre-rounded at producer)
        #pragma unroll
        for (int np = 0; np < 2; np++)
            #pragma unroll
            for (int q = 0; q < 4; q++)
                bq[cur][np][q] = f2tf(__uint_as_float(bq[cur][np][q]));
        #pragma unroll
        for (int mi = 0; mi < 4; mi++) {
            #pragma unroll
            for (int np = 0; np < 2; np++) {
                mma8(acc[mi][np * 2 + 0], af[cur][mi], &bq[cur][np][0]);
                mma8(acc[mi][np * 2 + 1], af[cur][mi], &bq[cur][np][2]);
            }
        }
    }
}

// float-smem slab for flash attention (cvt inline; compiler-scheduled loads).
template<int WM, int WN, bool BKN, int AST2, int BST>
__device__ __forceinline__ void mma_tile(const float* __restrict__ Ab,
                                         const float* __restrict__ Bb,
                                         int wm, int wn, int g, int c,
                                         float (&acc)[WM][WN][4]) {
    #pragma unroll
    for (int kk = 0; kk < 4; kk++) {
        const int k0 = kk * 8;
        uint32_t af[WM][4];
        #pragma unroll
        for (int mi = 0; mi < WM; mi++) {
            const float* Ar = Ab + (wm + mi * 16 + g) * AST2 + k0 + c;
            af[mi][0] = f2tf(Ar[0]);
            af[mi][1] = f2tf(Ar[8 * AST2]);
            af[mi][2] = f2tf(Ar[4]);
            af[mi][3] = f2tf(Ar[8 * AST2 + 4]);
        }
        uint32_t bf[WN][2];
        #pragma unroll
        for (int ni = 0; ni < WN; ni++) {
            if (BKN) {
                const float* Br = Bb + (k0 + c) * BST + wn + ni * 8 + g;
                bf[ni][0] = f2tf(Br[0]);
                bf[ni][1] = f2tf(Br[4 * BST]);
            } else {
                const float* Br = Bb + (wn + ni * 8 + g) * BST + k0 + c;
                bf[ni][0] = f2tf(Br[0]);
                bf[ni][1] = f2tf(Br[4]);
            }
        }
        #pragma unroll
        for (int mi = 0; mi < WM; mi++)
            #pragma unroll
            for (int ni = 0; ni < WN; ni++)
                mma8(acc[mi][ni], af[mi], bf[ni]);
    }
}

// ---------------- layernorm ----------------
__global__ void __launch_bounds__(256) ln_kernel(const float* __restrict__ x,
                                                 const float* __restrict__ g,
                                                 const float* __restrict__ b,
                                                 float* __restrict__ y,
                                                 float* __restrict__ yraw) {
    size_t row = blockIdx.x;
    const float* xr = x + row * DD;
    float* yr = y + row * DD;
    int t = threadIdx.x;
    float v[4];
    float s = 0.f;
    #pragma unroll
    for (int i = 0; i < 4; i++) { v[i] = xr[t + 256 * i]; s += v[i]; }
    s = blk_sum(s);
    float mean = s * (1.f / DD);
    float s2 = 0.f;
    #pragma unroll
    for (int i = 0; i < 4; i++) { float d = v[i] - mean; s2 += d * d; }
    s2 = blk_sum(s2);
    float inv = rsqrtf(s2 * (1.f / DD) + LN_EPS);
    #pragma unroll
    for (int i = 0; i < 4; i++) {
        int cc = t + 256 * i;
        float o = (v[i] - mean) * inv * g[cc] + b[cc];
        yr[cc] = rnd_tf(o);
        if (yraw) yraw[row * DD + cc] = o;
    }
}

// ---------------- tf32 GEMM: 128x128, 3-stage cp.async + pipelined ldmatrix ----------------
__global__ void __launch_bounds__(256, 2) gemm_tf32(const float* __restrict__ A, int lda,
                                                    const float* __restrict__ W, int ldw,
                                                    float* __restrict__ C, int ldc,
                                                    const float* __restrict__ bias,
                                                    const float* __restrict__ resid, int ldr,
                                                    int Kd, int round_out) {
    extern __shared__ float sm[];
    int t = threadIdx.x;
    int row0 = blockIdx.y * 128, col0 = blockIdx.x * 128;
    int lrow = t >> 1, lcol = (t & 1) * 16;
    const float* Ag = A + (size_t)(row0 + lrow) * lda + lcol;
    const float* Wg = W + (size_t)(col0 + lrow) * ldw + lcol;
    uint32_t sm_u = (uint32_t)__cvta_generic_to_shared(sm);
    uint32_t as0 = sm_u + (lrow * 36 + lcol) * 4;
    uint32_t bs0 = sm_u + (TILE_AB + lrow * 36 + lcol) * 4;
    int warp = t >> 5, lane = t & 31, g = lane >> 2, c = lane & 3;
    int wm = (warp >> 2) * 64, wn = (warp & 3) * 32;
    uint32_t a_frag = sm_u + ((wm + (lane & 15)) * 36 + (lane >> 4) * 4) * 4;
    uint32_t b_frag = sm_u + (TILE_AB + (wn + ((lane >> 4) << 3) + (lane & 7)) * 36 + ((lane >> 3) & 1) * 4) * 4;
    float acc[4][4][4] = {};
    int KT = Kd >> 5;
    #pragma unroll
    for (int s = 0; s < 2; s++) {
        const float* a = Ag + s * 32;
        const float* w = Wg + s * 32;
        uint32_t so = (uint32_t)(s * STAGE_F * 4);
        #pragma unroll
        for (int i = 0; i < 4; i++) cp16(as0 + so + i * 16, a + i * 4);
        #pragma unroll
        for (int i = 0; i < 4; i++) cp16(bs0 + so + i * 16, w + i * 4);
        cpcommit();
    }
    int sl = 0;
    for (int kt = 0; kt < KT; kt++) {
        cpwait1();
        __syncthreads();
        if (kt + 2 < KT) {
            int sn = sl + 2; if (sn >= NST) sn -= NST;
            const float* a = Ag + (kt + 2) * 32;
            const float* w = Wg + (kt + 2) * 32;
            uint32_t so = (uint32_t)(sn * STAGE_F * 4);
            #pragma unroll
            for (int i = 0; i < 4; i++) cp16(as0 + so + i * 16, a + i * 4);
            #pragma unroll
            for (int i = 0; i < 4; i++) cp16(bs0 + so + i * 16, w + i * 4);
            cpcommit();
        }
        uint32_t so = (uint32_t)(sl * STAGE_F * 4);
        mma_slab(a_frag + so, b_frag + so, acc);
        if (++sl == NST) sl = 0;
    }
    #pragma unroll
    for (int mi = 0; mi < 4; mi++) {
        int r = row0 + wm + mi * 16 + g;
        #pragma unroll
        for (int ni = 0; ni < 4; ni++) {
            int cc = col0 + wn + ni * 8 + c * 2;
            float v0 = acc[mi][ni][0], v1 = acc[mi][ni][1];
            float v2 = acc[mi][ni][2], v3 = acc[mi][ni][3];
            if (bias) { float b0 = bias[cc], b1 = bias[cc + 1]; v0 += b0; v1 += b1; v2 += b0; v3 += b1; }
            if (resid) {
                const float* q0 = resid + (size_t)r * ldr + cc;
                const float* q1 = resid + (size_t)(r + 8) * ldr + cc;
                v0 += q0[0]; v1 += q0[1]; v2 += q1[0]; v3 += q1[1];
            }
            if (round_out) { v0 = rnd_tf(v0); v1 = rnd_tf(v1); v2 = rnd_tf(v2); v3 = rnd_tf(v3); }
            *(float2*)(C + (size_t)r * ldc + cc) = make_float2(v0, v1);
            *(float2*)(C + (size_t)(r + 8) * ldc + cc) = make_float2(v2, v3);
        }
    }
}

// ---------------- fused flash attention (tf32, unchanged) ----------------
#define FA_N 64
#define FA_QS (128*68)
#define FA_KV (64*68)
#define FA_SMEM ((FA_QS + 4*FA_KV + FA_QS)*4)

__global__ void __launch_bounds__(256) flash_tf32(const float* __restrict__ Q, int ldq,
                                                  const float* __restrict__ Kp, int ldk,
                                                  const float* __restrict__ Vp, int ldv,
                                                  float* __restrict__ O, int Lk, float scale) {
    extern __shared__ float sm[];
    float* Qs = sm;
    float* Ks = Qs + FA_QS;
    float* Vs = Ks + 2 * FA_KV;
    float* Ps = Vs + 2 * FA_KV;
    int bh = blockIdx.y, b = bh >> 4, h = bh & 15;
    int q0 = blockIdx.x * 128;
    int t = threadIdx.x;
    const float* Qg = Q + ((size_t)(b * LL + q0)) * ldq + h * DHH;
    const float* Kg = Kp + ((size_t)b * Lk) * ldk + h * DHH;
    const float* Vg = Vp + ((size_t)b * Lk) * ldv + h * DHH;
    uint32_t qs0 = (uint32_t)__cvta_generic_to_shared(Qs);
    uint32_t ks0 = (uint32_t)__cvta_generic_to_shared(Ks);
    uint32_t vs0 = (uint32_t)__cvta_generic_to_shared(Vs);
    {
        int row = t >> 1, segb = (t & 1) * 8;
        const float* qr = Qg + (size_t)row * ldq;
        #pragma unroll
        for (int j = 0; j < 8; j++)
            cp16(qs0 + (row * 68 + (segb + j) * 4) * 4, qr + (segb + j) * 4);
    }
    int kr = t >> 2, kcb = (t & 3) * 16;
    {
        const float* kg = Kg + (size_t)kr * ldk + kcb;
        const float* vg = Vg + (size_t)kr * ldv + kcb;
        uint32_t kb = ks0 + (kr * 68 + kcb) * 4;
        uint32_t vb = vs0 + (kr * 68 + kcb) * 4;
        #pragma unroll
        for (int j = 0; j < 4; j++) cp16(kb + j * 16, kg + j * 4);
        #pragma unroll
        for (int j = 0; j < 4; j++) cp16(vb + j * 16, vg + j * 4);
    }
    cpcommit();
    int warp = t >> 5, lane = t & 31, g = lane >> 2, c = lane & 3;
    int wr = warp * 16;
    float Oa[1][8][4] = {};
    float m0 = -INFINITY, m1 = -INFINITY, l0 = 0.f, l1 = 0.f;
    int niter = Lk / FA_N;
    for (int it = 0; it < niter; it++) {
        if (it + 1 < niter) {
            int buf = (it + 1) & 1;
            const float* kg = Kg + (size_t)((it + 1) * FA_N + kr) * ldk + kcb;
            const float* vg = Vg + (size_t)((it + 1) * FA_N + kr) * ldv + kcb;
            uint32_t kb = ks0 + (buf * FA_KV + kr * 68 + kcb) * 4;
            uint32_t vb = vs0 + (buf * FA_KV + kr * 68 + kcb) * 4;
            #pragma unroll
            for (int j = 0; j < 4; j++) cp16(kb + j * 16, kg + j * 4);
            #pragma unroll
            for (int j = 0; j < 4; j++) cp16(vb + j * 16, vg + j * 4);
            cpcommit();
            cpwait1();
        } else cpwait0();
        __syncthreads();
        const float* Kb = Ks + (it & 1) * FA_KV;
        const float* Vb = Vs + (it & 1) * FA_KV;
        float S[1][8][4] = {};
        mma_tile<1, 8, false, 68, 68>(Qs, Kb, wr, 0, g, c, S);
        mma_tile<1, 8, false, 68, 68>(Qs + 32, Kb + 32, wr, 0, g, c, S);
        float rm0 = -INFINITY, rm1 = -INFINITY;
        #pragma unroll
        for (int ni = 0; ni < 8; ni++) {
            #pragma unroll
            for (int j = 0; j < 4; j++) S[0][ni][j] *= scale;
            rm0 = fmaxf(rm0, fmaxf(S[0][ni][0], S[0][ni][1]));
            rm1 = fmaxf(rm1, fmaxf(S[0][ni][2], S[0][ni][3]));
        }
        rm0 = fmaxf(rm0, __shfl_xor_sync(0xffffffffu, rm0, 1));
        rm0 = fmaxf(rm0, __shfl_xor_sync(0xffffffffu, rm0, 2));
        rm1 = fmaxf(rm1, __shfl_xor_sync(0xffffffffu, rm1, 1));
        rm1 = fmaxf(rm1, __shfl_xor_sync(0xffffffffu, rm1, 2));
        float mn0 = fmaxf(m0, rm0), mn1 = fmaxf(m1, rm1);
        float a0 = __expf(m0 - mn0), a1 = __expf(m1 - mn1);
        float ps0 = 0.f, ps1 = 0.f;
        #pragma unroll
        for (int ni = 0; ni < 8; ni++) {
            float p0 = __expf(S[0][ni][0] - mn0);
            float p1 = __expf(S[0][ni][1] - mn0);
            float p2 = __expf(S[0][ni][2] - mn1);
            float p3 = __expf(S[0][ni][3] - mn1);
            ps0 += p0 + p1; ps1 += p2 + p3;
            *(float2*)&Ps[(wr + g) * 68 + ni * 8 + 2 * c] = make_float2(p0, p1);
            *(float2*)&Ps[(wr + g + 8) * 68 + ni * 8 + 2 * c] = make_float2(p2, p3);
        }
        ps0 += __shfl_xor_sync(0xffffffffu, ps0, 1);
        ps0 += __shfl_xor_sync(0xffffffffu, ps0, 2);
        ps1 += __shfl_xor_sync(0xffffffffu, ps1, 1);
        ps1 += __shfl_xor_sync(0xffffffffu, ps1, 2);
        l0 = l0 * a0 + ps0;
        l1 = l1 * a1 + ps1;
        m0 = mn0; m1 = mn1;
        #pragma unroll
        for (int ni = 0; ni < 8; ni++) {
            Oa[0][ni][0] *= a0; Oa[0][ni][1] *= a0;
            Oa[0][ni][2] *= a1; Oa[0][ni][3] *= a1;
        }
        __syncwarp();
        mma_tile<1, 8, true, 68, 68>(Ps, Vb, wr, 0, g, c, Oa);
        mma_tile<1, 8, true, 68, 68>(Ps + 32, Vb + 32 * 68, wr, 0, g, c, Oa);
        __syncthreads();
    }
    float i0 = 1.f / l0, i1 = 1.f / l1;
    float* Og = O + ((size_t)(b * LL + q0 + wr)) * DD + h * DHH;
    #pragma unroll
    for (int ni = 0; ni < 8; ni++) {
        int cc = ni * 8 + 2 * c;
        *(float2*)(Og + (size_t)g * DD + cc) =
            make_float2(rnd_tf(Oa[0][ni][0] * i0), rnd_tf(Oa[0][ni][1] * i0));
        *(float2*)(Og + (size_t)(g + 8) * DD + cc) =
            make_float2(rnd_tf(Oa[0][ni][2] * i1), rnd_tf(Oa[0][ni][3] * i1));
    }
}

// ---------------- MoE routing ----------------
__global__ void moe_zero() {
    if (threadIdx.x < EE) g_cnt[threadIdx.x] = 0;
}

__global__ void __launch_bounds__(256) router_topk(const float* __restrict__ H,
                                                   const float* __restrict__ rw,
                                                   const float* __restrict__ rb) {
    int warp = (blockIdx.x * blockDim.x + threadIdx.x) >> 5;
    int lane = threadIdx.x & 31;
    if (warp >= NL) return;
    const float* h = H + (size_t)warp * DD;
    float logit[EE];
    #pragma unroll
    for (int e = 0; e < EE; e++) {
        const float* w = rw + (size_t)e * DD;
        float s = 0.f;
        for (int d = lane; d < DD; d += 32) s += h[d] * w[d];
        #pragma unroll
        for (int o = 16; o; o >>= 1) s += __shfl_xor_sync(0xffffffffu, s, o);
        logit[e] = s + rb[e];
    }
    if (lane == 0) {
        int i0 = 0; float m0 = logit[0];
        #pragma unroll
        for (int e = 1; e < EE; e++) if (logit[e] > m0) { m0 = logit[e]; i0 = e; }
        int i1 = -1; float m1 = -INFINITY;
        #pragma unroll
        for (int e = 0; e < EE; e++) if (e != i0 && logit[e] > m1) { m1 = logit[e]; i1 = e; }
        float z = expf(m1 - m0);
        float inv = 1.f / (1.f + z);
        g_idx[warp * 2] = i0;  g_idx[warp * 2 + 1] = i1;
        g_gate[warp * 2] = inv; g_gate[warp * 2 + 1] = z * inv;
        atomicAdd(&g_cnt[i0], 1);
        atomicAdd(&g_cnt[i1], 1);
    }
}

__global__ void moe_offsets() {
    if (threadIdx.x == 0) {
        int s = 0;
        for (int e = 0; e < EE; e++) { g_off[e] = s; s += g_cnt[e]; g_cur[e] = 0; }
    }
}

__global__ void __launch_bounds__(256) moe_assign() {
    int n = blockIdx.x * blockDim.x + threadIdx.x;
    if (n >= NL) return;
    #pragma unroll
    for (int k = 0; k < KKE; k++) {
        int e = g_idx[n * 2 + k];
        int pos = atomicAdd(&g_cur[e], 1);
        int slot = g_off[e] + pos;
        g_rowlist[slot] = n;
        g_pairslot[n * 2 + k] = slot;
    }
}

// ---------------- MoE grouped tf32 GEMM (3-stage pipeline) ----------------
__global__ void __launch_bounds__(256, 2) moe_gemm_tf32(const float* __restrict__ A, int lda, int gather,
                                                        const float* __restrict__ W,
                                                        const float* __restrict__ bias,
                                                        int M, int Kd,
                                                        float* __restrict__ C, int ldc, int act) {
    extern __shared__ float sm[];
    int e = blockIdx.z;
    int count = g_cnt[e];
    int row0 = blockIdx.y * 128;
    if (row0 >= count) return;
    int base = g_off[e];
    const float* We = W + (size_t)e * M * Kd;
    const float* be = bias + (size_t)e * M;
    int col0 = blockIdx.x * 128;
    int t = threadIdx.x;
    int lrow = t >> 1, lcol = (t & 1) * 16;
    int arow = row0 + lrow;
    bool valid = arow < count;
    int src;
    if (gather) src = g_rowlist[base + (valid ? arow : 0)];
    else        src = base + (valid ? arow : 0);
    const float* Ag = A + (size_t)src * lda + lcol;
    const float* Wg = We + (size_t)(col0 + lrow) * Kd + lcol;
    uint32_t sm_u = (uint32_t)__cvta_generic_to_shared(sm);
    uint32_t as0 = sm_u + (lrow * 36 + lcol) * 4;
    uint32_t bs0 = sm_u + (TILE_AB + lrow * 36 + lcol) * 4;
    int warp = t >> 5, lane = t & 31, g = lane >> 2, c = lane & 3;
    int wm = (warp >> 2) * 64, wn = (warp & 3) * 32;
    uint32_t a_frag = sm_u + ((wm + (lane & 15)) * 36 + (lane >> 4) * 4) * 4;
    uint32_t b_frag = sm_u + (TILE_AB + (wn + ((lane >> 4) << 3) + (lane & 7)) * 36 + ((lane >> 3) & 1) * 4) * 4;
    float acc[4][4][4] = {};
    int KT = Kd >> 5;
    #pragma unroll
    for (int s = 0; s < 2; s++) {
        const float* a = Ag + s * 32;
        const float* w = Wg + s * 32;
        uint32_t so = (uint32_t)(s * STAGE_F * 4);
        #pragma unroll
        for (int i = 0; i < 4; i++) cp16p(as0 + so + i * 16, a + i * 4, valid);
        #pragma unroll
        for (int i = 0; i < 4; i++) cp16(bs0 + so + i * 16, w + i * 4);
        cpcommit();
    }
    int sl = 0;
    for (int kt = 0; kt < KT; kt++) {
        cpwait1();
        __syncthreads();
        if (kt + 2 < KT) {
            int sn = sl + 2; if (sn >= NST) sn -= NST;
            const float* a = Ag + (kt + 2) * 32;
            const float* w = Wg + (kt + 2) * 32;
            uint32_t so = (uint32_t)(sn * STAGE_F * 4);
            #pragma unroll
            for (int i = 0; i < 4; i++) cp16p(as0 + so + i * 16, a + i * 4, valid);
            #pragma unroll
            for (int i = 0; i < 4; i++) cp16(bs0 + so + i * 16, w + i * 4);
            cpcommit();
        }
        uint32_t so = (uint32_t)(sl * STAGE_F * 4);
        mma_slab(a_frag + so, b_frag + so, acc);
        if (++sl == NST) sl = 0;
    }
    #pragma unroll
    for (int mi = 0; mi < 4; mi++) {
        int r = row0 + wm + mi * 16 + g;
        #pragma unroll
        for (int ni = 0; ni < 4; ni++) {
            int cc = col0 + wn + ni * 8 + c * 2;
            float b0 = be[cc], b1 = be[cc + 1];
            if (r < count) {
                float v0 = acc[mi][ni][0] + b0, v1 = acc[mi][ni][1] + b1;
                if (act) { v0 = rnd_tf(gelu_exact(v0)); v1 = rnd_tf(gelu_exact(v1)); }
                *(float2*)(C + (size_t)(base + r) * ldc + cc) = make_float2(v0, v1);
            }
            if (r + 8 < count) {
                float v2 = acc[mi][ni][2] + b0, v3 = acc[mi][ni][3] + b1;
                if (act) { v2 = rnd_tf(gelu_exact(v2)); v3 = rnd_tf(gelu_exact(v3)); }
                *(float2*)(C + (size_t)(base + r + 8) * ldc + cc) = make_float2(v2, v3);
            }
        }
    }
}

// ---------------- final mix ----------------
__global__ void __launch_bounds__(256) moe_mix(const float* __restrict__ x2,
                                               float* __restrict__ out) {
    int i = blockIdx.x * 256 + threadIdx.x;
    int n = i >> 10;
    int d = i & 1023;
    float v = x2[i];
    int s0 = g_pairslot[n * 2], s1 = g_pairslot[n * 2 + 1];
    v += g_gate[n * 2]     * g_eo[(size_t)s0 * DD + d];
    v += g_gate[n * 2 + 1] * g_eo[(size_t)s1 * DD + d];
    out[i] = v;
}

// ---------------- launch ----------------
extern "C" void kernel_launch(void* const* d_in, const int* in_sizes, int n_in,
                              void* d_out, int out_size) {
    const float* latents    = (const float*)d_in[0];
    const float* tokens     = (const float*)d_in[1];
    const float* sa_ln_g    = (const float*)d_in[2];
    const float* sa_ln_b    = (const float*)d_in[3];
    const float* sa_in_w    = (const float*)d_in[4];
    const float* sa_in_b    = (const float*)d_in[5];
    const float* sa_out_w   = (const float*)d_in[6];
    const float* sa_out_b   = (const float*)d_in[7];
    const float* ca_q_ln_g  = (const float*)d_in[8];
    const float* ca_q_ln_b  = (const float*)d_in[9];
    const float* ca_kv_ln_g = (const float*)d_in[10];
    const float* ca_kv_ln_b = (const float*)d_in[11];
    const float* ca_in_w    = (const float*)d_in[12];
    const float* ca_in_b    = (const float*)d_in[13];
    const float* ca_out_w   = (const float*)d_in[14];
    const float* ca_out_b   = (const float*)d_in[15];
    const float* moe_ln_g   = (const float*)d_in[16];
    const float* moe_ln_b   = (const float*)d_in[17];
    const float* router_w   = (const float*)d_in[18];
    const float* router_b   = (const float*)d_in[19];
    const float* e_fc1_w    = (const float*)d_in[20];
    const float* e_fc1_b    = (const float*)d_in[21];
    const float* e_fc2_w    = (const float*)d_in[22];
    const float* e_fc2_b    = (const float*)d_in[23];
    float* out = (float*)d_out;

    static int s_attr_done = 0;
    if (!s_attr_done) {
        cudaFuncSetAttribute(gemm_tf32, cudaFuncAttributeMaxDynamicSharedMemorySize, GEMM_SMEM);
        cudaFuncSetAttribute(moe_gemm_tf32, cudaFuncAttributeMaxDynamicSharedMemorySize, GEMM_SMEM);
        cudaFuncSetAttribute(flash_tf32, cudaFuncAttributeMaxDynamicSharedMemorySize, FA_SMEM);
        s_attr_done = 1;
    }

    float *p_lnq, *p_lnr, *p_lnt, *p_qkv, *p_q2, *p_kv, *p_attn, *p_x1, *p_x2, *p_h1, *p_eo;
    cudaGetSymbolAddress((void**)&p_lnq,  g_lnq);
    cudaGetSymbolAddress((void**)&p_lnr,  g_lnr);
    cudaGetSymbolAddress((void**)&p_lnt,  g_lnt);
    cudaGetSymbolAddress((void**)&p_qkv,  g_qkv);
    cudaGetSymbolAddress((void**)&p_q2,   g_q2);
    cudaGetSymbolAddress((void**)&p_kv,   g_kv);
    cudaGetSymbolAddress((void**)&p_attn, g_attn);
    cudaGetSymbolAddress((void**)&p_x1,   g_x1);
    cudaGetSymbolAddress((void**)&p_x2,   g_x2);
    cudaGetSymbolAddress((void**)&p_h1,   g_h1);
    cudaGetSymbolAddress((void**)&p_eo,   g_eo);

    const float scale = 0.125f;

    // ===== Self-attention =====
    ln_kernel<<<NL, 256>>>(latents, sa_ln_g, sa_ln_b, p_lnq, nullptr);
    gemm_tf32<<<dim3(24, 16), 256, GEMM_SMEM>>>(p_lnq, DD, sa_in_w, DD, p_qkv, 3 * DD,
                                                sa_in_b, nullptr, 0, DD, 1);
    flash_tf32<<<dim3(4, BHN), 256, FA_SMEM>>>(p_qkv, 3 * DD, p_qkv + DD, 3 * DD,
                                               p_qkv + 2 * DD, 3 * DD, p_attn, LL, scale);
    gemm_tf32<<<dim3(8, 16), 256, GEMM_SMEM>>>(p_attn, DD, sa_out_w, DD, p_x1, DD,
                                               sa_out_b, latents, DD, DD, 0);

    // ===== Cross-attention =====
    ln_kernel<<<NL, 256>>>(p_x1, ca_q_ln_g, ca_q_ln_b, p_lnq, nullptr);
    ln_kernel<<<NT, 256>>>(tokens, ca_kv_ln_g, ca_kv_ln_b, p_lnt, nullptr);
    gemm_tf32<<<dim3(8, 16), 256, GEMM_SMEM>>>(p_lnq, DD, ca_in_w, DD, p_q2, DD,
                                               ca_in_b, nullptr, 0, DD, 1);
    gemm_tf32<<<dim3(16, 64), 256, GEMM_SMEM>>>(p_lnt, DD, ca_in_w + (size_t)DD * DD, DD,
                                                p_kv, 2 * DD, ca_in_b + DD, nullptr, 0, DD, 1);
    flash_tf32<<<dim3(4, BHN), 256, FA_SMEM>>>(p_q2, DD, p_kv, 2 * DD,
                                               p_kv + DD, 2 * DD, p_attn, TT, scale);
    gemm_tf32<<<dim3(8, 16), 256, GEMM_SMEM>>>(p_attn, DD, ca_out_w, DD, p_x2, DD,
                                               ca_out_b, p_x1, DD, DD, 0);

    // ===== MoE =====
    ln_kernel<<<NL, 256>>>(p_x2, moe_ln_g, moe_ln_b, p_lnq, p_lnr);
    moe_zero<<<1, 32>>>();
    router_topk<<<NL / 8, 256>>>(p_lnr, router_w, router_b);
    moe_offsets<<<1, 1>>>();
    moe_assign<<<NL / 256, 256>>>();
    moe_gemm_tf32<<<dim3(DFFN / 128, 16, EE), 256, GEMM_SMEM>>>(p_lnq, DD, 1, e_fc1_w, e_fc1_b,
                                                                DFFN, DD, p_h1, DFFN, 1);
    moe_gemm_tf32<<<dim3(DD / 128, 16, EE), 256, GEMM_SMEM>>>(p_h1, DFFN, 0, e_fc2_w, e_fc2_b,
                                                              DD, DFFN, p_eo, DD, 0);
    moe_mix<<<(NL * DD) / 256, 256>>>(p_x2, out);
}

// round 12
// speedup vs baseline: 1.0036x; 1.0036x over previous
#include <cuda_runtime.h>
#include <math.h>
#include <stdint.h>

#define DD   1024
#define HH   16
#define DHH  64
#define BB   4
#define LL   512
#define TT   2048
#define EE   8
#define KKE  2
#define DFFN 4096
#define NL   (BB*LL)
#define NT   (BB*TT)
#define BHN  (BB*HH)
#define LN_EPS 1e-5f

// ---------------- scratch ----------------
__device__ float g_lnq[(size_t)NL*DD];
__device__ float g_lnr[(size_t)NL*DD];
__device__ float g_lnt[(size_t)NT*DD];
__device__ float g_qkv[(size_t)NL*3*DD];
__device__ float g_q2 [(size_t)NL*DD];
__device__ float g_kv [(size_t)NT*2*DD];
__device__ float g_attn[(size_t)NL*DD];
__device__ float g_x1 [(size_t)NL*DD];
__device__ float g_x2 [(size_t)NL*DD];
__device__ float g_h1 [(size_t)NL*KKE*DFFN];
__device__ float g_eo [(size_t)NL*KKE*DD];
__device__ float g_part [(size_t)2*NL*DD];          // split-K partials (dense GEMMs)
__device__ float g_part2[(size_t)2*NL*KKE*DD];      // split-K partials (fc2)
__device__ int   g_idx [NL*KKE];
__device__ float g_gate[NL*KKE];
__device__ int   g_cnt[EE];
__device__ int   g_off[EE];
__device__ int   g_cur[EE];
__device__ int   g_rowlist[NL*KKE];
__device__ int   g_pairslot[NL*KKE];

// ---------------- helpers ----------------
__device__ __forceinline__ float blk_sum(float v) {
    __shared__ float sh[32];
    int lane = threadIdx.x & 31, w = threadIdx.x >> 5;
    #pragma unroll
    for (int o = 16; o; o >>= 1) v += __shfl_xor_sync(0xffffffffu, v, o);
    if (lane == 0) sh[w] = v;
    __syncthreads();
    if (w == 0) {
        float x = (lane < (int)(blockDim.x >> 5)) ? sh[lane] : 0.f;
        #pragma unroll
        for (int o = 16; o; o >>= 1) x += __shfl_xor_sync(0xffffffffu, x, o);
        if (lane == 0) sh[0] = x;
    }
    __syncthreads();
    float r = sh[0];
    __syncthreads();
    return r;
}

__device__ __forceinline__ float gelu_exact(float x) {
    return 0.5f * x * (1.f + erff(x * 0.70710678118654752f));
}

// ---------------- tf32 mma primitives ----------------
__device__ __forceinline__ uint32_t f2tf(float f) {
    uint32_t u;
    asm("cvt.rna.tf32.f32 %0, %1;" : "=r"(u) : "f"(f));
    return u;
}
__device__ __forceinline__ float rnd_tf(float f) { return __uint_as_float(f2tf(f)); }

__device__ __forceinline__ void mma8(float* cr, const uint32_t* a, const uint32_t* b) {
    asm volatile(
        "mma.sync.aligned.m16n8k8.row.col.f32.tf32.tf32.f32 "
        "{%0,%1,%2,%3}, {%4,%5,%6,%7}, {%8,%9}, {%0,%1,%2,%3};"
        : "+f"(cr[0]), "+f"(cr[1]), "+f"(cr[2]), "+f"(cr[3])
        : "r"(a[0]), "r"(a[1]), "r"(a[2]), "r"(a[3]), "r"(b[0]), "r"(b[1]));
}

__device__ __forceinline__ void ldsm4(uint32_t* r, uint32_t addr) {
    asm volatile("ldmatrix.sync.aligned.m8n8.x4.shared.b16 {%0,%1,%2,%3}, [%4];"
        : "=r"(r[0]), "=r"(r[1]), "=r"(r[2]), "=r"(r[3]) : "r"(addr));
}

__device__ __forceinline__ void cp16(uint32_t dst, const void* src) {
    asm volatile("cp.async.cg.shared.global [%0], [%1], 16;" :: "r"(dst), "l"(src));
}
__device__ __forceinline__ void cp16p(uint32_t dst, const void* src, bool valid) {
    int sz = valid ? 16 : 0;
    asm volatile("cp.async.cg.shared.global [%0], [%1], 16, %2;" :: "r"(dst), "l"(src), "r"(sz));
}
__device__ __forceinline__ void cpcommit() { asm volatile("cp.async.commit_group;"); }
__device__ __forceinline__ void cpwait1() { asm volatile("cp.async.wait_group 1;"); }
__device__ __forceinline__ void cpwait0() { asm volatile("cp.async.wait_group 0;"); }

// 3-stage ring: per stage [A 128x36 | B 128x36]
#define TILE_AB (128*36)
#define STAGE_F (2*TILE_AB)
#define NST 3
#define GEMM_SMEM (NST*STAGE_F*4)   /* 110592 B */

// one 32-k slab via ldmatrix. A pre-rounded tf32 (raw), B cvt'd inline.
__device__ __forceinline__ void mma_slab(uint32_t a_base, uint32_t b_base,
                                         float (&acc)[4][4][4]) {
    #pragma unroll
    for (int kk = 0; kk < 4; kk++) {
        uint32_t af[4][4];
        #pragma unroll
        for (int mi = 0; mi < 4; mi++)
            ldsm4(af[mi], a_base + (mi * 16 * 36 + kk * 8) * 4);
        uint32_t bq[2][4];
        #pragma unroll
        for (int np = 0; np < 2; np++)
            ldsm4(bq[np], b_base + (np * 16 * 36 + kk * 8) * 4);
        #pragma unroll
        for (int np = 0; np < 2; np++)
            #pragma unroll
            for (int q = 0; q < 4; q++)
                bq[np][q] = f2tf(__uint_as_float(bq[np][q]));
        #pragma unroll
        for (int mi = 0; mi < 4; mi++) {
            #pragma unroll
            for (int np = 0; np < 2; np++) {
                mma8(acc[mi][np * 2 + 0], af[mi], &bq[np][0]);
                mma8(acc[mi][np * 2 + 1], af[mi], &bq[np][2]);
            }
        }
    }
}

// float-smem slab for flash attention (cvt inline).
template<int WM, int WN, bool BKN, int AST2, int BST>
__device__ __forceinline__ void mma_tile(const float* __restrict__ Ab,
                                         const float* __restrict__ Bb,
                                         int wm, int wn, int g, int c,
                                         float (&acc)[WM][WN][4]) {
    #pragma unroll
    for (int kk = 0; kk < 4; kk++) {
        const int k0 = kk * 8;
        uint32_t af[WM][4];
        #pragma unroll
        for (int mi = 0; mi < WM; mi++) {
            const float* Ar = Ab + (wm + mi * 16 + g) * AST2 + k0 + c;
            af[mi][0] = f2tf(Ar[0]);
            af[mi][1] = f2tf(Ar[8 * AST2]);
            af[mi][2] = f2tf(Ar[4]);
            af[mi][3] = f2tf(Ar[8 * AST2 + 4]);
        }
        uint32_t bf[WN][2];
        #pragma unroll
        for (int ni = 0; ni < WN; ni++) {
            if (BKN) {
                const float* Br = Bb + (k0 + c) * BST + wn + ni * 8 + g;
                bf[ni][0] = f2tf(Br[0]);
                bf[ni][1] = f2tf(Br[4 * BST]);
            } else {
                const float* Br = Bb + (wn + ni * 8 + g) * BST + k0 + c;
                bf[ni][0] = f2tf(Br[0]);
                bf[ni][1] = f2tf(Br[4]);
            }
        }
        #pragma unroll
        for (int mi = 0; mi < WM; mi++)
            #pragma unroll
            for (int ni = 0; ni < WN; ni++)
                mma8(acc[mi][ni], af[mi], bf[ni]);
    }
}

// ---------------- layernorm ----------------
__global__ void __launch_bounds__(256) ln_kernel(const float* __restrict__ x,
                                                 const float* __restrict__ g,
                                                 const float* __restrict__ b,
                                                 float* __restrict__ y,
                                                 float* __restrict__ yraw) {
    size_t row = blockIdx.x;
    const float* xr = x + row * DD;
    float* yr = y + row * DD;
    int t = threadIdx.x;
    float v[4];
    float s = 0.f;
    #pragma unroll
    for (int i = 0; i < 4; i++) { v[i] = xr[t + 256 * i]; s += v[i]; }
    s = blk_sum(s);
    float mean = s * (1.f / DD);
    float s2 = 0.f;
    #pragma unroll
    for (int i = 0; i < 4; i++) { float d = v[i] - mean; s2 += d * d; }
    s2 = blk_sum(s2);
    float inv = rsqrtf(s2 * (1.f / DD) + LN_EPS);
    #pragma unroll
    for (int i = 0; i < 4; i++) {
        int cc = t + 256 * i;
        float o = (v[i] - mean) * inv * g[cc] + b[cc];
        yr[cc] = rnd_tf(o);
        if (yraw) yraw[row * DD + cc] = o;
    }
}

// ---------------- tf32 GEMM: 128x128, 3-stage cp.async + ldmatrix ----------------
__global__ void __launch_bounds__(256, 2) gemm_tf32(const float* __restrict__ A, int lda,
                                                    const float* __restrict__ W, int ldw,
                                                    float* __restrict__ C, int ldc,
                                                    const float* __restrict__ bias,
                                                    const float* __restrict__ resid, int ldr,
                                                    int Kd, int round_out) {
    extern __shared__ float sm[];
    int t = threadIdx.x;
    int row0 = blockIdx.y * 128, col0 = blockIdx.x * 128;
    int lrow = t >> 1, lcol = (t & 1) * 16;
    const float* Ag = A + (size_t)(row0 + lrow) * lda + lcol;
    const float* Wg = W + (size_t)(col0 + lrow) * ldw + lcol;
    uint32_t sm_u = (uint32_t)__cvta_generic_to_shared(sm);
    uint32_t as0 = sm_u + (lrow * 36 + lcol) * 4;
    uint32_t bs0 = sm_u + (TILE_AB + lrow * 36 + lcol) * 4;
    int warp = t >> 5, lane = t & 31, g = lane >> 2, c = lane & 3;
    int wm = (warp >> 2) * 64, wn = (warp & 3) * 32;
    uint32_t a_frag = sm_u + ((wm + (lane & 15)) * 36 + (lane >> 4) * 4) * 4;
    uint32_t b_frag = sm_u + (TILE_AB + (wn + ((lane >> 4) << 3) + (lane & 7)) * 36 + ((lane >> 3) & 1) * 4) * 4;
    float acc[4][4][4] = {};
    int KT = Kd >> 5;
    #pragma unroll
    for (int s = 0; s < 2; s++) {
        const float* a = Ag + s * 32;
        const float* w = Wg + s * 32;
        uint32_t so = (uint32_t)(s * STAGE_F * 4);
        #pragma unroll
        for (int i = 0; i < 4; i++) cp16(as0 + so + i * 16, a + i * 4);
        #pragma unroll
        for (int i = 0; i < 4; i++) cp16(bs0 + so + i * 16, w + i * 4);
        cpcommit();
    }
    int sl = 0;
    for (int kt = 0; kt < KT; kt++) {
        cpwait1();
        __syncthreads();
        if (kt + 2 < KT) {
            int sn = sl + 2; if (sn >= NST) sn -= NST;
            const float* a = Ag + (kt + 2) * 32;
            const float* w = Wg + (kt + 2) * 32;
            uint32_t so = (uint32_t)(sn * STAGE_F * 4);
            #pragma unroll
            for (int i = 0; i < 4; i++) cp16(as0 + so + i * 16, a + i * 4);
            #pragma unroll
            for (int i = 0; i < 4; i++) cp16(bs0 + so + i * 16, w + i * 4);
            cpcommit();
        }
        uint32_t so = (uint32_t)(sl * STAGE_F * 4);
        mma_slab(a_frag + so, b_frag + so, acc);
        if (++sl == NST) sl = 0;
    }
    #pragma unroll
    for (int mi = 0; mi < 4; mi++) {
        int r = row0 + wm + mi * 16 + g;
        #pragma unroll
        for (int ni = 0; ni < 4; ni++) {
            int cc = col0 + wn + ni * 8 + c * 2;
            float v0 = acc[mi][ni][0], v1 = acc[mi][ni][1];
            float v2 = acc[mi][ni][2], v3 = acc[mi][ni][3];
            if (bias) { float b0 = bias[cc], b1 = bias[cc + 1]; v0 += b0; v1 += b1; v2 += b0; v3 += b1; }
            if (resid) {
                const float* q0 = resid + (size_t)r * ldr + cc;
                const float* q1 = resid + (size_t)(r + 8) * ldr + cc;
                v0 += q0[0]; v1 += q0[1]; v2 += q1[0]; v3 += q1[1];
            }
            if (round_out) { v0 = rnd_tf(v0); v1 = rnd_tf(v1); v2 = rnd_tf(v2); v3 = rnd_tf(v3); }
            *(float2*)(C + (size_t)r * ldc + cc) = make_float2(v0, v1);
            *(float2*)(C + (size_t)(r + 8) * ldc + cc) = make_float2(v2, v3);
        }
    }
}

// ---------------- split-K tf32 GEMM: writes raw partials (2048 rows x 1024 cols) ----------------
__global__ void __launch_bounds__(256, 2) gemm_sk(const float* __restrict__ A, int lda,
                                                  const float* __restrict__ W, int ldw,
                                                  float* __restrict__ part, int Kh) {
    extern __shared__ float sm[];
    int t = threadIdx.x;
    int z = blockIdx.z;
    int row0 = blockIdx.y * 128, col0 = blockIdx.x * 128;
    int lrow = t >> 1, lcol = (t & 1) * 16;
    const float* Ag = A + (size_t)(row0 + lrow) * lda + z * Kh + lcol;
    const float* Wg = W + (size_t)(col0 + lrow) * ldw + z * Kh + lcol;
    uint32_t sm_u = (uint32_t)__cvta_generic_to_shared(sm);
    uint32_t as0 = sm_u + (lrow * 36 + lcol) * 4;
    uint32_t bs0 = sm_u + (TILE_AB + lrow * 36 + lcol) * 4;
    int warp = t >> 5, lane = t & 31, g = lane >> 2, c = lane & 3;
    int wm = (warp >> 2) * 64, wn = (warp & 3) * 32;
    uint32_t a_frag = sm_u + ((wm + (lane & 15)) * 36 + (lane >> 4) * 4) * 4;
    uint32_t b_frag = sm_u + (TILE_AB + (wn + ((lane >> 4) << 3) + (lane & 7)) * 36 + ((lane >> 3) & 1) * 4) * 4;
    float acc[4][4][4] = {};
    int KT = Kh >> 5;
    #pragma unroll
    for (int s = 0; s < 2; s++) {
        const float* a = Ag + s * 32;
        const float* w = Wg + s * 32;
        uint32_t so = (uint32_t)(s * STAGE_F * 4);
        #pragma unroll
        for (int i = 0; i < 4; i++) cp16(as0 + so + i * 16, a + i * 4);
        #pragma unroll
        for (int i = 0; i < 4; i++) cp16(bs0 + so + i * 16, w + i * 4);
        cpcommit();
    }
    int sl = 0;
    for (int kt = 0; kt < KT; kt++) {
        cpwait1();
        __syncthreads();
        if (kt + 2 < KT) {
            int sn = sl + 2; if (sn >= NST) sn -= NST;
            const float* a = Ag + (kt + 2) * 32;
            const float* w = Wg + (kt + 2) * 32;
            uint32_t so = (uint32_t)(sn * STAGE_F * 4);
            #pragma unroll
            for (int i = 0; i < 4; i++) cp16(as0 + so + i * 16, a + i * 4);
            #pragma unroll
            for (int i = 0; i < 4; i++) cp16(bs0 + so + i * 16, w + i * 4);
            cpcommit();
        }
        uint32_t so = (uint32_t)(sl * STAGE_F * 4);
        mma_slab(a_frag + so, b_frag + so, acc);
        if (++sl == NST) sl = 0;
    }
    float* P = part + (size_t)z * NL * DD;
    #pragma unroll
    for (int mi = 0; mi < 4; mi++) {
        int r = row0 + wm + mi * 16 + g;
        #pragma unroll
        for (int ni = 0; ni < 4; ni++) {
            int cc = col0 + wn + ni * 8 + c * 2;
            *(float2*)(P + (size_t)r * DD + cc) = make_float2(acc[mi][ni][0], acc[mi][ni][1]);
            *(float2*)(P + (size_t)(r + 8) * DD + cc) = make_float2(acc[mi][ni][2], acc[mi][ni][3]);
        }
    }
}

// combiner: C = p0 + p1 + bias (+resid) (opt rnd)
__global__ void __launch_bounds__(256) sk_combine(const float* __restrict__ part,
                                                  const float* __restrict__ bias,
                                                  const float* __restrict__ resid, int ldr,
                                                  float* __restrict__ C, int ldc, int round_out) {
    int i = blockIdx.x * 256 + threadIdx.x;
    int r = i >> 10, d = i & 1023;
    float v = part[i] + part[(size_t)NL * DD + i] + bias[d];
    if (resid) v += resid[(size_t)r * ldr + d];
    if (round_out) v = rnd_tf(v);
    C[(size_t)r * ldc + d] = v;
}

// ---------------- fused flash attention (tf32, single-buffer KV, 2 CTAs/SM) ----------------
#define FA_N 64
#define FA_QS (128*68)
#define FA_KV (64*68)
#define FA_SMEM ((FA_QS + 2*FA_KV + FA_QS)*4)   /* 104448 B */

__global__ void __launch_bounds__(256, 2) flash_tf32(const float* __restrict__ Q, int ldq,
                                                     const float* __restrict__ Kp, int ldk,
                                                     const float* __restrict__ Vp, int ldv,
                                                     float* __restrict__ O, int Lk, float scale) {
    extern __shared__ float sm[];
    float* Qs = sm;
    float* Ks = Qs + FA_QS;
    float* Vs = Ks + FA_KV;
    float* Ps = Vs + FA_KV;
    int bh = blockIdx.y, b = bh >> 4, h = bh & 15;
    int q0 = blockIdx.x * 128;
    int t = threadIdx.x;
    const float* Qg = Q + ((size_t)(b * LL + q0)) * ldq + h * DHH;
    const float* Kg = Kp + ((size_t)b * Lk) * ldk + h * DHH;
    const float* Vg = Vp + ((size_t)b * Lk) * ldv + h * DHH;
    uint32_t qs0 = (uint32_t)__cvta_generic_to_shared(Qs);
    uint32_t ks0 = (uint32_t)__cvta_generic_to_shared(Ks);
    uint32_t vs0 = (uint32_t)__cvta_generic_to_shared(Vs);
    {
        int row = t >> 1, segb = (t & 1) * 8;
        const float* qr = Qg + (size_t)row * ldq;
        #pragma unroll
        for (int j = 0; j < 8; j++)
            cp16(qs0 + (row * 68 + (segb + j) * 4) * 4, qr + (segb + j) * 4);
    }
    int kr = t >> 2, kcb = (t & 3) * 16;
    {
        const float* kg = Kg + (size_t)kr * ldk + kcb;
        const float* vg = Vg + (size_t)kr * ldv + kcb;
        uint32_t kb = ks0 + (kr * 68 + kcb) * 4;
        uint32_t vb = vs0 + (kr * 68 + kcb) * 4;
        #pragma unroll
        for (int j = 0; j < 4; j++) cp16(kb + j * 16, kg + j * 4);
        #pragma unroll
        for (int j = 0; j < 4; j++) cp16(vb + j * 16, vg + j * 4);
    }
    cpcommit();
    int warp = t >> 5, lane = t & 31, g = lane >> 2, c = lane & 3;
    int wr = warp * 16;
    float Oa[1][8][4] = {};
    float m0 = -INFINITY, m1 = -INFINITY, l0 = 0.f, l1 = 0.f;
    int niter = Lk / FA_N;
    for (int it = 0; it < niter; it++) {
        cpwait0();
        __syncthreads();
        float S[1][8][4] = {};
        mma_tile<1, 8, false, 68, 68>(Qs, Ks, wr, 0, g, c, S);
        mma_tile<1, 8, false, 68, 68>(Qs + 32, Ks + 32, wr, 0, g, c, S);
        float rm0 = -INFINITY, rm1 = -INFINITY;
        #pragma unroll
        for (int ni = 0; ni < 8; ni++) {
            #pragma unroll
            for (int j = 0; j < 4; j++) S[0][ni][j] *= scale;
            rm0 = fmaxf(rm0, fmaxf(S[0][ni][0], S[0][ni][1]));
            rm1 = fmaxf(rm1, fmaxf(S[0][ni][2], S[0][ni][3]));
        }
        rm0 = fmaxf(rm0, __shfl_xor_sync(0xffffffffu, rm0, 1));
        rm0 = fmaxf(rm0, __shfl_xor_sync(0xffffffffu, rm0, 2));
        rm1 = fmaxf(rm1, __shfl_xor_sync(0xffffffffu, rm1, 1));
        rm1 = fmaxf(rm1, __shfl_xor_sync(0xffffffffu, rm1, 2));
        float mn0 = fmaxf(m0, rm0), mn1 = fmaxf(m1, rm1);
        float a0 = __expf(m0 - mn0), a1 = __expf(m1 - mn1);
        float ps0 = 0.f, ps1 = 0.f;
        #pragma unroll
        for (int ni = 0; ni < 8; ni++) {
            float p0 = __expf(S[0][ni][0] - mn0);
            float p1 = __expf(S[0][ni][1] - mn0);
            float p2 = __expf(S[0][ni][2] - mn1);
            float p3 = __expf(S[0][ni][3] - mn1);
            ps0 += p0 + p1; ps1 += p2 + p3;
            *(float2*)&Ps[(wr + g) * 68 + ni * 8 + 2 * c] = make_float2(p0, p1);
            *(float2*)&Ps[(wr + g + 8) * 68 + ni * 8 + 2 * c] = make_float2(p2, p3);
        }
        ps0 += __shfl_xor_sync(0xffffffffu, ps0, 1);
        ps0 += __shfl_xor_sync(0xffffffffu, ps0, 2);
        ps1 += __shfl_xor_sync(0xffffffffu, ps1, 1);
        ps1 += __shfl_xor_sync(0xffffffffu, ps1, 2);
        l0 = l0 * a0 + ps0;
        l1 = l1 * a1 + ps1;
        m0 = mn0; m1 = mn1;
        #pragma unroll
        for (int ni = 0; ni < 8; ni++) {
            Oa[0][ni][0] *= a0; Oa[0][ni][1] *= a0;
            Oa[0][ni][2] *= a1; Oa[0][ni][3] *= a1;
        }
        __syncwarp();
        mma_tile<1, 8, true, 68, 68>(Ps, Vs, wr, 0, g, c, Oa);
        mma_tile<1, 8, true, 68, 68>(Ps + 32, Vs + 32 * 68, wr, 0, g, c, Oa);
        __syncthreads();   // all warps done reading Ks/Vs before refill
        if (it + 1 < niter) {
            const float* kg = Kg + (size_t)((it + 1) * FA_N + kr) * ldk + kcb;
            const float* vg = Vg + (size_t)((it + 1) * FA_N + kr) * ldv + kcb;
            uint32_t kb = ks0 + (kr * 68 + kcb) * 4;
            uint32_t vb = vs0 + (kr * 68 + kcb) * 4;
            #pragma unroll
            for (int j = 0; j < 4; j++) cp16(kb + j * 16, kg + j * 4);
            #pragma unroll
            for (int j = 0; j < 4; j++) cp16(vb + j * 16, vg + j * 4);
            cpcommit();
        }
    }
    float i0 = 1.f / l0, i1 = 1.f / l1;
    float* Og = O + ((size_t)(b * LL + q0 + wr)) * DD + h * DHH;
    #pragma unroll
    for (int ni = 0; ni < 8; ni++) {
        int cc = ni * 8 + 2 * c;
        *(float2*)(Og + (size_t)g * DD + cc) =
            make_float2(rnd_tf(Oa[0][ni][0] * i0), rnd_tf(Oa[0][ni][1] * i0));
        *(float2*)(Og + (size_t)(g + 8) * DD + cc) =
            make_float2(rnd_tf(Oa[0][ni][2] * i1), rnd_tf(Oa[0][ni][3] * i1));
    }
}

// ---------------- MoE routing ----------------
__global__ void moe_zero() {
    if (threadIdx.x < EE) g_cnt[threadIdx.x] = 0;
}

__global__ void __launch_bounds__(256) router_topk(const float* __restrict__ H,
                                                   const float* __restrict__ rw,
                                                   const float* __restrict__ rb) {
    int warp = (blockIdx.x * blockDim.x + threadIdx.x) >> 5;
    int lane = threadIdx.x & 31;
    if (warp >= NL) return;
    const float* h = H + (size_t)warp * DD;
    float logit[EE];
    #pragma unroll
    for (int e = 0; e < EE; e++) {
        const float* w = rw + (size_t)e * DD;
        float s = 0.f;
        for (int d = lane; d < DD; d += 32) s += h[d] * w[d];
        #pragma unroll
        for (int o = 16; o; o >>= 1) s += __shfl_xor_sync(0xffffffffu, s, o);
        logit[e] = s + rb[e];
    }
    if (lane == 0) {
        int i0 = 0; float m0 = logit[0];
        #pragma unroll
        for (int e = 1; e < EE; e++) if (logit[e] > m0) { m0 = logit[e]; i0 = e; }
        int i1 = -1; float m1 = -INFINITY;
        #pragma unroll
        for (int e = 0; e < EE; e++) if (e != i0 && logit[e] > m1) { m1 = logit[e]; i1 = e; }
        float z = expf(m1 - m0);
        float inv = 1.f / (1.f + z);
        g_idx[warp * 2] = i0;  g_idx[warp * 2 + 1] = i1;
        g_gate[warp * 2] = inv; g_gate[warp * 2 + 1] = z * inv;
        atomicAdd(&g_cnt[i0], 1);
        atomicAdd(&g_cnt[i1], 1);
    }
}

__global__ void moe_offsets() {
    if (threadIdx.x == 0) {
        int s = 0;
        for (int e = 0; e < EE; e++) { g_off[e] = s; s += g_cnt[e]; g_cur[e] = 0; }
    }
}

__global__ void __launch_bounds__(256) moe_assign() {
    int n = blockIdx.x * blockDim.x + threadIdx.x;
    if (n >= NL) return;
    #pragma unroll
    for (int k = 0; k < KKE; k++) {
        int e = g_idx[n * 2 + k];
        int pos = atomicAdd(&g_cur[e], 1);
        int slot = g_off[e] + pos;
        g_rowlist[slot] = n;
        g_pairslot[n * 2 + k] = slot;
    }
}

// ---------------- MoE grouped tf32 GEMM (fc1; 3-stage pipeline) ----------------
__global__ void __launch_bounds__(256, 2) moe_gemm_tf32(const float* __restrict__ A, int lda, int gather,
                                                        const float* __restrict__ W,
                                                        const float* __restrict__ bias,
                                                        int M, int Kd,
                                                        float* __restrict__ C, int ldc, int act) {
    extern __shared__ float sm[];
    int e = blockIdx.z;
    int count = g_cnt[e];
    int row0 = blockIdx.y * 128;
    if (row0 >= count) return;
    int base = g_off[e];
    const float* We = W + (size_t)e * M * Kd;
    const float* be = bias + (size_t)e * M;
    int col0 = blockIdx.x * 128;
    int t = threadIdx.x;
    int lrow = t >> 1, lcol = (t & 1) * 16;
    int arow = row0 + lrow;
    bool valid = arow < count;
    int src;
    if (gather) src = g_rowlist[base + (valid ? arow : 0)];
    else        src = base + (valid ? arow : 0);
    const float* Ag = A + (size_t)src * lda + lcol;
    const float* Wg = We + (size_t)(col0 + lrow) * Kd + lcol;
    uint32_t sm_u = (uint32_t)__cvta_generic_to_shared(sm);
    uint32_t as0 = sm_u + (lrow * 36 + lcol) * 4;
    uint32_t bs0 = sm_u + (TILE_AB + lrow * 36 + lcol) * 4;
    int warp = t >> 5, lane = t & 31, g = lane >> 2, c = lane & 3;
    int wm = (warp >> 2) * 64, wn = (warp & 3) * 32;
    uint32_t a_frag = sm_u + ((wm + (lane & 15)) * 36 + (lane >> 4) * 4) * 4;
    uint32_t b_frag = sm_u + (TILE_AB + (wn + ((lane >> 4) << 3) + (lane & 7)) * 36 + ((lane >> 3) & 1) * 4) * 4;
    float acc[4][4][4] = {};
    int KT = Kd >> 5;
    #pragma unroll
    for (int s = 0; s < 2; s++) {
        const float* a = Ag + s * 32;
        const float* w = Wg + s * 32;
        uint32_t so = (uint32_t)(s * STAGE_F * 4);
        #pragma unroll
        for (int i = 0; i < 4; i++) cp16p(as0 + so + i * 16, a + i * 4, valid);
        #pragma unroll
        for (int i = 0; i < 4; i++) cp16(bs0 + so + i * 16, w + i * 4);
        cpcommit();
    }
    int sl = 0;
    for (int kt = 0; kt < KT; kt++) {
        cpwait1();
        __syncthreads();
        if (kt + 2 < KT) {
            int sn = sl + 2; if (sn >= NST) sn -= NST;
            const float* a = Ag + (kt + 2) * 32;
            const float* w = Wg + (kt + 2) * 32;
            uint32_t so = (uint32_t)(sn * STAGE_F * 4);
            #pragma unroll
            for (int i = 0; i < 4; i++) cp16p(as0 + so + i * 16, a + i * 4, valid);
            #pragma unroll
            for (int i = 0; i < 4; i++) cp16(bs0 + so + i * 16, w + i * 4);
            cpcommit();
        }
        uint32_t so = (uint32_t)(sl * STAGE_F * 4);
        mma_slab(a_frag + so, b_frag + so, acc);
        if (++sl == NST) sl = 0;
    }
    #pragma unroll
    for (int mi = 0; mi < 4; mi++) {
        int r = row0 + wm + mi * 16 + g;
        #pragma unroll
        for (int ni = 0; ni < 4; ni++) {
            int cc = col0 + wn + ni * 8 + c * 2;
            float b0 = be[cc], b1 = be[cc + 1];
            if (r < count) {
                float v0 = acc[mi][ni][0] + b0, v1 = acc[mi][ni][1] + b1;
                if (act) { v0 = rnd_tf(gelu_exact(v0)); v1 = rnd_tf(gelu_exact(v1)); }
                *(float2*)(C + (size_t)(base + r) * ldc + cc) = make_float2(v0, v1);
            }
            if (r + 8 < count) {
                float v2 = acc[mi][ni][2] + b0, v3 = acc[mi][ni][3] + b1;
                if (act) { v2 = rnd_tf(gelu_exact(v2)); v3 = rnd_tf(gelu_exact(v3)); }
                *(float2*)(C + (size_t)(base + r + 8) * ldc + cc) = make_float2(v2, v3);
            }
        }
    }
}

// ---------------- MoE fc2 split-K: grid (8, 32, 8); y = rowtile | khalf ----------------
__global__ void __launch_bounds__(256, 2) moe_gemm_sk(const float* __restrict__ A, int lda,
                                                      const float* __restrict__ W,
                                                      const float* __restrict__ bias,
                                                      int M, int Kd,
                                                      float* __restrict__ part) {
    extern __shared__ float sm[];
    int e = blockIdx.z;
    int count = g_cnt[e];
    int rt = blockIdx.y & 15, kz = blockIdx.y >> 4;
    int row0 = rt * 128;
    if (row0 >= count) return;
    int Kh = Kd >> 1;
    int base = g_off[e];
    const float* We = W + (size_t)e * M * Kd;
    const float* be = bias + (size_t)e * M;
    int col0 = blockIdx.x * 128;
    int t = threadIdx.x;
    int lrow = t >> 1, lcol = (t & 1) * 16;
    int arow = row0 + lrow;
    bool valid = arow < count;
    int src = base + (valid ? arow : 0);
    const float* Ag = A + (size_t)src * lda + kz * Kh + lcol;
    const float* Wg = We + (size_t)(col0 + lrow) * Kd + kz * Kh + lcol;
    uint32_t sm_u = (uint32_t)__cvta_generic_to_shared(sm);
    uint32_t as0 = sm_u + (lrow * 36 + lcol) * 4;
    uint32_t bs0 = sm_u + (TILE_AB + lrow * 36 + lcol) * 4;
    int warp = t >> 5, lane = t & 31, g = lane >> 2, c = lane & 3;
    int wm = (warp >> 2) * 64, wn = (warp & 3) * 32;
    uint32_t a_frag = sm_u + ((wm + (lane & 15)) * 36 + (lane >> 4) * 4) * 4;
    uint32_t b_frag = sm_u + (TILE_AB + (wn + ((lane >> 4) << 3) + (lane & 7)) * 36 + ((lane >> 3) & 1) * 4) * 4;
    float acc[4][4][4] = {};
    int KT = Kh >> 5;
    #pragma unroll
    for (int s = 0; s < 2; s++) {
        const float* a = Ag + s * 32;
        const float* w = Wg + s * 32;
        uint32_t so = (uint32_t)(s * STAGE_F * 4);
        #pragma unroll
        for (int i = 0; i < 4; i++) cp16p(as0 + so + i * 16, a + i * 4, valid);
        #pragma unroll
        for (int i = 0; i < 4; i++) cp16(bs0 + so + i * 16, w + i * 4);
        cpcommit();
    }
    int sl = 0;
    for (int kt = 0; kt < KT; kt++) {
        cpwait1();
        __syncthreads();
        if (kt + 2 < KT) {
            int sn = sl + 2; if (sn >= NST) sn -= NST;
            const float* a = Ag + (kt + 2) * 32;
            const float* w = Wg + (kt + 2) * 32;
            uint32_t so = (uint32_t)(sn * STAGE_F * 4);
            #pragma unroll
            for (int i = 0; i < 4; i++) cp16p(as0 + so + i * 16, a + i * 4, valid);
            #pragma unroll
            for (int i = 0; i < 4; i++) cp16(bs0 + so + i * 16, w + i * 4);
            cpcommit();
        }
        uint32_t so = (uint32_t)(sl * STAGE_F * 4);
        mma_slab(a_frag + so, b_frag + so, acc);
        if (++sl == NST) sl = 0;
    }
    float* P = part + (size_t)kz * NL * KKE * DD;
    #pragma unroll
    for (int mi = 0; mi < 4; mi++) {
        int r = row0 + wm + mi * 16 + g;
        #pragma unroll
        for (int ni = 0; ni < 4; ni++) {
            int cc = col0 + wn + ni * 8 + c * 2;
            float b0 = (kz == 0) ? bias[0] * 0.f + be[cc] : 0.f;
            float b1 = (kz == 0) ? be[cc + 1] : 0.f;
            if (r < count) {
                *(float2*)(P + (size_t)(base + r) * DD + cc) =
                    make_float2(acc[mi][ni][0] + b0, acc[mi][ni][1] + b1);
            }
            if (r + 8 < count) {
                *(float2*)(P + (size_t)(base + r + 8) * DD + cc) =
                    make_float2(acc[mi][ni][2] + b0, acc[mi][ni][3] + b1);
            }
        }
    }
}

__global__ void __launch_bounds__(256) moe_combine2(const float* __restrict__ part,
                                                    float* __restrict__ eo) {
    int i = blockIdx.x * 256 + threadIdx.x;
    eo[i] = part[i] + part[(size_t)NL * KKE * DD + i];
}

// ---------------- final mix ----------------
__global__ void __launch_bounds__(256) moe_mix(const float* __restrict__ x2,
                                               float* __restrict__ out) {
    int i = blockIdx.x * 256 + threadIdx.x;
    int n = i >> 10;
    int d = i & 1023;
    float v = x2[i];
    int s0 = g_pairslot[n * 2], s1 = g_pairslot[n * 2 + 1];
    v += g_gate[n * 2]     * g_eo[(size_t)s0 * DD + d];
    v += g_gate[n * 2 + 1] * g_eo[(size_t)s1 * DD + d];
    out[i] = v;
}

// ---------------- launch ----------------
extern "C" void kernel_launch(void* const* d_in, const int* in_sizes, int n_in,
                              void* d_out, int out_size) {
    const float* latents    = (const float*)d_in[0];
    const float* tokens     = (const float*)d_in[1];
    const float* sa_ln_g    = (const float*)d_in[2];
    const float* sa_ln_b    = (const float*)d_in[3];
    const float* sa_in_w    = (const float*)d_in[4];
    const float* sa_in_b    = (const float*)d_in[5];
    const float* sa_out_w   = (const float*)d_in[6];
    const float* sa_out_b   = (const float*)d_in[7];
    const float* ca_q_ln_g  = (const float*)d_in[8];
    const float* ca_q_ln_b  = (const float*)d_in[9];
    const float* ca_kv_ln_g = (const float*)d_in[10];
    const float* ca_kv_ln_b = (const float*)d_in[11];
    const float* ca_in_w    = (const float*)d_in[12];
    const float* ca_in_b    = (const float*)d_in[13];
    const float* ca_out_w   = (const float*)d_in[14];
    const float* ca_out_b   = (const float*)d_in[15];
    const float* moe_ln_g   = (const float*)d_in[16];
    const float* moe_ln_b   = (const float*)d_in[17];
    const float* router_w   = (const float*)d_in[18];
    const float* router_b   = (const float*)d_in[19];
    const float* e_fc1_w    = (const float*)d_in[20];
    const float* e_fc1_b    = (const float*)d_in[21];
    const float* e_fc2_w    = (const float*)d_in[22];
    const float* e_fc2_b    = (const float*)d_in[23];
    float* out = (float*)d_out;

    static int s_attr_done = 0;
    if (!s_attr_done) {
        cudaFuncSetAttribute(gemm_tf32, cudaFuncAttributeMaxDynamicSharedMemorySize, GEMM_SMEM);
        cudaFuncSetAttribute(gemm_sk, cudaFuncAttributeMaxDynamicSharedMemorySize, GEMM_SMEM);
        cudaFuncSetAttribute(moe_gemm_tf32, cudaFuncAttributeMaxDynamicSharedMemorySize, GEMM_SMEM);
        cudaFuncSetAttribute(moe_gemm_sk, cudaFuncAttributeMaxDynamicSharedMemorySize, GEMM_SMEM);
        cudaFuncSetAttribute(flash_tf32, cudaFuncAttributeMaxDynamicSharedMemorySize, FA_SMEM);
        s_attr_done = 1;
    }

    float *p_lnq, *p_lnr, *p_lnt, *p_qkv, *p_q2, *p_kv, *p_attn, *p_x1, *p_x2, *p_h1, *p_eo;
    float *p_part, *p_part2;
    cudaGetSymbolAddress((void**)&p_lnq,  g_lnq);
    cudaGetSymbolAddress((void**)&p_lnr,  g_lnr);
    cudaGetSymbolAddress((void**)&p_lnt,  g_lnt);
    cudaGetSymbolAddress((void**)&p_qkv,  g_qkv);
    cudaGetSymbolAddress((void**)&p_q2,   g_q2);
    cudaGetSymbolAddress((void**)&p_kv,   g_kv);
    cudaGetSymbolAddress((void**)&p_attn, g_attn);
    cudaGetSymbolAddress((void**)&p_x1,   g_x1);
    cudaGetSymbolAddress((void**)&p_x2,   g_x2);
    cudaGetSymbolAddress((void**)&p_h1,   g_h1);
    cudaGetSymbolAddress((void**)&p_eo,   g_eo);
    cudaGetSymbolAddress((void**)&p_part, g_part);
    cudaGetSymbolAddress((void**)&p_part2, g_part2);

    const float scale = 0.125f;

    // ===== Self-attention =====
    ln_kernel<<<NL, 256>>>(latents, sa_ln_g, sa_ln_b, p_lnq, nullptr);
    gemm_tf32<<<dim3(24, 16), 256, GEMM_SMEM>>>(p_lnq, DD, sa_in_w, DD, p_qkv, 3 * DD,
                                                sa_in_b, nullptr, 0, DD, 1);
    flash_tf32<<<dim3(4, BHN), 256, FA_SMEM>>>(p_qkv, 3 * DD, p_qkv + DD, 3 * DD,
                                               p_qkv + 2 * DD, 3 * DD, p_attn, LL, scale);
    gemm_sk<<<dim3(8, 16, 2), 256, GEMM_SMEM>>>(p_attn, DD, sa_out_w, DD, p_part, 512);
    sk_combine<<<(NL * DD) / 256, 256>>>(p_part, sa_out_b, latents, DD, p_x1, DD, 0);

    // ===== Cross-attention =====
    ln_kernel<<<NL, 256>>>(p_x1, ca_q_ln_g, ca_q_ln_b, p_lnq, nullptr);
    ln_kernel<<<NT, 256>>>(tokens, ca_kv_ln_g, ca_kv_ln_b, p_lnt, nullptr);
    gemm_sk<<<dim3(8, 16, 2), 256, GEMM_SMEM>>>(p_lnq, DD, ca_in_w, DD, p_part, 512);
    sk_combine<<<(NL * DD) / 256, 256>>>(p_part, ca_in_b, nullptr, 0, p_q2, DD, 1);
    gemm_tf32<<<dim3(16, 64), 256, GEMM_SMEM>>>(p_lnt, DD, ca_in_w + (size_t)DD * DD, DD,
                                                p_kv, 2 * DD, ca_in_b + DD, nullptr, 0, DD, 1);
    flash_tf32<<<dim3(4, BHN), 256, FA_SMEM>>>(p_q2, DD, p_kv, 2 * DD,
                                               p_kv + DD, 2 * DD, p_attn, TT, scale);
    gemm_sk<<<dim3(8, 16, 2), 256, GEMM_SMEM>>>(p_attn, DD, ca_out_w, DD, p_part, 512);
    sk_combine<<<(NL * DD) / 256, 256>>>(p_part, ca_out_b, p_x1, DD, p_x2, DD, 0);

    // ===== MoE =====
    ln_kernel<<<NL, 256>>>(p_x2, moe_ln_g, moe_ln_b, p_lnq, p_lnr);
    moe_zero<<<1, 32>>>();
    router_topk<<<NL / 8, 256>>>(p_lnr, router_w, router_b);
    moe_offsets<<<1, 1>>>();
    moe_assign<<<NL / 256, 256>>>();
    moe_gemm_tf32<<<dim3(DFFN / 128, 16, EE), 256, GEMM_SMEM>>>(p_lnq, DD, 1, e_fc1_w, e_fc1_b,
                                                                DFFN, DD, p_h1, DFFN, 1);
    moe_gemm_sk<<<dim3(DD / 128, 32, EE), 256, GEMM_SMEM>>>(p_h1, DFFN, e_fc2_w, e_fc2_b,
                                                            DD, DFFN, p_part2);
    moe_combine2<<<(NL * KKE * DD) / 256, 256>>>(p_part2, p_eo);
    moe_mix<<<(NL * DD) / 256, 256>>>(p_x2, out);
}

// round 13
// speedup vs baseline: 1.0101x; 1.0065x over previous
#include <cuda_runtime.h>
#include <math.h>
#include <stdint.h>

#define DD   1024
#define HH   16
#define DHH  64
#define BB   4
#define LL   512
#define TT   2048
#define EE   8
#define KKE  2
#define DFFN 4096
#define NL   (BB*LL)
#define NT   (BB*TT)
#define BHN  (BB*HH)
#define LN_EPS 1e-5f

// ---------------- scratch ----------------
__device__ float g_lnq[(size_t)NL*DD];
__device__ float g_lnr[(size_t)NL*DD];
__device__ float g_lnt[(size_t)NT*DD];
__device__ float g_qkv[(size_t)NL*3*DD];
__device__ float g_q2 [(size_t)NL*DD];
__device__ float g_kv [(size_t)NT*2*DD];
__device__ float g_attn[(size_t)NL*DD];
__device__ float g_x1 [(size_t)NL*DD];
__device__ float g_x2 [(size_t)NL*DD];
__device__ float g_h1 [(size_t)NL*KKE*DFFN];
__device__ float g_eo [(size_t)NL*KKE*DD];
__device__ float g_part [(size_t)2*NL*DD];
__device__ float g_part2[(size_t)2*NL*KKE*DD];
__device__ int   g_idx [NL*KKE];
__device__ float g_gate[NL*KKE];
__device__ int   g_cnt[EE];
__device__ int   g_off[EE];
__device__ int   g_cur[EE];
__device__ int   g_rowlist[NL*KKE];
__device__ int   g_pairslot[NL*KKE];

// ---------------- helpers ----------------
__device__ __forceinline__ float blk_sum(float v) {
    __shared__ float sh[32];
    int lane = threadIdx.x & 31, w = threadIdx.x >> 5;
    #pragma unroll
    for (int o = 16; o; o >>= 1) v += __shfl_xor_sync(0xffffffffu, v, o);
    if (lane == 0) sh[w] = v;
    __syncthreads();
    if (w == 0) {
        float x = (lane < (int)(blockDim.x >> 5)) ? sh[lane] : 0.f;
        #pragma unroll
        for (int o = 16; o; o >>= 1) x += __shfl_xor_sync(0xffffffffu, x, o);
        if (lane == 0) sh[0] = x;
    }
    __syncthreads();
    float r = sh[0];
    __syncthreads();
    return r;
}

__device__ __forceinline__ float gelu_exact(float x) {
    return 0.5f * x * (1.f + erff(x * 0.70710678118654752f));
}

// ---------------- tf32 mma primitives ----------------
__device__ __forceinline__ uint32_t f2tf(float f) {
    uint32_t u;
    asm("cvt.rna.tf32.f32 %0, %1;" : "=r"(u) : "f"(f));
    return u;
}
__device__ __forceinline__ float rnd_tf(float f) { return __uint_as_float(f2tf(f)); }

__device__ __forceinline__ void mma8(float* cr, const uint32_t* a, const uint32_t* b) {
    asm volatile(
        "mma.sync.aligned.m16n8k8.row.col.f32.tf32.tf32.f32 "
        "{%0,%1,%2,%3}, {%4,%5,%6,%7}, {%8,%9}, {%0,%1,%2,%3};"
        : "+f"(cr[0]), "+f"(cr[1]), "+f"(cr[2]), "+f"(cr[3])
        : "r"(a[0]), "r"(a[1]), "r"(a[2]), "r"(a[3]), "r"(b[0]), "r"(b[1]));
}

__device__ __forceinline__ void ldsm4(uint32_t* r, uint32_t addr) {
    asm volatile("ldmatrix.sync.aligned.m8n8.x4.shared.b16 {%0,%1,%2,%3}, [%4];"
        : "=r"(r[0]), "=r"(r[1]), "=r"(r[2]), "=r"(r[3]) : "r"(addr));
}

__device__ __forceinline__ void cp16(uint32_t dst, const void* src) {
    asm volatile("cp.async.cg.shared.global [%0], [%1], 16;" :: "r"(dst), "l"(src));
}
__device__ __forceinline__ void cp16p(uint32_t dst, const void* src, bool valid) {
    int sz = valid ? 16 : 0;
    asm volatile("cp.async.cg.shared.global [%0], [%1], 16, %2;" :: "r"(dst), "l"(src), "r"(sz));
}
__device__ __forceinline__ void cpcommit() { asm volatile("cp.async.commit_group;"); }
__device__ __forceinline__ void cpwait1() { asm volatile("cp.async.wait_group 1;"); }
__device__ __forceinline__ void cpwait0() { asm volatile("cp.async.wait_group 0;"); }

// 3-stage ring: per stage [A 128x36 | B 128x36]
#define TILE_AB (128*36)
#define STAGE_F (2*TILE_AB)
#define NST 3
#define GEMM_SMEM (NST*STAGE_F*4)   /* 110592 B */

__device__ __forceinline__ void mma_slab(uint32_t a_base, uint32_t b_base,
                                         float (&acc)[4][4][4]) {
    #pragma unroll
    for (int kk = 0; kk < 4; kk++) {
        uint32_t af[4][4];
        #pragma unroll
        for (int mi = 0; mi < 4; mi++)
            ldsm4(af[mi], a_base + (mi * 16 * 36 + kk * 8) * 4);
        uint32_t bq[2][4];
        #pragma unroll
        for (int np = 0; np < 2; np++)
            ldsm4(bq[np], b_base + (np * 16 * 36 + kk * 8) * 4);
        #pragma unroll
        for (int np = 0; np < 2; np++)
            #pragma unroll
            for (int q = 0; q < 4; q++)
                bq[np][q] = f2tf(__uint_as_float(bq[np][q]));
        #pragma unroll
        for (int mi = 0; mi < 4; mi++) {
            #pragma unroll
            for (int np = 0; np < 2; np++) {
                mma8(acc[mi][np * 2 + 0], af[mi], &bq[np][0]);
                mma8(acc[mi][np * 2 + 1], af[mi], &bq[np][2]);
            }
        }
    }
}

template<int WM, int WN, bool BKN, int AST2, int BST>
__device__ __forceinline__ void mma_tile(const float* __restrict__ Ab,
                                         const float* __restrict__ Bb,
                                         int wm, int wn, int g, int c,
                                         float (&acc)[WM][WN][4]) {
    #pragma unroll
    for (int kk = 0; kk < 4; kk++) {
        const int k0 = kk * 8;
        uint32_t af[WM][4];
        #pragma unroll
        for (int mi = 0; mi < WM; mi++) {
            const float* Ar = Ab + (wm + mi * 16 + g) * AST2 + k0 + c;
            af[mi][0] = f2tf(Ar[0]);
            af[mi][1] = f2tf(Ar[8 * AST2]);
            af[mi][2] = f2tf(Ar[4]);
            af[mi][3] = f2tf(Ar[8 * AST2 + 4]);
        }
        uint32_t bf[WN][2];
        #pragma unroll
        for (int ni = 0; ni < WN; ni++) {
            if (BKN) {
                const float* Br = Bb + (k0 + c) * BST + wn + ni * 8 + g;
                bf[ni][0] = f2tf(Br[0]);
                bf[ni][1] = f2tf(Br[4 * BST]);
            } else {
                const float* Br = Bb + (wn + ni * 8 + g) * BST + k0 + c;
                bf[ni][0] = f2tf(Br[0]);
                bf[ni][1] = f2tf(Br[4]);
            }
        }
        #pragma unroll
        for (int mi = 0; mi < WM; mi++)
            #pragma unroll
            for (int ni = 0; ni < WN; ni++)
                mma8(acc[mi][ni], af[mi], bf[ni]);
    }
}

// ---------------- layernorm ----------------
__global__ void __launch_bounds__(256) ln_kernel(const float* __restrict__ x,
                                                 const float* __restrict__ g,
                                                 const float* __restrict__ b,
                                                 float* __restrict__ y,
                                                 float* __restrict__ yraw) {
    size_t row = blockIdx.x;
    const float* xr = x + row * DD;
    float* yr = y + row * DD;
    int t = threadIdx.x;
    float v[4];
    float s = 0.f;
    #pragma unroll
    for (int i = 0; i < 4; i++) { v[i] = xr[t + 256 * i]; s += v[i]; }
    s = blk_sum(s);
    float mean = s * (1.f / DD);
    float s2 = 0.f;
    #pragma unroll
    for (int i = 0; i < 4; i++) { float d = v[i] - mean; s2 += d * d; }
    s2 = blk_sum(s2);
    float inv = rsqrtf(s2 * (1.f / DD) + LN_EPS);
    #pragma unroll
    for (int i = 0; i < 4; i++) {
        int cc = t + 256 * i;
        float o = (v[i] - mean) * inv * g[cc] + b[cc];
        yr[cc] = rnd_tf(o);
        if (yraw) yraw[row * DD + cc] = o;
    }
}

// ---------------- tf32 GEMM ----------------
__global__ void __launch_bounds__(256, 2) gemm_tf32(const float* __restrict__ A, int lda,
                                                    const float* __restrict__ W, int ldw,
                                                    float* __restrict__ C, int ldc,
                                                    const float* __restrict__ bias,
                                                    const float* __restrict__ resid, int ldr,
                                                    int Kd, int round_out) {
    extern __shared__ float sm[];
    int t = threadIdx.x;
    int row0 = blockIdx.y * 128, col0 = blockIdx.x * 128;
    int lrow = t >> 1, lcol = (t & 1) * 16;
    const float* Ag = A + (size_t)(row0 + lrow) * lda + lcol;
    const float* Wg = W + (size_t)(col0 + lrow) * ldw + lcol;
    uint32_t sm_u = (uint32_t)__cvta_generic_to_shared(sm);
    uint32_t as0 = sm_u + (lrow * 36 + lcol) * 4;
    uint32_t bs0 = sm_u + (TILE_AB + lrow * 36 + lcol) * 4;
    int warp = t >> 5, lane = t & 31, g = lane >> 2, c = lane & 3;
    int wm = (warp >> 2) * 64, wn = (warp & 3) * 32;
    uint32_t a_frag = sm_u + ((wm + (lane & 15)) * 36 + (lane >> 4) * 4) * 4;
    uint32_t b_frag = sm_u + (TILE_AB + (wn + ((lane >> 4) << 3) + (lane & 7)) * 36 + ((lane >> 3) & 1) * 4) * 4;
    float acc[4][4][4] = {};
    int KT = Kd >> 5;
    #pragma unroll
    for (int s = 0; s < 2; s++) {
        const float* a = Ag + s * 32;
        const float* w = Wg + s * 32;
        uint32_t so = (uint32_t)(s * STAGE_F * 4);
        #pragma unroll
        for (int i = 0; i < 4; i++) cp16(as0 + so + i * 16, a + i * 4);
        #pragma unroll
        for (int i = 0; i < 4; i++) cp16(bs0 + so + i * 16, w + i * 4);
        cpcommit();
    }
    int sl = 0;
    for (int kt = 0; kt < KT; kt++) {
        cpwait1();
        __syncthreads();
        if (kt + 2 < KT) {
            int sn = sl + 2; if (sn >= NST) sn -= NST;
            const float* a = Ag + (kt + 2) * 32;
            const float* w = Wg + (kt + 2) * 32;
            uint32_t so = (uint32_t)(sn * STAGE_F * 4);
            #pragma unroll
            for (int i = 0; i < 4; i++) cp16(as0 + so + i * 16, a + i * 4);
            #pragma unroll
            for (int i = 0; i < 4; i++) cp16(bs0 + so + i * 16, w + i * 4);
            cpcommit();
        }
        uint32_t so = (uint32_t)(sl * STAGE_F * 4);
        mma_slab(a_frag + so, b_frag + so, acc);
        if (++sl == NST) sl = 0;
    }
    #pragma unroll
    for (int mi = 0; mi < 4; mi++) {
        int r = row0 + wm + mi * 16 + g;
        #pragma unroll
        for (int ni = 0; ni < 4; ni++) {
            int cc = col0 + wn + ni * 8 + c * 2;
            float v0 = acc[mi][ni][0], v1 = acc[mi][ni][1];
            float v2 = acc[mi][ni][2], v3 = acc[mi][ni][3];
            if (bias) { float b0 = bias[cc], b1 = bias[cc + 1]; v0 += b0; v1 += b1; v2 += b0; v3 += b1; }
            if (resid) {
                const float* q0 = resid + (size_t)r * ldr + cc;
                const float* q1 = resid + (size_t)(r + 8) * ldr + cc;
                v0 += q0[0]; v1 += q0[1]; v2 += q1[0]; v3 += q1[1];
            }
            if (round_out) { v0 = rnd_tf(v0); v1 = rnd_tf(v1); v2 = rnd_tf(v2); v3 = rnd_tf(v3); }
            *(float2*)(C + (size_t)r * ldc + cc) = make_float2(v0, v1);
            *(float2*)(C + (size_t)(r + 8) * ldc + cc) = make_float2(v2, v3);
        }
    }
}

// ---------------- split-K tf32 GEMM ----------------
__global__ void __launch_bounds__(256, 2) gemm_sk(const float* __restrict__ A, int lda,
                                                  const float* __restrict__ W, int ldw,
                                                  float* __restrict__ part, int Kh) {
    extern __shared__ float sm[];
    int t = threadIdx.x;
    int z = blockIdx.z;
    int row0 = blockIdx.y * 128, col0 = blockIdx.x * 128;
    int lrow = t >> 1, lcol = (t & 1) * 16;
    const float* Ag = A + (size_t)(row0 + lrow) * lda + z * Kh + lcol;
    const float* Wg = W + (size_t)(col0 + lrow) * ldw + z * Kh + lcol;
    uint32_t sm_u = (uint32_t)__cvta_generic_to_shared(sm);
    uint32_t as0 = sm_u + (lrow * 36 + lcol) * 4;
    uint32_t bs0 = sm_u + (TILE_AB + lrow * 36 + lcol) * 4;
    int warp = t >> 5, lane = t & 31, g = lane >> 2, c = lane & 3;
    int wm = (warp >> 2) * 64, wn = (warp & 3) * 32;
    uint32_t a_frag = sm_u + ((wm + (lane & 15)) * 36 + (lane >> 4) * 4) * 4;
    uint32_t b_frag = sm_u + (TILE_AB + (wn + ((lane >> 4) << 3) + (lane & 7)) * 36 + ((lane >> 3) & 1) * 4) * 4;
    float acc[4][4][4] = {};
    int KT = Kh >> 5;
    #pragma unroll
    for (int s = 0; s < 2; s++) {
        const float* a = Ag + s * 32;
        const float* w = Wg + s * 32;
        uint32_t so = (uint32_t)(s * STAGE_F * 4);
        #pragma unroll
        for (int i = 0; i < 4; i++) cp16(as0 + so + i * 16, a + i * 4);
        #pragma unroll
        for (int i = 0; i < 4; i++) cp16(bs0 + so + i * 16, w + i * 4);
        cpcommit();
    }
    int sl = 0;
    for (int kt = 0; kt < KT; kt++) {
        cpwait1();
        __syncthreads();
        if (kt + 2 < KT) {
            int sn = sl + 2; if (sn >= NST) sn -= NST;
            const float* a = Ag + (kt + 2) * 32;
            const float* w = Wg + (kt + 2) * 32;
            uint32_t so = (uint32_t)(sn * STAGE_F * 4);
            #pragma unroll
            for (int i = 0; i < 4; i++) cp16(as0 + so + i * 16, a + i * 4);
            #pragma unroll
            for (int i = 0; i < 4; i++) cp16(bs0 + so + i * 16, w + i * 4);
            cpcommit();
        }
        uint32_t so = (uint32_t)(sl * STAGE_F * 4);
        mma_slab(a_frag + so, b_frag + so, acc);
        if (++sl == NST) sl = 0;
    }
    float* P = part + (size_t)z * NL * DD;
    #pragma unroll
    for (int mi = 0; mi < 4; mi++) {
        int r = row0 + wm + mi * 16 + g;
        #pragma unroll
        for (int ni = 0; ni < 4; ni++) {
            int cc = col0 + wn + ni * 8 + c * 2;
            *(float2*)(P + (size_t)r * DD + cc) = make_float2(acc[mi][ni][0], acc[mi][ni][1]);
            *(float2*)(P + (size_t)(r + 8) * DD + cc) = make_float2(acc[mi][ni][2], acc[mi][ni][3]);
        }
    }
}

__global__ void __launch_bounds__(256) sk_combine(const float* __restrict__ part,
                                                  const float* __restrict__ bias,
                                                  const float* __restrict__ resid, int ldr,
                                                  float* __restrict__ C, int ldc, int round_out) {
    int i = blockIdx.x * 256 + threadIdx.x;
    int r = i >> 10, d = i & 1023;
    float v = part[i] + part[(size_t)NL * DD + i] + bias[d];
    if (resid) v += resid[(size_t)r * ldr + d];
    if (round_out) v = rnd_tf(v);
    C[(size_t)r * ldc + d] = v;
}

// ---------------- fused flash attention (tf32, single-buffer KV) ----------------
#define FA_N 64
#define FA_QS (128*68)
#define FA_KV (64*68)
#define FA_SMEM ((FA_QS + 2*FA_KV + FA_QS)*4)

__global__ void __launch_bounds__(256, 2) flash_tf32(const float* __restrict__ Q, int ldq,
                                                     const float* __restrict__ Kp, int ldk,
                                                     const float* __restrict__ Vp, int ldv,
                                                     float* __restrict__ O, int Lk, float scale) {
    extern __shared__ float sm[];
    float* Qs = sm;
    float* Ks = Qs + FA_QS;
    float* Vs = Ks + FA_KV;
    float* Ps = Vs + FA_KV;
    int bh = blockIdx.y, b = bh >> 4, h = bh & 15;
    int q0 = blockIdx.x * 128;
    int t = threadIdx.x;
    const float* Qg = Q + ((size_t)(b * LL + q0)) * ldq + h * DHH;
    const float* Kg = Kp + ((size_t)b * Lk) * ldk + h * DHH;
    const float* Vg = Vp + ((size_t)b * Lk) * ldv + h * DHH;
    uint32_t qs0 = (uint32_t)__cvta_generic_to_shared(Qs);
    uint32_t ks0 = (uint32_t)__cvta_generic_to_shared(Ks);
    uint32_t vs0 = (uint32_t)__cvta_generic_to_shared(Vs);
    {
        int row = t >> 1, segb = (t & 1) * 8;
        const float* qr = Qg + (size_t)row * ldq;
        #pragma unroll
        for (int j = 0; j < 8; j++)
            cp16(qs0 + (row * 68 + (segb + j) * 4) * 4, qr + (segb + j) * 4);
    }
    int kr = t >> 2, kcb = (t & 3) * 16;
    {
        const float* kg = Kg + (size_t)kr * ldk + kcb;
        const float* vg = Vg + (size_t)kr * ldv + kcb;
        uint32_t kb = ks0 + (kr * 68 + kcb) * 4;
        uint32_t vb = vs0 + (kr * 68 + kcb) * 4;
        #pragma unroll
        for (int j = 0; j < 4; j++) cp16(kb + j * 16, kg + j * 4);
        #pragma unroll
        for (int j = 0; j < 4; j++) cp16(vb + j * 16, vg + j * 4);
    }
    cpcommit();
    int warp = t >> 5, lane = t & 31, g = lane >> 2, c = lane & 3;
    int wr = warp * 16;
    float Oa[1][8][4] = {};
    float m0 = -INFINITY, m1 = -INFINITY, l0 = 0.f, l1 = 0.f;
    int niter = Lk / FA_N;
    for (int it = 0; it < niter; it++) {
        cpwait0();
        __syncthreads();
        float S[1][8][4] = {};
        mma_tile<1, 8, false, 68, 68>(Qs, Ks, wr, 0, g, c, S);
        mma_tile<1, 8, false, 68, 68>(Qs + 32, Ks + 32, wr, 0, g, c, S);
        float rm0 = -INFINITY, rm1 = -INFINITY;
        #pragma unroll
        for (int ni = 0; ni < 8; ni++) {
            #pragma unroll
            for (int j = 0; j < 4; j++) S[0][ni][j] *= scale;
            rm0 = fmaxf(rm0, fmaxf(S[0][ni][0], S[0][ni][1]));
            rm1 = fmaxf(rm1, fmaxf(S[0][ni][2], S[0][ni][3]));
        }
        rm0 = fmaxf(rm0, __shfl_xor_sync(0xffffffffu, rm0, 1));
        rm0 = fmaxf(rm0, __shfl_xor_sync(0xffffffffu, rm0, 2));
        rm1 = fmaxf(rm1, __shfl_xor_sync(0xffffffffu, rm1, 1));
        rm1 = fmaxf(rm1, __shfl_xor_sync(0xffffffffu, rm1, 2));
        float mn0 = fmaxf(m0, rm0), mn1 = fmaxf(m1, rm1);
        float a0 = __expf(m0 - mn0), a1 = __expf(m1 - mn1);
        float ps0 = 0.f, ps1 = 0.f;
        #pragma unroll
        for (int ni = 0; ni < 8; ni++) {
            float p0 = __expf(S[0][ni][0] - mn0);
            float p1 = __expf(S[0][ni][1] - mn0);
            float p2 = __expf(S[0][ni][2] - mn1);
            float p3 = __expf(S[0][ni][3] - mn1);
            ps0 += p0 + p1; ps1 += p2 + p3;
            *(float2*)&Ps[(wr + g) * 68 + ni * 8 + 2 * c] = make_float2(p0, p1);
            *(float2*)&Ps[(wr + g + 8) * 68 + ni * 8 + 2 * c] = make_float2(p2, p3);
        }
        ps0 += __shfl_xor_sync(0xffffffffu, ps0, 1);
        ps0 += __shfl_xor_sync(0xffffffffu, ps0, 2);
        ps1 += __shfl_xor_sync(0xffffffffu, ps1, 1);
        ps1 += __shfl_xor_sync(0xffffffffu, ps1, 2);
        l0 = l0 * a0 + ps0;
        l1 = l1 * a1 + ps1;
        m0 = mn0; m1 = mn1;
        #pragma unroll
        for (int ni = 0; ni < 8; ni++) {
            Oa[0][ni][0] *= a0; Oa[0][ni][1] *= a0;
            Oa[0][ni][2] *= a1; Oa[0][ni][3] *= a1;
        }
        __syncwarp();
        mma_tile<1, 8, true, 68, 68>(Ps, Vs, wr, 0, g, c, Oa);
        mma_tile<1, 8, true, 68, 68>(Ps + 32, Vs + 32 * 68, wr, 0, g, c, Oa);
        __syncthreads();
        if (it + 1 < niter) {
            const float* kg = Kg + (size_t)((it + 1) * FA_N + kr) * ldk + kcb;
            const float* vg = Vg + (size_t)((it + 1) * FA_N + kr) * ldv + kcb;
            uint32_t kb = ks0 + (kr * 68 + kcb) * 4;
            uint32_t vb = vs0 + (kr * 68 + kcb) * 4;
            #pragma unroll
            for (int j = 0; j < 4; j++) cp16(kb + j * 16, kg + j * 4);
            #pragma unroll
            for (int j = 0; j < 4; j++) cp16(vb + j * 16, vg + j * 4);
            cpcommit();
        }
    }
    float i0 = 1.f / l0, i1 = 1.f / l1;
    float* Og = O + ((size_t)(b * LL + q0 + wr)) * DD + h * DHH;
    #pragma unroll
    for (int ni = 0; ni < 8; ni++) {
        int cc = ni * 8 + 2 * c;
        *(float2*)(Og + (size_t)g * DD + cc) =
            make_float2(rnd_tf(Oa[0][ni][0] * i0), rnd_tf(Oa[0][ni][1] * i0));
        *(float2*)(Og + (size_t)(g + 8) * DD + cc) =
            make_float2(rnd_tf(Oa[0][ni][2] * i1), rnd_tf(Oa[0][ni][3] * i1));
    }
}

// ---------------- MoE routing ----------------
__global__ void moe_zero() {
    if (threadIdx.x < EE) g_cnt[threadIdx.x] = 0;
}

__global__ void __launch_bounds__(256) router_topk(const float* __restrict__ H,
                                                   const float* __restrict__ rw,
                                                   const float* __restrict__ rb) {
    int warp = (blockIdx.x * blockDim.x + threadIdx.x) >> 5;
    int lane = threadIdx.x & 31;
    if (warp >= NL) return;
    const float* h = H + (size_t)warp * DD;
    float logit[EE];
    #pragma unroll
    for (int e = 0; e < EE; e++) {
        const float* w = rw + (size_t)e * DD;
        float s = 0.f;
        for (int d = lane; d < DD; d += 32) s += h[d] * w[d];
        #pragma unroll
        for (int o = 16; o; o >>= 1) s += __shfl_xor_sync(0xffffffffu, s, o);
        logit[e] = s + rb[e];
    }
    if (lane == 0) {
        int i0 = 0; float m0 = logit[0];
        #pragma unroll
        for (int e = 1; e < EE; e++) if (logit[e] > m0) { m0 = logit[e]; i0 = e; }
        int i1 = -1; float m1 = -INFINITY;
        #pragma unroll
        for (int e = 0; e < EE; e++) if (e != i0 && logit[e] > m1) { m1 = logit[e]; i1 = e; }
        float z = expf(m1 - m0);
        float inv = 1.f / (1.f + z);
        g_idx[warp * 2] = i0;  g_idx[warp * 2 + 1] = i1;
        g_gate[warp * 2] = inv; g_gate[warp * 2 + 1] = z * inv;
        atomicAdd(&g_cnt[i0], 1);
        atomicAdd(&g_cnt[i1], 1);
    }
}

__global__ void moe_offsets() {
    if (threadIdx.x == 0) {
        int s = 0;
        for (int e = 0; e < EE; e++) { g_off[e] = s; s += g_cnt[e]; g_cur[e] = 0; }
    }
}

__global__ void __launch_bounds__(256) moe_assign() {
    int n = blockIdx.x * blockDim.x + threadIdx.x;
    if (n >= NL) return;
    #pragma unroll
    for (int k = 0; k < KKE; k++) {
        int e = g_idx[n * 2 + k];
        int pos = atomicAdd(&g_cur[e], 1);
        int slot = g_off[e] + pos;
        g_rowlist[slot] = n;
        g_pairslot[n * 2 + k] = slot;
    }
}

// ---------------- MoE grouped tf32 GEMM (fc1) ----------------
__global__ void __launch_bounds__(256, 2) moe_gemm_tf32(const float* __restrict__ A, int lda, int gather,
                                                        const float* __restrict__ W,
                                                        const float* __restrict__ bias,
                                                        int M, int Kd,
                                                        float* __restrict__ C, int ldc, int act) {
    extern __shared__ float sm[];
    int e = blockIdx.z;
    int count = g_cnt[e];
    int row0 = blockIdx.y * 128;
    if (row0 >= count) return;
    int base = g_off[e];
    const float* We = W + (size_t)e * M * Kd;
    const float* be = bias + (size_t)e * M;
    int col0 = blockIdx.x * 128;
    int t = threadIdx.x;
    int lrow = t >> 1, lcol = (t & 1) * 16;
    int arow = row0 + lrow;
    bool valid = arow < count;
    int src;
    if (gather) src = g_rowlist[base + (valid ? arow : 0)];
    else        src = base + (valid ? arow : 0);
    const float* Ag = A + (size_t)src * lda + lcol;
    const float* Wg = We + (size_t)(col0 + lrow) * Kd + lcol;
    uint32_t sm_u = (uint32_t)__cvta_generic_to_shared(sm);
    uint32_t as0 = sm_u + (lrow * 36 + lcol) * 4;
    uint32_t bs0 = sm_u + (TILE_AB + lrow * 36 + lcol) * 4;
    int warp = t >> 5, lane = t & 31, g = lane >> 2, c = lane & 3;
    int wm = (warp >> 2) * 64, wn = (warp & 3) * 32;
    uint32_t a_frag = sm_u + ((wm + (lane & 15)) * 36 + (lane >> 4) * 4) * 4;
    uint32_t b_frag = sm_u + (TILE_AB + (wn + ((lane >> 4) << 3) + (lane & 7)) * 36 + ((lane >> 3) & 1) * 4) * 4;
    float acc[4][4][4] = {};
    int KT = Kd >> 5;
    #pragma unroll
    for (int s = 0; s < 2; s++) {
        const float* a = Ag + s * 32;
        const float* w = Wg + s * 32;
        uint32_t so = (uint32_t)(s * STAGE_F * 4);
        #pragma unroll
        for (int i = 0; i < 4; i++) cp16p(as0 + so + i * 16, a + i * 4, valid);
        #pragma unroll
        for (int i = 0; i < 4; i++) cp16(bs0 + so + i * 16, w + i * 4);
        cpcommit();
    }
    int sl = 0;
    for (int kt = 0; kt < KT; kt++) {
        cpwait1();
        __syncthreads();
        if (kt + 2 < KT) {
            int sn = sl + 2; if (sn >= NST) sn -= NST;
            const float* a = Ag + (kt + 2) * 32;
            const float* w = Wg + (kt + 2) * 32;
            uint32_t so = (uint32_t)(sn * STAGE_F * 4);
            #pragma unroll
            for (int i = 0; i < 4; i++) cp16p(as0 + so + i * 16, a + i * 4, valid);
            #pragma unroll
            for (int i = 0; i < 4; i++) cp16(bs0 + so + i * 16, w + i * 4);
            cpcommit();
        }
        uint32_t so = (uint32_t)(sl * STAGE_F * 4);
        mma_slab(a_frag + so, b_frag + so, acc);
        if (++sl == NST) sl = 0;
    }
    #pragma unroll
    for (int mi = 0; mi < 4; mi++) {
        int r = row0 + wm + mi * 16 + g;
        #pragma unroll
        for (int ni = 0; ni < 4; ni++) {
            int cc = col0 + wn + ni * 8 + c * 2;
            float b0 = be[cc], b1 = be[cc + 1];
            if (r < count) {
                float v0 = acc[mi][ni][0] + b0, v1 = acc[mi][ni][1] + b1;
                if (act) { v0 = rnd_tf(gelu_exact(v0)); v1 = rnd_tf(gelu_exact(v1)); }
                *(float2*)(C + (size_t)(base + r) * ldc + cc) = make_float2(v0, v1);
            }
            if (r + 8 < count) {
                float v2 = acc[mi][ni][2] + b0, v3 = acc[mi][ni][3] + b1;
                if (act) { v2 = rnd_tf(gelu_exact(v2)); v3 = rnd_tf(gelu_exact(v3)); }
                *(float2*)(C + (size_t)(base + r + 8) * ldc + cc) = make_float2(v2, v3);
            }
        }
    }
}

// ---------------- MoE fc2 split-K ----------------
__global__ void __launch_bounds__(256, 2) moe_gemm_sk(const float* __restrict__ A, int lda,
                                                      const float* __restrict__ W,
                                                      const float* __restrict__ bias,
                                                      int M, int Kd,
                                                      float* __restrict__ part) {
    extern __shared__ float sm[];
    int e = blockIdx.z;
    int count = g_cnt[e];
    int rt = blockIdx.y & 15, kz = blockIdx.y >> 4;
    int row0 = rt * 128;
    if (row0 >= count) return;
    int Kh = Kd >> 1;
    int base = g_off[e];
    const float* We = W + (size_t)e * M * Kd;
    const float* be = bias + (size_t)e * M;
    int col0 = blockIdx.x * 128;
    int t = threadIdx.x;
    int lrow = t >> 1, lcol = (t & 1) * 16;
    int arow = row0 + lrow;
    bool valid = arow < count;
    int src = base + (valid ? arow : 0);
    const float* Ag = A + (size_t)src * lda + kz * Kh + lcol;
    const float* Wg = We + (size_t)(col0 + lrow) * Kd + kz * Kh + lcol;
    uint32_t sm_u = (uint32_t)__cvta_generic_to_shared(sm);
    uint32_t as0 = sm_u + (lrow * 36 + lcol) * 4;
    uint32_t bs0 = sm_u + (TILE_AB + lrow * 36 + lcol) * 4;
    int warp = t >> 5, lane = t & 31, g = lane >> 2, c = lane & 3;
    int wm = (warp >> 2) * 64, wn = (warp & 3) * 32;
    uint32_t a_frag = sm_u + ((wm + (lane & 15)) * 36 + (lane >> 4) * 4) * 4;
    uint32_t b_frag = sm_u + (TILE_AB + (wn + ((lane >> 4) << 3) + (lane & 7)) * 36 + ((lane >> 3) & 1) * 4) * 4;
    float acc[4][4][4] = {};
    int KT = Kh >> 5;
    #pragma unroll
    for (int s = 0; s < 2; s++) {
        const float* a = Ag + s * 32;
        const float* w = Wg + s * 32;
        uint32_t so = (uint32_t)(s * STAGE_F * 4);
        #pragma unroll
        for (int i = 0; i < 4; i++) cp16p(as0 + so + i * 16, a + i * 4, valid);
        #pragma unroll
        for (int i = 0; i < 4; i++) cp16(bs0 + so + i * 16, w + i * 4);
        cpcommit();
    }
    int sl = 0;
    for (int kt = 0; kt < KT; kt++) {
        cpwait1();
        __syncthreads();
        if (kt + 2 < KT) {
            int sn = sl + 2; if (sn >= NST) sn -= NST;
            const float* a = Ag + (kt + 2) * 32;
            const float* w = Wg + (kt + 2) * 32;
            uint32_t so = (uint32_t)(sn * STAGE_F * 4);
            #pragma unroll
            for (int i = 0; i < 4; i++) cp16p(as0 + so + i * 16, a + i * 4, valid);
            #pragma unroll
            for (int i = 0; i < 4; i++) cp16(bs0 + so + i * 16, w + i * 4);
            cpcommit();
        }
        uint32_t so = (uint32_t)(sl * STAGE_F * 4);
        mma_slab(a_frag + so, b_frag + so, acc);
        if (++sl == NST) sl = 0;
    }
    float* P = part + (size_t)kz * NL * KKE * DD;
    #pragma unroll
    for (int mi = 0; mi < 4; mi++) {
        int r = row0 + wm + mi * 16 + g;
        #pragma unroll
        for (int ni = 0; ni < 4; ni++) {
            int cc = col0 + wn + ni * 8 + c * 2;
            float b0 = (kz == 0) ? be[cc] : 0.f;
            float b1 = (kz == 0) ? be[cc + 1] : 0.f;
            if (r < count) {
                *(float2*)(P + (size_t)(base + r) * DD + cc) =
                    make_float2(acc[mi][ni][0] + b0, acc[mi][ni][1] + b1);
            }
            if (r + 8 < count) {
                *(float2*)(P + (size_t)(base + r + 8) * DD + cc) =
                    make_float2(acc[mi][ni][2] + b0, acc[mi][ni][3] + b1);
            }
        }
    }
}

__global__ void __launch_bounds__(256) moe_combine2(const float* __restrict__ part,
                                                    float* __restrict__ eo) {
    int i = blockIdx.x * 256 + threadIdx.x;
    eo[i] = part[i] + part[(size_t)NL * KKE * DD + i];
}

// ---------------- final mix ----------------
__global__ void __launch_bounds__(256) moe_mix(const float* __restrict__ x2,
                                               float* __restrict__ out) {
    int i = blockIdx.x * 256 + threadIdx.x;
    int n = i >> 10;
    int d = i & 1023;
    float v = x2[i];
    int s0 = g_pairslot[n * 2], s1 = g_pairslot[n * 2 + 1];
    v += g_gate[n * 2]     * g_eo[(size_t)s0 * DD + d];
    v += g_gate[n * 2 + 1] * g_eo[(size_t)s1 * DD + d];
    out[i] = v;
}

// ---------------- launch ----------------
extern "C" void kernel_launch(void* const* d_in, const int* in_sizes, int n_in,
                              void* d_out, int out_size) {
    const float* latents    = (const float*)d_in[0];
    const float* tokens     = (const float*)d_in[1];
    const float* sa_ln_g    = (const float*)d_in[2];
    const float* sa_ln_b    = (const float*)d_in[3];
    const float* sa_in_w    = (const float*)d_in[4];
    const float* sa_in_b    = (const float*)d_in[5];
    const float* sa_out_w   = (const float*)d_in[6];
    const float* sa_out_b   = (const float*)d_in[7];
    const float* ca_q_ln_g  = (const float*)d_in[8];
    const float* ca_q_ln_b  = (const float*)d_in[9];
    const float* ca_kv_ln_g = (const float*)d_in[10];
    const float* ca_kv_ln_b = (const float*)d_in[11];
    const float* ca_in_w    = (const float*)d_in[12];
    const float* ca_in_b    = (const float*)d_in[13];
    const float* ca_out_w   = (const float*)d_in[14];
    const float* ca_out_b   = (const float*)d_in[15];
    const float* moe_ln_g   = (const float*)d_in[16];
    const float* moe_ln_b   = (const float*)d_in[17];
    const float* router_w   = (const float*)d_in[18];
    const float* router_b   = (const float*)d_in[19];
    const float* e_fc1_w    = (const float*)d_in[20];
    const float* e_fc1_b    = (const float*)d_in[21];
    const float* e_fc2_w    = (const float*)d_in[22];
    const float* e_fc2_b    = (const float*)d_in[23];
    float* out = (float*)d_out;

    static int s_init = 0;
    static cudaStream_t s2;
    static cudaEvent_t ev_fork, ev_join;
    if (!s_init) {
        cudaFuncSetAttribute(gemm_tf32, cudaFuncAttributeMaxDynamicSharedMemorySize, GEMM_SMEM);
        cudaFuncSetAttribute(gemm_sk, cudaFuncAttributeMaxDynamicSharedMemorySize, GEMM_SMEM);
        cudaFuncSetAttribute(moe_gemm_tf32, cudaFuncAttributeMaxDynamicSharedMemorySize, GEMM_SMEM);
        cudaFuncSetAttribute(moe_gemm_sk, cudaFuncAttributeMaxDynamicSharedMemorySize, GEMM_SMEM);
        cudaFuncSetAttribute(flash_tf32, cudaFuncAttributeMaxDynamicSharedMemorySize, FA_SMEM);
        cudaStreamCreateWithFlags(&s2, cudaStreamNonBlocking);
        cudaEventCreateWithFlags(&ev_fork, cudaEventDisableTiming);
        cudaEventCreateWithFlags(&ev_join, cudaEventDisableTiming);
        s_init = 1;
    }

    float *p_lnq, *p_lnr, *p_lnt, *p_qkv, *p_q2, *p_kv, *p_attn, *p_x1, *p_x2, *p_h1, *p_eo;
    float *p_part, *p_part2;
    cudaGetSymbolAddress((void**)&p_lnq,  g_lnq);
    cudaGetSymbolAddress((void**)&p_lnr,  g_lnr);
    cudaGetSymbolAddress((void**)&p_lnt,  g_lnt);
    cudaGetSymbolAddress((void**)&p_qkv,  g_qkv);
    cudaGetSymbolAddress((void**)&p_q2,   g_q2);
    cudaGetSymbolAddress((void**)&p_kv,   g_kv);
    cudaGetSymbolAddress((void**)&p_attn, g_attn);
    cudaGetSymbolAddress((void**)&p_x1,   g_x1);
    cudaGetSymbolAddress((void**)&p_x2,   g_x2);
    cudaGetSymbolAddress((void**)&p_h1,   g_h1);
    cudaGetSymbolAddress((void**)&p_eo,   g_eo);
    cudaGetSymbolAddress((void**)&p_part, g_part);
    cudaGetSymbolAddress((void**)&p_part2, g_part2);

    const float scale = 0.125f;

    // ===== fork: token LN + KV projection run concurrently with the SA chain =====
    cudaEventRecord(ev_fork, 0);
    cudaStreamWaitEvent(s2, ev_fork, 0);
    ln_kernel<<<NT, 256, 0, s2>>>(tokens, ca_kv_ln_g, ca_kv_ln_b, p_lnt, nullptr);
    gemm_tf32<<<dim3(16, 64), 256, GEMM_SMEM, s2>>>(p_lnt, DD, ca_in_w + (size_t)DD * DD, DD,
                                                    p_kv, 2 * DD, ca_in_b + DD, nullptr, 0, DD, 1);
    cudaEventRecord(ev_join, s2);

    // ===== Self-attention (main stream) =====
    ln_kernel<<<NL, 256>>>(latents, sa_ln_g, sa_ln_b, p_lnq, nullptr);
    gemm_tf32<<<dim3(24, 16), 256, GEMM_SMEM>>>(p_lnq, DD, sa_in_w, DD, p_qkv, 3 * DD,
                                                sa_in_b, nullptr, 0, DD, 1);
    flash_tf32<<<dim3(4, BHN), 256, FA_SMEM>>>(p_qkv, 3 * DD, p_qkv + DD, 3 * DD,
                                               p_qkv + 2 * DD, 3 * DD, p_attn, LL, scale);
    gemm_sk<<<dim3(8, 16, 2), 256, GEMM_SMEM>>>(p_attn, DD, sa_out_w, DD, p_part, 512);
    sk_combine<<<(NL * DD) / 256, 256>>>(p_part, sa_out_b, latents, DD, p_x1, DD, 0);

    // ===== Cross-attention (q side) =====
    ln_kernel<<<NL, 256>>>(p_x1, ca_q_ln_g, ca_q_ln_b, p_lnq, nullptr);
    gemm_sk<<<dim3(8, 16, 2), 256, GEMM_SMEM>>>(p_lnq, DD, ca_in_w, DD, p_part, 512);
    sk_combine<<<(NL * DD) / 256, 256>>>(p_part, ca_in_b, nullptr, 0, p_q2, DD, 1);

    // join: KV must be ready before flash CA
    cudaStreamWaitEvent(0, ev_join, 0);
    flash_tf32<<<dim3(4, BHN), 256, FA_SMEM>>>(p_q2, DD, p_kv, 2 * DD,
                                               p_kv + DD, 2 * DD, p_attn, TT, scale);
    gemm_sk<<<dim3(8, 16, 2), 256, GEMM_SMEM>>>(p_attn, DD, ca_out_w, DD, p_part, 512);
    sk_combine<<<(NL * DD) / 256, 256>>>(p_part, ca_out_b, p_x1, DD, p_x2, DD, 0);

    // ===== MoE =====
    ln_kernel<<<NL, 256>>>(p_x2, moe_ln_g, moe_ln_b, p_lnq, p_lnr);
    moe_zero<<<1, 32>>>();
    router_topk<<<NL / 8, 256>>>(p_lnr, router_w, router_b);
    moe_offsets<<<1, 1>>>();
    moe_assign<<<NL / 256, 256>>>();
    moe_gemm_tf32<<<dim3(DFFN / 128, 16, EE), 256, GEMM_SMEM>>>(p_lnq, DD, 1, e_fc1_w, e_fc1_b,
                                                                DFFN, DD, p_h1, DFFN, 1);
    moe_gemm_sk<<<dim3(DD / 128, 32, EE), 256, GEMM_SMEM>>>(p_h1, DFFN, e_fc2_w, e_fc2_b,
                                                            DD, DFFN, p_part2);
    moe_combine2<<<(NL * KKE * DD) / 256, 256>>>(p_part2, p_eo);
    moe_mix<<<(NL * DD) / 256, 256>>>(p_x2, out);
}

// round 14
// speedup vs baseline: 1.0280x; 1.0177x over previous
#include <cuda_runtime.h>
#include <math.h>
#include <stdint.h>

#define DD   1024
#define HH   16
#define DHH  64
#define BB   4
#define LL   512
#define TT   2048
#define EE   8
#define KKE  2
#define DFFN 4096
#define NL   (BB*LL)
#define NT   (BB*TT)
#define BHN  (BB*HH)
#define LN_EPS 1e-5f

// ---------------- scratch ----------------
__device__ float g_lnq[(size_t)NL*DD];
__device__ float g_lnr[(size_t)NL*DD];
__device__ float g_lnt[(size_t)NT*DD];
__device__ float g_qkv[(size_t)NL*3*DD];
__device__ float g_q2 [(size_t)NL*DD];
__device__ float g_kv [(size_t)NT*2*DD];
__device__ float g_attn[(size_t)NL*DD];
__device__ float g_x1 [(size_t)NL*DD];
__device__ float g_x2 [(size_t)NL*DD];
__device__ float g_h1 [(size_t)NL*KKE*DFFN];
__device__ float g_eo [(size_t)NL*KKE*DD];
__device__ float g_part [(size_t)2*NL*DD];
__device__ float g_part2[(size_t)2*NL*KKE*DD];
__device__ int   g_idx [NL*KKE];
__device__ float g_gate[NL*KKE];
__device__ int   g_cnt[EE];
__device__ int   g_off[EE];
__device__ int   g_cur[EE];
__device__ int   g_rowlist[NL*KKE];
__device__ int   g_pairslot[NL*KKE];
// tf32-pre-rounded weight copies (invariant per launch; rounding = rna, same as inline cvt)
__device__ float g_w_sain [(size_t)3*DD*DD];
__device__ float g_w_saout[(size_t)DD*DD];
__device__ float g_w_cain [(size_t)3*DD*DD];
__device__ float g_w_caout[(size_t)DD*DD];
__device__ float g_w_fc1  [(size_t)EE*DFFN*DD];
__device__ float g_w_fc2  [(size_t)EE*DD*DFFN];

// ---------------- helpers ----------------
__device__ __forceinline__ float blk_sum(float v) {
    __shared__ float sh[32];
    int lane = threadIdx.x & 31, w = threadIdx.x >> 5;
    #pragma unroll
    for (int o = 16; o; o >>= 1) v += __shfl_xor_sync(0xffffffffu, v, o);
    if (lane == 0) sh[w] = v;
    __syncthreads();
    if (w == 0) {
        float x = (lane < (int)(blockDim.x >> 5)) ? sh[lane] : 0.f;
        #pragma unroll
        for (int o = 16; o; o >>= 1) x += __shfl_xor_sync(0xffffffffu, x, o);
        if (lane == 0) sh[0] = x;
    }
    __syncthreads();
    float r = sh[0];
    __syncthreads();
    return r;
}

__device__ __forceinline__ float gelu_exact(float x) {
    return 0.5f * x * (1.f + erff(x * 0.70710678118654752f));
}

// ---------------- tf32 mma primitives ----------------
__device__ __forceinline__ uint32_t f2tf(float f) {
    uint32_t u;
    asm("cvt.rna.tf32.f32 %0, %1;" : "=r"(u) : "f"(f));
    return u;
}
__device__ __forceinline__ float rnd_tf(float f) { return __uint_as_float(f2tf(f)); }

__device__ __forceinline__ void mma8(float* cr, const uint32_t* a, const uint32_t* b) {
    asm volatile(
        "mma.sync.aligned.m16n8k8.row.col.f32.tf32.tf32.f32 "
        "{%0,%1,%2,%3}, {%4,%5,%6,%7}, {%8,%9}, {%0,%1,%2,%3};"
        : "+f"(cr[0]), "+f"(cr[1]), "+f"(cr[2]), "+f"(cr[3])
        : "r"(a[0]), "r"(a[1]), "r"(a[2]), "r"(a[3]), "r"(b[0]), "r"(b[1]));
}

__device__ __forceinline__ void ldsm4(uint32_t* r, uint32_t addr) {
    asm volatile("ldmatrix.sync.aligned.m8n8.x4.shared.b16 {%0,%1,%2,%3}, [%4];"
        : "=r"(r[0]), "=r"(r[1]), "=r"(r[2]), "=r"(r[3]) : "r"(addr));
}

__device__ __forceinline__ void cp16(uint32_t dst, const void* src) {
    asm volatile("cp.async.cg.shared.global [%0], [%1], 16;" :: "r"(dst), "l"(src));
}
__device__ __forceinline__ void cp16p(uint32_t dst, const void* src, bool valid) {
    int sz = valid ? 16 : 0;
    asm volatile("cp.async.cg.shared.global [%0], [%1], 16, %2;" :: "r"(dst), "l"(src), "r"(sz));
}
__device__ __forceinline__ void cpcommit() { asm volatile("cp.async.commit_group;"); }
__device__ __forceinline__ void cpwait1() { asm volatile("cp.async.wait_group 1;"); }
__device__ __forceinline__ void cpwait0() { asm volatile("cp.async.wait_group 0;"); }

// 3-stage ring: per stage [A 128x36 | B 128x36]
#define TILE_AB (128*36)
#define STAGE_F (2*TILE_AB)
#define NST 3
#define GEMM_SMEM (NST*STAGE_F*4)   /* 110592 B */

// one 32-k slab. BOTH operands pre-rounded tf32 -> raw bits, zero cvts.
__device__ __forceinline__ void mma_slab(uint32_t a_base, uint32_t b_base,
                                         float (&acc)[4][4][4]) {
    #pragma unroll
    for (int kk = 0; kk < 4; kk++) {
        uint32_t af[4][4];
        #pragma unroll
        for (int mi = 0; mi < 4; mi++)
            ldsm4(af[mi], a_base + (mi * 16 * 36 + kk * 8) * 4);
        uint32_t bq[2][4];
        #pragma unroll
        for (int np = 0; np < 2; np++)
            ldsm4(bq[np], b_base + (np * 16 * 36 + kk * 8) * 4);
        #pragma unroll
        for (int mi = 0; mi < 4; mi++) {
            #pragma unroll
            for (int np = 0; np < 2; np++) {
                mma8(acc[mi][np * 2 + 0], af[mi], &bq[np][0]);
                mma8(acc[mi][np * 2 + 1], af[mi], &bq[np][2]);
            }
        }
    }
}

// float-smem slab (flash). CVTA/CVTB: whether operand needs rounding (false when
// producer already rounded -> cvt would be identity, skip it).
template<int WM, int WN, bool BKN, int AST2, int BST, bool CVTA, bool CVTB>
__device__ __forceinline__ void mma_tile(const float* __restrict__ Ab,
                                         const float* __restrict__ Bb,
                                         int wm, int wn, int g, int c,
                                         float (&acc)[WM][WN][4]) {
    #pragma unroll
    for (int kk = 0; kk < 4; kk++) {
        const int k0 = kk * 8;
        uint32_t af[WM][4];
        #pragma unroll
        for (int mi = 0; mi < WM; mi++) {
            const float* Ar = Ab + (wm + mi * 16 + g) * AST2 + k0 + c;
            float a0 = Ar[0], a1 = Ar[8 * AST2], a2 = Ar[4], a3 = Ar[8 * AST2 + 4];
            af[mi][0] = CVTA ? f2tf(a0) : __float_as_uint(a0);
            af[mi][1] = CVTA ? f2tf(a1) : __float_as_uint(a1);
            af[mi][2] = CVTA ? f2tf(a2) : __float_as_uint(a2);
            af[mi][3] = CVTA ? f2tf(a3) : __float_as_uint(a3);
        }
        uint32_t bf[WN][2];
        #pragma unroll
        for (int ni = 0; ni < WN; ni++) {
            float b0, b1;
            if (BKN) {
                const float* Br = Bb + (k0 + c) * BST + wn + ni * 8 + g;
                b0 = Br[0]; b1 = Br[4 * BST];
            } else {
                const float* Br = Bb + (wn + ni * 8 + g) * BST + k0 + c;
                b0 = Br[0]; b1 = Br[4];
            }
            bf[ni][0] = CVTB ? f2tf(b0) : __float_as_uint(b0);
            bf[ni][1] = CVTB ? f2tf(b1) : __float_as_uint(b1);
        }
        #pragma unroll
        for (int mi = 0; mi < WM; mi++)
            #pragma unroll
            for (int ni = 0; ni < WN; ni++)
                mma8(acc[mi][ni], af[mi], bf[ni]);
    }
}

// ---------------- weight pre-round ----------------
__global__ void __launch_bounds__(256) rnd_w4(const float* __restrict__ s,
                                              float* __restrict__ d, int n4) {
    int i = blockIdx.x * 256 + threadIdx.x;
    if (i < n4) {
        float4 v = *(const float4*)(s + (size_t)i * 4);
        v.x = rnd_tf(v.x); v.y = rnd_tf(v.y); v.z = rnd_tf(v.z); v.w = rnd_tf(v.w);
        *(float4*)(d + (size_t)i * 4) = v;
    }
}

// ---------------- layernorm ----------------
__global__ void __launch_bounds__(256) ln_kernel(const float* __restrict__ x,
                                                 const float* __restrict__ g,
                                                 const float* __restrict__ b,
                                                 float* __restrict__ y,
                                                 float* __restrict__ yraw) {
    size_t row = blockIdx.x;
    const float* xr = x + row * DD;
    float* yr = y + row * DD;
    int t = threadIdx.x;
    float v[4];
    float s = 0.f;
    #pragma unroll
    for (int i = 0; i < 4; i++) { v[i] = xr[t + 256 * i]; s += v[i]; }
    s = blk_sum(s);
    float mean = s * (1.f / DD);
    float s2 = 0.f;
    #pragma unroll
    for (int i = 0; i < 4; i++) { float d = v[i] - mean; s2 += d * d; }
    s2 = blk_sum(s2);
    float inv = rsqrtf(s2 * (1.f / DD) + LN_EPS);
    #pragma unroll
    for (int i = 0; i < 4; i++) {
        int cc = t + 256 * i;
        float o = (v[i] - mean) * inv * g[cc] + b[cc];
        yr[cc] = rnd_tf(o);
        if (yraw) yraw[row * DD + cc] = o;
    }
}

// ---------------- tf32 GEMM (both operands pre-rounded) ----------------
__global__ void __launch_bounds__(256, 2) gemm_tf32(const float* __restrict__ A, int lda,
                                                    const float* __restrict__ W, int ldw,
                                                    float* __restrict__ C, int ldc,
                                                    const float* __restrict__ bias,
                                                    const float* __restrict__ resid, int ldr,
                                                    int Kd, int round_out) {
    extern __shared__ float sm[];
    int t = threadIdx.x;
    int row0 = blockIdx.y * 128, col0 = blockIdx.x * 128;
    int lrow = t >> 1, lcol = (t & 1) * 16;
    const float* Ag = A + (size_t)(row0 + lrow) * lda + lcol;
    const float* Wg = W + (size_t)(col0 + lrow) * ldw + lcol;
    uint32_t sm_u = (uint32_t)__cvta_generic_to_shared(sm);
    uint32_t as0 = sm_u + (lrow * 36 + lcol) * 4;
    uint32_t bs0 = sm_u + (TILE_AB + lrow * 36 + lcol) * 4;
    int warp = t >> 5, lane = t & 31, g = lane >> 2, c = lane & 3;
    int wm = (warp >> 2) * 64, wn = (warp & 3) * 32;
    uint32_t a_frag = sm_u + ((wm + (lane & 15)) * 36 + (lane >> 4) * 4) * 4;
    uint32_t b_frag = sm_u + (TILE_AB + (wn + ((lane >> 4) << 3) + (lane & 7)) * 36 + ((lane >> 3) & 1) * 4) * 4;
    float acc[4][4][4] = {};
    int KT = Kd >> 5;
    #pragma unroll
    for (int s = 0; s < 2; s++) {
        const float* a = Ag + s * 32;
        const float* w = Wg + s * 32;
        uint32_t so = (uint32_t)(s * STAGE_F * 4);
        #pragma unroll
        for (int i = 0; i < 4; i++) cp16(as0 + so + i * 16, a + i * 4);
        #pragma unroll
        for (int i = 0; i < 4; i++) cp16(bs0 + so + i * 16, w + i * 4);
        cpcommit();
    }
    int sl = 0;
    for (int kt = 0; kt < KT; kt++) {
        cpwait1();
        __syncthreads();
        if (kt + 2 < KT) {
            int sn = sl + 2; if (sn >= NST) sn -= NST;
            const float* a = Ag + (kt + 2) * 32;
            const float* w = Wg + (kt + 2) * 32;
            uint32_t so = (uint32_t)(sn * STAGE_F * 4);
            #pragma unroll
            for (int i = 0; i < 4; i++) cp16(as0 + so + i * 16, a + i * 4);
            #pragma unroll
            for (int i = 0; i < 4; i++) cp16(bs0 + so + i * 16, w + i * 4);
            cpcommit();
        }
        uint32_t so = (uint32_t)(sl * STAGE_F * 4);
        mma_slab(a_frag + so, b_frag + so, acc);
        if (++sl == NST) sl = 0;
    }
    #pragma unroll
    for (int mi = 0; mi < 4; mi++) {
        int r = row0 + wm + mi * 16 + g;
        #pragma unroll
        for (int ni = 0; ni < 4; ni++) {
            int cc = col0 + wn + ni * 8 + c * 2;
            float v0 = acc[mi][ni][0], v1 = acc[mi][ni][1];
            float v2 = acc[mi][ni][2], v3 = acc[mi][ni][3];
            if (bias) { float b0 = bias[cc], b1 = bias[cc + 1]; v0 += b0; v1 += b1; v2 += b0; v3 += b1; }
            if (resid) {
                const float* q0 = resid + (size_t)r * ldr + cc;
                const float* q1 = resid + (size_t)(r + 8) * ldr + cc;
                v0 += q0[0]; v1 += q0[1]; v2 += q1[0]; v3 += q1[1];
            }
            if (round_out) { v0 = rnd_tf(v0); v1 = rnd_tf(v1); v2 = rnd_tf(v2); v3 = rnd_tf(v3); }
            *(float2*)(C + (size_t)r * ldc + cc) = make_float2(v0, v1);
            *(float2*)(C + (size_t)(r + 8) * ldc + cc) = make_float2(v2, v3);
        }
    }
}

// ---------------- split-K tf32 GEMM ----------------
__global__ void __launch_bounds__(256, 2) gemm_sk(const float* __restrict__ A, int lda,
                                                  const float* __restrict__ W, int ldw,
                                                  float* __restrict__ part, int Kh) {
    extern __shared__ float sm[];
    int t = threadIdx.x;
    int z = blockIdx.z;
    int row0 = blockIdx.y * 128, col0 = blockIdx.x * 128;
    int lrow = t >> 1, lcol = (t & 1) * 16;
    const float* Ag = A + (size_t)(row0 + lrow) * lda + z * Kh + lcol;
    const float* Wg = W + (size_t)(col0 + lrow) * ldw + z * Kh + lcol;
    uint32_t sm_u = (uint32_t)__cvta_generic_to_shared(sm);
    uint32_t as0 = sm_u + (lrow * 36 + lcol) * 4;
    uint32_t bs0 = sm_u + (TILE_AB + lrow * 36 + lcol) * 4;
    int warp = t >> 5, lane = t & 31, g = lane >> 2, c = lane & 3;
    int wm = (warp >> 2) * 64, wn = (warp & 3) * 32;
    uint32_t a_frag = sm_u + ((wm + (lane & 15)) * 36 + (lane >> 4) * 4) * 4;
    uint32_t b_frag = sm_u + (TILE_AB + (wn + ((lane >> 4) << 3) + (lane & 7)) * 36 + ((lane >> 3) & 1) * 4) * 4;
    float acc[4][4][4] = {};
    int KT = Kh >> 5;
    #pragma unroll
    for (int s = 0; s < 2; s++) {
        const float* a = Ag + s * 32;
        const float* w = Wg + s * 32;
        uint32_t so = (uint32_t)(s * STAGE_F * 4);
        #pragma unroll
        for (int i = 0; i < 4; i++) cp16(as0 + so + i * 16, a + i * 4);
        #pragma unroll
        for (int i = 0; i < 4; i++) cp16(bs0 + so + i * 16, w + i * 4);
        cpcommit();
    }
    int sl = 0;
    for (int kt = 0; kt < KT; kt++) {
        cpwait1();
        __syncthreads();
        if (kt + 2 < KT) {
            int sn = sl + 2; if (sn >= NST) sn -= NST;
            const float* a = Ag + (kt + 2) * 32;
            const float* w = Wg + (kt + 2) * 32;
            uint32_t so = (uint32_t)(sn * STAGE_F * 4);
            #pragma unroll
            for (int i = 0; i < 4; i++) cp16(as0 + so + i * 16, a + i * 4);
            #pragma unroll
            for (int i = 0; i < 4; i++) cp16(bs0 + so + i * 16, w + i * 4);
            cpcommit();
        }
        uint32_t so = (uint32_t)(sl * STAGE_F * 4);
        mma_slab(a_frag + so, b_frag + so, acc);
        if (++sl == NST) sl = 0;
    }
    float* P = part + (size_t)z * NL * DD;
    #pragma unroll
    for (int mi = 0; mi < 4; mi++) {
        int r = row0 + wm + mi * 16 + g;
        #pragma unroll
        for (int ni = 0; ni < 4; ni++) {
            int cc = col0 + wn + ni * 8 + c * 2;
            *(float2*)(P + (size_t)r * DD + cc) = make_float2(acc[mi][ni][0], acc[mi][ni][1]);
            *(float2*)(P + (size_t)(r + 8) * DD + cc) = make_float2(acc[mi][ni][2], acc[mi][ni][3]);
        }
    }
}

__global__ void __launch_bounds__(256) sk_combine(const float* __restrict__ part,
                                                  const float* __restrict__ bias,
                                                  const float* __restrict__ resid, int ldr,
                                                  float* __restrict__ C, int ldc, int round_out) {
    int i = blockIdx.x * 256 + threadIdx.x;
    int r = i >> 10, d = i & 1023;
    float v = part[i] + part[(size_t)NL * DD + i] + bias[d];
    if (resid) v += resid[(size_t)r * ldr + d];
    if (round_out) v = rnd_tf(v);
    C[(size_t)r * ldc + d] = v;
}

// ---------------- fused flash attention (tf32, single-buffer KV) ----------------
#define FA_N 64
#define FA_QS (128*68)
#define FA_KV (64*68)
#define FA_SMEM ((FA_QS + 2*FA_KV + FA_QS)*4)

__global__ void __launch_bounds__(256, 2) flash_tf32(const float* __restrict__ Q, int ldq,
                                                     const float* __restrict__ Kp, int ldk,
                                                     const float* __restrict__ Vp, int ldv,
                                                     float* __restrict__ O, int Lk, float scale) {
    extern __shared__ float sm[];
    float* Qs = sm;
    float* Ks = Qs + FA_QS;
    float* Vs = Ks + FA_KV;
    float* Ps = Vs + FA_KV;
    int bh = blockIdx.y, b = bh >> 4, h = bh & 15;
    int q0 = blockIdx.x * 128;
    int t = threadIdx.x;
    const float* Qg = Q + ((size_t)(b * LL + q0)) * ldq + h * DHH;
    const float* Kg = Kp + ((size_t)b * Lk) * ldk + h * DHH;
    const float* Vg = Vp + ((size_t)b * Lk) * ldv + h * DHH;
    uint32_t qs0 = (uint32_t)__cvta_generic_to_shared(Qs);
    uint32_t ks0 = (uint32_t)__cvta_generic_to_shared(Ks);
    uint32_t vs0 = (uint32_t)__cvta_generic_to_shared(Vs);
    {
        int row = t >> 1, segb = (t & 1) * 8;
        const float* qr = Qg + (size_t)row * ldq;
        #pragma unroll
        for (int j = 0; j < 8; j++)
            cp16(qs0 + (row * 68 + (segb + j) * 4) * 4, qr + (segb + j) * 4);
    }
    int kr = t >> 2, kcb = (t & 3) * 16;
    {
        const float* kg = Kg + (size_t)kr * ldk + kcb;
        const float* vg = Vg + (size_t)kr * ldv + kcb;
        uint32_t kb = ks0 + (kr * 68 + kcb) * 4;
        uint32_t vb = vs0 + (kr * 68 + kcb) * 4;
        #pragma unroll
        for (int j = 0; j < 4; j++) cp16(kb + j * 16, kg + j * 4);
        #pragma unroll
        for (int j = 0; j < 4; j++) cp16(vb + j * 16, vg + j * 4);
    }
    cpcommit();
    int warp = t >> 5, lane = t & 31, g = lane >> 2, c = lane & 3;
    int wr = warp * 16;
    float Oa[1][8][4] = {};
    float m0 = -INFINITY, m1 = -INFINITY, l0 = 0.f, l1 = 0.f;
    int niter = Lk / FA_N;
    for (int it = 0; it < niter; it++) {
        cpwait0();
        __syncthreads();
        float S[1][8][4] = {};
        // Q and K pre-rounded by producers -> raw bits, no cvt
        mma_tile<1, 8, false, 68, 68, false, false>(Qs, Ks, wr, 0, g, c, S);
        mma_tile<1, 8, false, 68, 68, false, false>(Qs + 32, Ks + 32, wr, 0, g, c, S);
        float rm0 = -INFINITY, rm1 = -INFINITY;
        #pragma unroll
        for (int ni = 0; ni < 8; ni++) {
            #pragma unroll
            for (int j = 0; j < 4; j++) S[0][ni][j] *= scale;
            rm0 = fmaxf(rm0, fmaxf(S[0][ni][0], S[0][ni][1]));
            rm1 = fmaxf(rm1, fmaxf(S[0][ni][2], S[0][ni][3]));
        }
        rm0 = fmaxf(rm0, __shfl_xor_sync(0xffffffffu, rm0, 1));
        rm0 = fmaxf(rm0, __shfl_xor_sync(0xffffffffu, rm0, 2));
        rm1 = fmaxf(rm1, __shfl_xor_sync(0xffffffffu, rm1, 1));
        rm1 = fmaxf(rm1, __shfl_xor_sync(0xffffffffu, rm1, 2));
        float mn0 = fmaxf(m0, rm0), mn1 = fmaxf(m1, rm1);
        float a0 = __expf(m0 - mn0), a1 = __expf(m1 - mn1);
        float ps0 = 0.f, ps1 = 0.f;
        #pragma unroll
        for (int ni = 0; ni < 8; ni++) {
            float p0 = __expf(S[0][ni][0] - mn0);
            float p1 = __expf(S[0][ni][1] - mn0);
            float p2 = __expf(S[0][ni][2] - mn1);
            float p3 = __expf(S[0][ni][3] - mn1);
            ps0 += p0 + p1; ps1 += p2 + p3;
            *(float2*)&Ps[(wr + g) * 68 + ni * 8 + 2 * c] = make_float2(p0, p1);
            *(float2*)&Ps[(wr + g + 8) * 68 + ni * 8 + 2 * c] = make_float2(p2, p3);
        }
        ps0 += __shfl_xor_sync(0xffffffffu, ps0, 1);
        ps0 += __shfl_xor_sync(0xffffffffu, ps0, 2);
        ps1 += __shfl_xor_sync(0xffffffffu, ps1, 1);
        ps1 += __shfl_xor_sync(0xffffffffu, ps1, 2);
        l0 = l0 * a0 + ps0;
        l1 = l1 * a1 + ps1;
        m0 = mn0; m1 = mn1;
        #pragma unroll
        for (int ni = 0; ni < 8; ni++) {
            Oa[0][ni][0] *= a0; Oa[0][ni][1] *= a0;
            Oa[0][ni][2] *= a1; Oa[0][ni][3] *= a1;
        }
        __syncwarp();
        // P unrounded -> cvt A; V pre-rounded -> raw B
        mma_tile<1, 8, true, 68, 68, true, false>(Ps, Vs, wr, 0, g, c, Oa);
        mma_tile<1, 8, true, 68, 68, true, false>(Ps + 32, Vs + 32 * 68, wr, 0, g, c, Oa);
        __syncthreads();
        if (it + 1 < niter) {
            const float* kg = Kg + (size_t)((it + 1) * FA_N + kr) * ldk + kcb;
            const float* vg = Vg + (size_t)((it + 1) * FA_N + kr) * ldv + kcb;
            uint32_t kb = ks0 + (kr * 68 + kcb) * 4;
            uint32_t vb = vs0 + (kr * 68 + kcb) * 4;
            #pragma unroll
            for (int j = 0; j < 4; j++) cp16(kb + j * 16, kg + j * 4);
            #pragma unroll
            for (int j = 0; j < 4; j++) cp16(vb + j * 16, vg + j * 4);
            cpcommit();
        }
    }
    float i0 = 1.f / l0, i1 = 1.f / l1;
    float* Og = O + ((size_t)(b * LL + q0 + wr)) * DD + h * DHH;
    #pragma unroll
    for (int ni = 0; ni < 8; ni++) {
        int cc = ni * 8 + 2 * c;
        *(float2*)(Og + (size_t)g * DD + cc) =
            make_float2(rnd_tf(Oa[0][ni][0] * i0), rnd_tf(Oa[0][ni][1] * i0));
        *(float2*)(Og + (size_t)(g + 8) * DD + cc) =
            make_float2(rnd_tf(Oa[0][ni][2] * i1), rnd_tf(Oa[0][ni][3] * i1));
    }
}

// ---------------- MoE routing ----------------
__global__ void moe_zero() {
    if (threadIdx.x < EE) g_cnt[threadIdx.x] = 0;
}

__global__ void __launch_bounds__(256) router_topk(const float* __restrict__ H,
                                                   const float* __restrict__ rw,
                                                   const float* __restrict__ rb) {
    int warp = (blockIdx.x * blockDim.x + threadIdx.x) >> 5;
    int lane = threadIdx.x & 31;
    if (warp >= NL) return;
    const float* h = H + (size_t)warp * DD;
    float logit[EE];
    #pragma unroll
    for (int e = 0; e < EE; e++) {
        const float* w = rw + (size_t)e * DD;
        float s = 0.f;
        for (int d = lane; d < DD; d += 32) s += h[d] * w[d];
        #pragma unroll
        for (int o = 16; o; o >>= 1) s += __shfl_xor_sync(0xffffffffu, s, o);
        logit[e] = s + rb[e];
    }
    if (lane == 0) {
        int i0 = 0; float m0 = logit[0];
        #pragma unroll
        for (int e = 1; e < EE; e++) if (logit[e] > m0) { m0 = logit[e]; i0 = e; }
        int i1 = -1; float m1 = -INFINITY;
        #pragma unroll
        for (int e = 0; e < EE; e++) if (e != i0 && logit[e] > m1) { m1 = logit[e]; i1 = e; }
        float z = expf(m1 - m0);
        float inv = 1.f / (1.f + z);
        g_idx[warp * 2] = i0;  g_idx[warp * 2 + 1] = i1;
        g_gate[warp * 2] = inv; g_gate[warp * 2 + 1] = z * inv;
        atomicAdd(&g_cnt[i0], 1);
        atomicAdd(&g_cnt[i1], 1);
    }
}

__global__ void moe_offsets() {
    if (threadIdx.x == 0) {
        int s = 0;
        for (int e = 0; e < EE; e++) { g_off[e] = s; s += g_cnt[e]; g_cur[e] = 0; }
    }
}

__global__ void __launch_bounds__(256) moe_assign() {
    int n = blockIdx.x * blockDim.x + threadIdx.x;
    if (n >= NL) return;
    #pragma unroll
    for (int k = 0; k < KKE; k++) {
        int e = g_idx[n * 2 + k];
        int pos = atomicAdd(&g_cur[e], 1);
        int slot = g_off[e] + pos;
        g_rowlist[slot] = n;
        g_pairslot[n * 2 + k] = slot;
    }
}

// ---------------- MoE grouped tf32 GEMM (fc1) ----------------
__global__ void __launch_bounds__(256, 2) moe_gemm_tf32(const float* __restrict__ A, int lda, int gather,
                                                        const float* __restrict__ W,
                                                        const float* __restrict__ bias,
                                                        int M, int Kd,
                                                        float* __restrict__ C, int ldc, int act) {
    extern __shared__ float sm[];
    int e = blockIdx.z;
    int count = g_cnt[e];
    int row0 = blockIdx.y * 128;
    if (row0 >= count) return;
    int base = g_off[e];
    const float* We = W + (size_t)e * M * Kd;
    const float* be = bias + (size_t)e * M;
    int col0 = blockIdx.x * 128;
    int t = threadIdx.x;
    int lrow = t >> 1, lcol = (t & 1) * 16;
    int arow = row0 + lrow;
    bool valid = arow < count;
    int src;
    if (gather) src = g_rowlist[base + (valid ? arow : 0)];
    else        src = base + (valid ? arow : 0);
    const float* Ag = A + (size_t)src * lda + lcol;
    const float* Wg = We + (size_t)(col0 + lrow) * Kd + lcol;
    uint32_t sm_u = (uint32_t)__cvta_generic_to_shared(sm);
    uint32_t as0 = sm_u + (lrow * 36 + lcol) * 4;
    uint32_t bs0 = sm_u + (TILE_AB + lrow * 36 + lcol) * 4;
    int warp = t >> 5, lane = t & 31, g = lane >> 2, c = lane & 3;
    int wm = (warp >> 2) * 64, wn = (warp & 3) * 32;
    uint32_t a_frag = sm_u + ((wm + (lane & 15)) * 36 + (lane >> 4) * 4) * 4;
    uint32_t b_frag = sm_u + (TILE_AB + (wn + ((lane >> 4) << 3) + (lane & 7)) * 36 + ((lane >> 3) & 1) * 4) * 4;
    float acc[4][4][4] = {};
    int KT = Kd >> 5;
    #pragma unroll
    for (int s = 0; s < 2; s++) {
        const float* a = Ag + s * 32;
        const float* w = Wg + s * 32;
        uint32_t so = (uint32_t)(s * STAGE_F * 4);
        #pragma unroll
        for (int i = 0; i < 4; i++) cp16p(as0 + so + i * 16, a + i * 4, valid);
        #pragma unroll
        for (int i = 0; i < 4; i++) cp16(bs0 + so + i * 16, w + i * 4);
        cpcommit();
    }
    int sl = 0;
    for (int kt = 0; kt < KT; kt++) {
        cpwait1();
        __syncthreads();
        if (kt + 2 < KT) {
            int sn = sl + 2; if (sn >= NST) sn -= NST;
            const float* a = Ag + (kt + 2) * 32;
            const float* w = Wg + (kt + 2) * 32;
            uint32_t so = (uint32_t)(sn * STAGE_F * 4);
            #pragma unroll
            for (int i = 0; i < 4; i++) cp16p(as0 + so + i * 16, a + i * 4, valid);
            #pragma unroll
            for (int i = 0; i < 4; i++) cp16(bs0 + so + i * 16, w + i * 4);
            cpcommit();
        }
        uint32_t so = (uint32_t)(sl * STAGE_F * 4);
        mma_slab(a_frag + so, b_frag + so, acc);
        if (++sl == NST) sl = 0;
    }
    #pragma unroll
    for (int mi = 0; mi < 4; mi++) {
        int r = row0 + wm + mi * 16 + g;
        #pragma unroll
        for (int ni = 0; ni < 4; ni++) {
            int cc = col0 + wn + ni * 8 + c * 2;
            float b0 = be[cc], b1 = be[cc + 1];
            if (r < count) {
                float v0 = acc[mi][ni][0] + b0, v1 = acc[mi][ni][1] + b1;
                if (act) { v0 = rnd_tf(gelu_exact(v0)); v1 = rnd_tf(gelu_exact(v1)); }
                *(float2*)(C + (size_t)(base + r) * ldc + cc) = make_float2(v0, v1);
            }
            if (r + 8 < count) {
                float v2 = acc[mi][ni][2] + b0, v3 = acc[mi][ni][3] + b1;
                if (act) { v2 = rnd_tf(gelu_exact(v2)); v3 = rnd_tf(gelu_exact(v3)); }
                *(float2*)(C + (size_t)(base + r + 8) * ldc + cc) = make_float2(v2, v3);
            }
        }
    }
}

// ---------------- MoE fc2 split-K ----------------
__global__ void __launch_bounds__(256, 2) moe_gemm_sk(const float* __restrict__ A, int lda,
                                                      const float* __restrict__ W,
                                                      const float* __restrict__ bias,
                                                      int M, int Kd,
                                                      float* __restrict__ part) {
    extern __shared__ float sm[];
    int e = blockIdx.z;
    int count = g_cnt[e];
    int rt = blockIdx.y & 15, kz = blockIdx.y >> 4;
    int row0 = rt * 128;
    if (row0 >= count) return;
    int Kh = Kd >> 1;
    int base = g_off[e];
    const float* We = W + (size_t)e * M * Kd;
    const float* be = bias + (size_t)e * M;
    int col0 = blockIdx.x * 128;
    int t = threadIdx.x;
    int lrow = t >> 1, lcol = (t & 1) * 16;
    int arow = row0 + lrow;
    bool valid = arow < count;
    int src = base + (valid ? arow : 0);
    const float* Ag = A + (size_t)src * lda + kz * Kh + lcol;
    const float* Wg = We + (size_t)(col0 + lrow) * Kd + kz * Kh + lcol;
    uint32_t sm_u = (uint32_t)__cvta_generic_to_shared(sm);
    uint32_t as0 = sm_u + (lrow * 36 + lcol) * 4;
    uint32_t bs0 = sm_u + (TILE_AB + lrow * 36 + lcol) * 4;
    int warp = t >> 5, lane = t & 31, g = lane >> 2, c = lane & 3;
    int wm = (warp >> 2) * 64, wn = (warp & 3) * 32;
    uint32_t a_frag = sm_u + ((wm + (lane & 15)) * 36 + (lane >> 4) * 4) * 4;
    uint32_t b_frag = sm_u + (TILE_AB + (wn + ((lane >> 4) << 3) + (lane & 7)) * 36 + ((lane >> 3) & 1) * 4) * 4;
    float acc[4][4][4] = {};
    int KT = Kh >> 5;
    #pragma unroll
    for (int s = 0; s < 2; s++) {
        const float* a = Ag + s * 32;
        const float* w = Wg + s * 32;
        uint32_t so = (uint32_t)(s * STAGE_F * 4);
        #pragma unroll
        for (int i = 0; i < 4; i++) cp16p(as0 + so + i * 16, a + i * 4, valid);
        #pragma unroll
        for (int i = 0; i < 4; i++) cp16(bs0 + so + i * 16, w + i * 4);
        cpcommit();
    }
    int sl = 0;
    for (int kt = 0; kt < KT; kt++) {
        cpwait1();
        __syncthreads();
        if (kt + 2 < KT) {
            int sn = sl + 2; if (sn >= NST) sn -= NST;
            const float* a = Ag + (kt + 2) * 32;
            const float* w = Wg + (kt + 2) * 32;
            uint32_t so = (uint32_t)(sn * STAGE_F * 4);
            #pragma unroll
            for (int i = 0; i < 4; i++) cp16p(as0 + so + i * 16, a + i * 4, valid);
            #pragma unroll
            for (int i = 0; i < 4; i++) cp16(bs0 + so + i * 16, w + i * 4);
            cpcommit();
        }
        uint32_t so = (uint32_t)(sl * STAGE_F * 4);
        mma_slab(a_frag + so, b_frag + so, acc);
        if (++sl == NST) sl = 0;
    }
    float* P = part + (size_t)kz * NL * KKE * DD;
    #pragma unroll
    for (int mi = 0; mi < 4; mi++) {
        int r = row0 + wm + mi * 16 + g;
        #pragma unroll
        for (int ni = 0; ni < 4; ni++) {
            int cc = col0 + wn + ni * 8 + c * 2;
            float b0 = (kz == 0) ? be[cc] : 0.f;
            float b1 = (kz == 0) ? be[cc + 1] : 0.f;
            if (r < count) {
                *(float2*)(P + (size_t)(base + r) * DD + cc) =
                    make_float2(acc[mi][ni][0] + b0, acc[mi][ni][1] + b1);
            }
            if (r + 8 < count) {
                *(float2*)(P + (size_t)(base + r + 8) * DD + cc) =
                    make_float2(acc[mi][ni][2] + b0, acc[mi][ni][3] + b1);
            }
        }
    }
}

__global__ void __launch_bounds__(256) moe_combine2(const float* __restrict__ part,
                                                    float* __restrict__ eo) {
    int i = blockIdx.x * 256 + threadIdx.x;
    eo[i] = part[i] + part[(size_t)NL * KKE * DD + i];
}

// ---------------- final mix ----------------
__global__ void __launch_bounds__(256) moe_mix(const float* __restrict__ x2,
                                               float* __restrict__ out) {
    int i = blockIdx.x * 256 + threadIdx.x;
    int n = i >> 10;
    int d = i & 1023;
    float v = x2[i];
    int s0 = g_pairslot[n * 2], s1 = g_pairslot[n * 2 + 1];
    v += g_gate[n * 2]     * g_eo[(size_t)s0 * DD + d];
    v += g_gate[n * 2 + 1] * g_eo[(size_t)s1 * DD + d];
    out[i] = v;
}

// ---------------- launch ----------------
extern "C" void kernel_launch(void* const* d_in, const int* in_sizes, int n_in,
                              void* d_out, int out_size) {
    const float* latents    = (const float*)d_in[0];
    const float* tokens     = (const float*)d_in[1];
    const float* sa_ln_g    = (const float*)d_in[2];
    const float* sa_ln_b    = (const float*)d_in[3];
    const float* sa_in_w    = (const float*)d_in[4];
    const float* sa_in_b    = (const float*)d_in[5];
    const float* sa_out_w   = (const float*)d_in[6];
    const float* sa_out_b   = (const float*)d_in[7];
    const float* ca_q_ln_g  = (const float*)d_in[8];
    const float* ca_q_ln_b  = (const float*)d_in[9];
    const float* ca_kv_ln_g = (const float*)d_in[10];
    const float* ca_kv_ln_b = (const float*)d_in[11];
    const float* ca_in_w    = (const float*)d_in[12];
    const float* ca_in_b    = (const float*)d_in[13];
    const float* ca_out_w   = (const float*)d_in[14];
    const float* ca_out_b   = (const float*)d_in[15];
    const float* moe_ln_g   = (const float*)d_in[16];
    const float* moe_ln_b   = (const float*)d_in[17];
    const float* router_w   = (const float*)d_in[18];
    const float* router_b   = (const float*)d_in[19];
    const float* e_fc1_w    = (const float*)d_in[20];
    const float* e_fc1_b    = (const float*)d_in[21];
    const float* e_fc2_w    = (const float*)d_in[22];
    const float* e_fc2_b    = (const float*)d_in[23];
    float* out = (float*)d_out;

    static int s_init = 0;
    static cudaStream_t s2;
    static cudaEvent_t ev_fork, ev_join, ev_join2;
    if (!s_init) {
        cudaFuncSetAttribute(gemm_tf32, cudaFuncAttributeMaxDynamicSharedMemorySize, GEMM_SMEM);
        cudaFuncSetAttribute(gemm_sk, cudaFuncAttributeMaxDynamicSharedMemorySize, GEMM_SMEM);
        cudaFuncSetAttribute(moe_gemm_tf32, cudaFuncAttributeMaxDynamicSharedMemorySize, GEMM_SMEM);
        cudaFuncSetAttribute(moe_gemm_sk, cudaFuncAttributeMaxDynamicSharedMemorySize, GEMM_SMEM);
        cudaFuncSetAttribute(flash_tf32, cudaFuncAttributeMaxDynamicSharedMemorySize, FA_SMEM);
        cudaStreamCreateWithFlags(&s2, cudaStreamNonBlocking);
        cudaEventCreateWithFlags(&ev_fork, cudaEventDisableTiming);
        cudaEventCreateWithFlags(&ev_join, cudaEventDisableTiming);
        cudaEventCreateWithFlags(&ev_join2, cudaEventDisableTiming);
        s_init = 1;
    }

    float *p_lnq, *p_lnr, *p_lnt, *p_qkv, *p_q2, *p_kv, *p_attn, *p_x1, *p_x2, *p_h1, *p_eo;
    float *p_part, *p_part2;
    float *w_sain, *w_saout, *w_cain, *w_caout, *w_fc1, *w_fc2;
    cudaGetSymbolAddress((void**)&p_lnq,  g_lnq);
    cudaGetSymbolAddress((void**)&p_lnr,  g_lnr);
    cudaGetSymbolAddress((void**)&p_lnt,  g_lnt);
    cudaGetSymbolAddress((void**)&p_qkv,  g_qkv);
    cudaGetSymbolAddress((void**)&p_q2,   g_q2);
    cudaGetSymbolAddress((void**)&p_kv,   g_kv);
    cudaGetSymbolAddress((void**)&p_attn, g_attn);
    cudaGetSymbolAddress((void**)&p_x1,   g_x1);
    cudaGetSymbolAddress((void**)&p_x2,   g_x2);
    cudaGetSymbolAddress((void**)&p_h1,   g_h1);
    cudaGetSymbolAddress((void**)&p_eo,   g_eo);
    cudaGetSymbolAddress((void**)&p_part, g_part);
    cudaGetSymbolAddress((void**)&p_part2, g_part2);
    cudaGetSymbolAddress((void**)&w_sain,  g_w_sain);
    cudaGetSymbolAddress((void**)&w_saout, g_w_saout);
    cudaGetSymbolAddress((void**)&w_cain,  g_w_cain);
    cudaGetSymbolAddress((void**)&w_caout, g_w_caout);
    cudaGetSymbolAddress((void**)&w_fc1,   g_w_fc1);
    cudaGetSymbolAddress((void**)&w_fc2,   g_w_fc2);

    const float scale = 0.125f;

    // ===== fork: side stream rounds big weights, does token LN + KV GEMM =====
    cudaEventRecord(ev_fork, 0);
    cudaStreamWaitEvent(s2, ev_fork, 0);
    rnd_w4<<<(3 * DD * DD / 4 + 255) / 256, 256, 0, s2>>>(ca_in_w, w_cain, 3 * DD * DD / 4);
    ln_kernel<<<NT, 256, 0, s2>>>(tokens, ca_kv_ln_g, ca_kv_ln_b, p_lnt, nullptr);
    gemm_tf32<<<dim3(16, 64), 256, GEMM_SMEM, s2>>>(p_lnt, DD, w_cain + (size_t)DD * DD, DD,
                                                    p_kv, 2 * DD, ca_in_b + DD, nullptr, 0, DD, 1);
    cudaEventRecord(ev_join, s2);
    rnd_w4<<<(EE * DFFN * DD / 4 + 255) / 256, 256, 0, s2>>>(e_fc1_w, w_fc1, EE * DFFN * DD / 4);
    rnd_w4<<<(EE * DD * DFFN / 4 + 255) / 256, 256, 0, s2>>>(e_fc2_w, w_fc2, EE * DD * DFFN / 4);
    cudaEventRecord(ev_join2, s2);

    // ===== main stream: small weight rounds + SA chain =====
    rnd_w4<<<(3 * DD * DD / 4 + 255) / 256, 256>>>(sa_in_w, w_sain, 3 * DD * DD / 4);
    rnd_w4<<<(DD * DD / 4 + 255) / 256, 256>>>(sa_out_w, w_saout, DD * DD / 4);
    rnd_w4<<<(DD * DD / 4 + 255) / 256, 256>>>(ca_out_w, w_caout, DD * DD / 4);
    ln_kernel<<<NL, 256>>>(latents, sa_ln_g, sa_ln_b, p_lnq, nullptr);
    gemm_tf32<<<dim3(24, 16), 256, GEMM_SMEM>>>(p_lnq, DD, w_sain, DD, p_qkv, 3 * DD,
                                                sa_in_b, nullptr, 0, DD, 1);
    flash_tf32<<<dim3(4, BHN), 256, FA_SMEM>>>(p_qkv, 3 * DD, p_qkv + DD, 3 * DD,
                                               p_qkv + 2 * DD, 3 * DD, p_attn, LL, scale);
    gemm_sk<<<dim3(8, 16, 2), 256, GEMM_SMEM>>>(p_attn, DD, w_saout, DD, p_part, 512);
    sk_combine<<<(NL * DD) / 256, 256>>>(p_part, sa_out_b, latents, DD, p_x1, DD, 0);

    // ===== Cross-attention (q side) =====
    ln_kernel<<<NL, 256>>>(p_x1, ca_q_ln_g, ca_q_ln_b, p_lnq, nullptr);
    cudaStreamWaitEvent(0, ev_join, 0);  // w_cain ready (and KV done)
    gemm_sk<<<dim3(8, 16, 2), 256, GEMM_SMEM>>>(p_lnq, DD, w_cain, DD, p_part, 512);
    sk_combine<<<(NL * DD) / 256, 256>>>(p_part, ca_in_b, nullptr, 0, p_q2, DD, 1);

    flash_tf32<<<dim3(4, BHN), 256, FA_SMEM>>>(p_q2, DD, p_kv, 2 * DD,
                                               p_kv + DD, 2 * DD, p_attn, TT, scale);
    gemm_sk<<<dim3(8, 16, 2), 256, GEMM_SMEM>>>(p_attn, DD, w_caout, DD, p_part, 512);
    sk_combine<<<(NL * DD) / 256, 256>>>(p_part, ca_out_b, p_x1, DD, p_x2, DD, 0);

    // ===== MoE =====
    ln_kernel<<<NL, 256>>>(p_x2, moe_ln_g, moe_ln_b, p_lnq, p_lnr);
    moe_zero<<<1, 32>>>();
    router_topk<<<NL / 8, 256>>>(p_lnr, router_w, router_b);
    moe_offsets<<<1, 1>>>();
    moe_assign<<<NL / 256, 256>>>();
    cudaStreamWaitEvent(0, ev_join2, 0);  // w_fc1/w_fc2 ready
    moe_gemm_tf32<<<dim3(DFFN / 128, 16, EE), 256, GEMM_SMEM>>>(p_lnq, DD, 1, w_fc1, e_fc1_b,
                                                                DFFN, DD, p_h1, DFFN, 1);
    moe_gemm_sk<<<dim3(DD / 128, 32, EE), 256, GEMM_SMEM>>>(p_h1, DFFN, w_fc2, e_fc2_b,
                                                            DD, DFFN, p_part2);
    moe_combine2<<<(NL * KKE * DD) / 256, 256>>>(p_part2, p_eo);
    moe_mix<<<(NL * DD) / 256, 256>>>(p_x2, out);
}

// round 15
// speedup vs baseline: 1.0430x; 1.0146x over previous
#include <cuda_runtime.h>
#include <math.h>
#include <stdint.h>

#define DD   1024
#define HH   16
#define DHH  64
#define BB   4
#define LL   512
#define TT   2048
#define EE   8
#define KKE  2
#define DFFN 4096
#define NL   (BB*LL)
#define NT   (BB*TT)
#define BHN  (BB*HH)
#define LN_EPS 1e-5f

// ---------------- scratch ----------------
__device__ float g_lnq[(size_t)NL*DD];
__device__ float g_lnr[(size_t)NL*DD];
__device__ float g_lnt[(size_t)NT*DD];
__device__ float g_qkv[(size_t)NL*3*DD];
__device__ float g_q2 [(size_t)NL*DD];
__device__ float g_kv [(size_t)NT*2*DD];
__device__ float g_attn[(size_t)NL*DD];
__device__ float g_x1 [(size_t)NL*DD];
__device__ float g_x2 [(size_t)NL*DD];
__device__ float g_h1 [(size_t)NL*KKE*DFFN];
__device__ float g_part [(size_t)2*NL*DD];
__device__ float g_part2[(size_t)2*NL*KKE*DD];
__device__ int   g_idx [NL*KKE];
__device__ float g_gate[NL*KKE];
__device__ int   g_cnt[EE];
__device__ int   g_off[EE];
__device__ int   g_cur[EE];
__device__ int   g_rowlist[NL*KKE];
__device__ int   g_pairslot[NL*KKE];
// tf32-pre-rounded weight copies
__device__ float g_w_sain [(size_t)3*DD*DD];
__device__ float g_w_saout[(size_t)DD*DD];
__device__ float g_w_cain [(size_t)3*DD*DD];
__device__ float g_w_caout[(size_t)DD*DD];
__device__ float g_w_fc1  [(size_t)EE*DFFN*DD];
__device__ float g_w_fc2  [(size_t)EE*DD*DFFN];

// ---------------- helpers ----------------
__device__ __forceinline__ float blk_sum(float v) {
    __shared__ float sh[32];
    int lane = threadIdx.x & 31, w = threadIdx.x >> 5;
    #pragma unroll
    for (int o = 16; o; o >>= 1) v += __shfl_xor_sync(0xffffffffu, v, o);
    if (lane == 0) sh[w] = v;
    __syncthreads();
    if (w == 0) {
        float x = (lane < (int)(blockDim.x >> 5)) ? sh[lane] : 0.f;
        #pragma unroll
        for (int o = 16; o; o >>= 1) x += __shfl_xor_sync(0xffffffffu, x, o);
        if (lane == 0) sh[0] = x;
    }
    __syncthreads();
    float r = sh[0];
    __syncthreads();
    return r;
}

__device__ __forceinline__ float gelu_exact(float x) {
    return 0.5f * x * (1.f + erff(x * 0.70710678118654752f));
}

// ---------------- tf32 mma primitives ----------------
__device__ __forceinline__ uint32_t f2tf(float f) {
    uint32_t u;
    asm("cvt.rna.tf32.f32 %0, %1;" : "=r"(u) : "f"(f));
    return u;
}
__device__ __forceinline__ float rnd_tf(float f) { return __uint_as_float(f2tf(f)); }

__device__ __forceinline__ void mma8(float* cr, const uint32_t* a, const uint32_t* b) {
    asm volatile(
        "mma.sync.aligned.m16n8k8.row.col.f32.tf32.tf32.f32 "
        "{%0,%1,%2,%3}, {%4,%5,%6,%7}, {%8,%9}, {%0,%1,%2,%3};"
        : "+f"(cr[0]), "+f"(cr[1]), "+f"(cr[2]), "+f"(cr[3])
        : "r"(a[0]), "r"(a[1]), "r"(a[2]), "r"(a[3]), "r"(b[0]), "r"(b[1]));
}

__device__ __forceinline__ void ldsm4(uint32_t* r, uint32_t addr) {
    asm volatile("ldmatrix.sync.aligned.m8n8.x4.shared.b16 {%0,%1,%2,%3}, [%4];"
        : "=r"(r[0]), "=r"(r[1]), "=r"(r[2]), "=r"(r[3]) : "r"(addr));
}

__device__ __forceinline__ void cp16(uint32_t dst, const void* src) {
    asm volatile("cp.async.cg.shared.global [%0], [%1], 16;" :: "r"(dst), "l"(src));
}
__device__ __forceinline__ void cp16p(uint32_t dst, const void* src, bool valid) {
    int sz = valid ? 16 : 0;
    asm volatile("cp.async.cg.shared.global [%0], [%1], 16, %2;" :: "r"(dst), "l"(src), "r"(sz));
}
__device__ __forceinline__ void cpcommit() { asm volatile("cp.async.commit_group;"); }
__device__ __forceinline__ void cpwait1() { asm volatile("cp.async.wait_group 1;"); }
__device__ __forceinline__ void cpwait0() { asm volatile("cp.async.wait_group 0;"); }

#define TILE_AB (128*36)
#define STAGE_F (2*TILE_AB)
#define NST 3
#define GEMM_SMEM (NST*STAGE_F*4)

// one 32-k slab, both operands pre-rounded -> raw bits.
__device__ __forceinline__ void mma_slab(uint32_t a_base, uint32_t b_base,
                                         float (&acc)[4][4][4]) {
    #pragma unroll
    for (int kk = 0; kk < 4; kk++) {
        uint32_t af[4][4];
        #pragma unroll
        for (int mi = 0; mi < 4; mi++)
            ldsm4(af[mi], a_base + (mi * 16 * 36 + kk * 8) * 4);
        uint32_t bq[2][4];
        #pragma unroll
        for (int np = 0; np < 2; np++)
            ldsm4(bq[np], b_base + (np * 16 * 36 + kk * 8) * 4);
        #pragma unroll
        for (int mi = 0; mi < 4; mi++) {
            #pragma unroll
            for (int np = 0; np < 2; np++) {
                mma8(acc[mi][np * 2 + 0], af[mi], &bq[np][0]);
                mma8(acc[mi][np * 2 + 1], af[mi], &bq[np][2]);
            }
        }
    }
}

template<int WM, int WN, bool BKN, int AST2, int BST, bool CVTA, bool CVTB>
__device__ __forceinline__ void mma_tile(const float* __restrict__ Ab,
                                         const float* __restrict__ Bb,
                                         int wm, int wn, int g, int c,
                                         float (&acc)[WM][WN][4]) {
    #pragma unroll
    for (int kk = 0; kk < 4; kk++) {
        const int k0 = kk * 8;
        uint32_t af[WM][4];
        #pragma unroll
        for (int mi = 0; mi < WM; mi++) {
            const float* Ar = Ab + (wm + mi * 16 + g) * AST2 + k0 + c;
            float a0 = Ar[0], a1 = Ar[8 * AST2], a2 = Ar[4], a3 = Ar[8 * AST2 + 4];
            af[mi][0] = CVTA ? f2tf(a0) : __float_as_uint(a0);
            af[mi][1] = CVTA ? f2tf(a1) : __float_as_uint(a1);
            af[mi][2] = CVTA ? f2tf(a2) : __float_as_uint(a2);
            af[mi][3] = CVTA ? f2tf(a3) : __float_as_uint(a3);
        }
        uint32_t bf[WN][2];
        #pragma unroll
        for (int ni = 0; ni < WN; ni++) {
            float b0, b1;
            if (BKN) {
                const float* Br = Bb + (k0 + c) * BST + wn + ni * 8 + g;
                b0 = Br[0]; b1 = Br[4 * BST];
            } else {
                const float* Br = Bb + (wn + ni * 8 + g) * BST + k0 + c;
                b0 = Br[0]; b1 = Br[4];
            }
            bf[ni][0] = CVTB ? f2tf(b0) : __float_as_uint(b0);
            bf[ni][1] = CVTB ? f2tf(b1) : __float_as_uint(b1);
        }
        #pragma unroll
        for (int mi = 0; mi < WM; mi++)
            #pragma unroll
            for (int ni = 0; ni < WN; ni++)
                mma8(acc[mi][ni], af[mi], bf[ni]);
    }
}

// ---------------- weight pre-round ----------------
__global__ void __launch_bounds__(256) rnd_w4(const float* __restrict__ s,
                                              float* __restrict__ d, int n4) {
    int i = blockIdx.x * 256 + threadIdx.x;
    if (i < n4) {
        float4 v = *(const float4*)(s + (size_t)i * 4);
        v.x = rnd_tf(v.x); v.y = rnd_tf(v.y); v.z = rnd_tf(v.z); v.w = rnd_tf(v.w);
        *(float4*)(d + (size_t)i * 4) = v;
    }
}

// ---------------- layernorm ----------------
__global__ void __launch_bounds__(256) ln_kernel(const float* __restrict__ x,
                                                 const float* __restrict__ g,
                                                 const float* __restrict__ b,
                                                 float* __restrict__ y,
                                                 float* __restrict__ yraw) {
    size_t row = blockIdx.x;
    const float* xr = x + row * DD;
    float* yr = y + row * DD;
    int t = threadIdx.x;
    float v[4];
    float s = 0.f;
    #pragma unroll
    for (int i = 0; i < 4; i++) { v[i] = xr[t + 256 * i]; s += v[i]; }
    s = blk_sum(s);
    float mean = s * (1.f / DD);
    float s2 = 0.f;
    #pragma unroll
    for (int i = 0; i < 4; i++) { float d = v[i] - mean; s2 += d * d; }
    s2 = blk_sum(s2);
    float inv = rsqrtf(s2 * (1.f / DD) + LN_EPS);
    #pragma unroll
    for (int i = 0; i < 4; i++) {
        int cc = t + 256 * i;
        float o = (v[i] - mean) * inv * g[cc] + b[cc];
        yr[cc] = rnd_tf(o);
        if (yraw) yraw[row * DD + cc] = o;
    }
}

// ---------------- fused split-K combine + residual + layernorm ----------------
// x = p0 + p1 + bias + resid ; write x ; LN(x) -> y (rounded) [+ yraw]
__global__ void __launch_bounds__(256) combine_ln(const float* __restrict__ part,
                                                  const float* __restrict__ bias,
                                                  const float* __restrict__ resid, int ldr,
                                                  float* __restrict__ x_out, int ldx,
                                                  const float* __restrict__ g,
                                                  const float* __restrict__ b,
                                                  float* __restrict__ y,
                                                  float* __restrict__ yraw) {
    size_t row = blockIdx.x;
    int t = threadIdx.x;
    const float* p0 = part + row * DD;
    const float* p1 = part + (size_t)NL * DD + row * DD;
    const float* rr = resid + row * ldr;
    float v[4];
    float s = 0.f;
    #pragma unroll
    for (int i = 0; i < 4; i++) {
        int cc = t + 256 * i;
        float x = p0[cc] + p1[cc] + bias[cc] + rr[cc];
        x_out[row * ldx + cc] = x;
        v[i] = x; s += x;
    }
    s = blk_sum(s);
    float mean = s * (1.f / DD);
    float s2 = 0.f;
    #pragma unroll
    for (int i = 0; i < 4; i++) { float d = v[i] - mean; s2 += d * d; }
    s2 = blk_sum(s2);
    float inv = rsqrtf(s2 * (1.f / DD) + LN_EPS);
    #pragma unroll
    for (int i = 0; i < 4; i++) {
        int cc = t + 256 * i;
        float o = (v[i] - mean) * inv * g[cc] + b[cc];
        y[row * DD + cc] = rnd_tf(o);
        if (yraw) yraw[row * DD + cc] = o;
    }
}

// ---------------- tf32 GEMM ----------------
__global__ void __launch_bounds__(256, 2) gemm_tf32(const float* __restrict__ A, int lda,
                                                    const float* __restrict__ W, int ldw,
                                                    float* __restrict__ C, int ldc,
                                                    const float* __restrict__ bias,
                                                    const float* __restrict__ resid, int ldr,
                                                    int Kd, int round_out) {
    extern __shared__ float sm[];
    int t = threadIdx.x;
    int row0 = blockIdx.y * 128, col0 = blockIdx.x * 128;
    int lrow = t >> 1, lcol = (t & 1) * 16;
    const float* Ag = A + (size_t)(row0 + lrow) * lda + lcol;
    const float* Wg = W + (size_t)(col0 + lrow) * ldw + lcol;
    uint32_t sm_u = (uint32_t)__cvta_generic_to_shared(sm);
    uint32_t as0 = sm_u + (lrow * 36 + lcol) * 4;
    uint32_t bs0 = sm_u + (TILE_AB + lrow * 36 + lcol) * 4;
    int warp = t >> 5, lane = t & 31, g = lane >> 2, c = lane & 3;
    int wm = (warp >> 2) * 64, wn = (warp & 3) * 32;
    uint32_t a_frag = sm_u + ((wm + (lane & 15)) * 36 + (lane >> 4) * 4) * 4;
    uint32_t b_frag = sm_u + (TILE_AB + (wn + ((lane >> 4) << 3) + (lane & 7)) * 36 + ((lane >> 3) & 1) * 4) * 4;
    float acc[4][4][4] = {};
    int KT = Kd >> 5;
    #pragma unroll
    for (int s = 0; s < 2; s++) {
        const float* a = Ag + s * 32;
        const float* w = Wg + s * 32;
        uint32_t so = (uint32_t)(s * STAGE_F * 4);
        #pragma unroll
        for (int i = 0; i < 4; i++) cp16(as0 + so + i * 16, a + i * 4);
        #pragma unroll
        for (int i = 0; i < 4; i++) cp16(bs0 + so + i * 16, w + i * 4);
        cpcommit();
    }
    int sl = 0;
    for (int kt = 0; kt < KT; kt++) {
        cpwait1();
        __syncthreads();
        if (kt + 2 < KT) {
            int sn = sl + 2; if (sn >= NST) sn -= NST;
            const float* a = Ag + (kt + 2) * 32;
            const float* w = Wg + (kt + 2) * 32;
            uint32_t so = (uint32_t)(sn * STAGE_F * 4);
            #pragma unroll
            for (int i = 0; i < 4; i++) cp16(as0 + so + i * 16, a + i * 4);
            #pragma unroll
            for (int i = 0; i < 4; i++) cp16(bs0 + so + i * 16, w + i * 4);
            cpcommit();
        }
        uint32_t so = (uint32_t)(sl * STAGE_F * 4);
        mma_slab(a_frag + so, b_frag + so, acc);
        if (++sl == NST) sl = 0;
    }
    #pragma unroll
    for (int mi = 0; mi < 4; mi++) {
        int r = row0 + wm + mi * 16 + g;
        #pragma unroll
        for (int ni = 0; ni < 4; ni++) {
            int cc = col0 + wn + ni * 8 + c * 2;
            float v0 = acc[mi][ni][0], v1 = acc[mi][ni][1];
            float v2 = acc[mi][ni][2], v3 = acc[mi][ni][3];
            if (bias) { float b0 = bias[cc], b1 = bias[cc + 1]; v0 += b0; v1 += b1; v2 += b0; v3 += b1; }
            if (resid) {
                const float* q0 = resid + (size_t)r * ldr + cc;
                const float* q1 = resid + (size_t)(r + 8) * ldr + cc;
                v0 += q0[0]; v1 += q0[1]; v2 += q1[0]; v3 += q1[1];
            }
            if (round_out) { v0 = rnd_tf(v0); v1 = rnd_tf(v1); v2 = rnd_tf(v2); v3 = rnd_tf(v3); }
            *(float2*)(C + (size_t)r * ldc + cc) = make_float2(v0, v1);
            *(float2*)(C + (size_t)(r + 8) * ldc + cc) = make_float2(v2, v3);
        }
    }
}

// ---------------- split-K tf32 GEMM ----------------
__global__ void __launch_bounds__(256, 2) gemm_sk(const float* __restrict__ A, int lda,
                                                  const float* __restrict__ W, int ldw,
                                                  float* __restrict__ part, int Kh) {
    extern __shared__ float sm[];
    int t = threadIdx.x;
    int z = blockIdx.z;
    int row0 = blockIdx.y * 128, col0 = blockIdx.x * 128;
    int lrow = t >> 1, lcol = (t & 1) * 16;
    const float* Ag = A + (size_t)(row0 + lrow) * lda + z * Kh + lcol;
    const float* Wg = W + (size_t)(col0 + lrow) * ldw + z * Kh + lcol;
    uint32_t sm_u = (uint32_t)__cvta_generic_to_shared(sm);
    uint32_t as0 = sm_u + (lrow * 36 + lcol) * 4;
    uint32_t bs0 = sm_u + (TILE_AB + lrow * 36 + lcol) * 4;
    int warp = t >> 5, lane = t & 31, g = lane >> 2, c = lane & 3;
    int wm = (warp >> 2) * 64, wn = (warp & 3) * 32;
    uint32_t a_frag = sm_u + ((wm + (lane & 15)) * 36 + (lane >> 4) * 4) * 4;
    uint32_t b_frag = sm_u + (TILE_AB + (wn + ((lane >> 4) << 3) + (lane & 7)) * 36 + ((lane >> 3) & 1) * 4) * 4;
    float acc[4][4][4] = {};
    int KT = Kh >> 5;
    #pragma unroll
    for (int s = 0; s < 2; s++) {
        const float* a = Ag + s * 32;
        const float* w = Wg + s * 32;
        uint32_t so = (uint32_t)(s * STAGE_F * 4);
        #pragma unroll
        for (int i = 0; i < 4; i++) cp16(as0 + so + i * 16, a + i * 4);
        #pragma unroll
        for (int i = 0; i < 4; i++) cp16(bs0 + so + i * 16, w + i * 4);
        cpcommit();
    }
    int sl = 0;
    for (int kt = 0; kt < KT; kt++) {
        cpwait1();
        __syncthreads();
        if (kt + 2 < KT) {
            int sn = sl + 2; if (sn >= NST) sn -= NST;
            const float* a = Ag + (kt + 2) * 32;
            const float* w = Wg + (kt + 2) * 32;
            uint32_t so = (uint32_t)(sn * STAGE_F * 4);
            #pragma unroll
            for (int i = 0; i < 4; i++) cp16(as0 + so + i * 16, a + i * 4);
            #pragma unroll
            for (int i = 0; i < 4; i++) cp16(bs0 + so + i * 16, w + i * 4);
            cpcommit();
        }
        uint32_t so = (uint32_t)(sl * STAGE_F * 4);
        mma_slab(a_frag + so, b_frag + so, acc);
        if (++sl == NST) sl = 0;
    }
    float* P = part + (size_t)z * NL * DD;
    #pragma unroll
    for (int mi = 0; mi < 4; mi++) {
        int r = row0 + wm + mi * 16 + g;
        #pragma unroll
        for (int ni = 0; ni < 4; ni++) {
            int cc = col0 + wn + ni * 8 + c * 2;
            *(float2*)(P + (size_t)r * DD + cc) = make_float2(acc[mi][ni][0], acc[mi][ni][1]);
            *(float2*)(P + (size_t)(r + 8) * DD + cc) = make_float2(acc[mi][ni][2], acc[mi][ni][3]);
        }
    }
}

// plain combiner (for ca_q projection -> q2)
__global__ void __launch_bounds__(256) sk_combine(const float* __restrict__ part,
                                                  const float* __restrict__ bias,
                                                  float* __restrict__ C, int ldc, int round_out) {
    int i = blockIdx.x * 256 + threadIdx.x;
    int r = i >> 10, d = i & 1023;
    float v = part[i] + part[(size_t)NL * DD + i] + bias[d];
    if (round_out) v = rnd_tf(v);
    C[(size_t)r * ldc + d] = v;
}

// ---------------- fused flash attention (tf32, single-buffer KV) ----------------
#define FA_N 64
#define FA_QS (128*68)
#define FA_KV (64*68)
#define FA_SMEM ((FA_QS + 2*FA_KV + FA_QS)*4)

__global__ void __launch_bounds__(256, 2) flash_tf32(const float* __restrict__ Q, int ldq,
                                                     const float* __restrict__ Kp, int ldk,
                                                     const float* __restrict__ Vp, int ldv,
                                                     float* __restrict__ O, int Lk, float scale) {
    extern __shared__ float sm[];
    float* Qs = sm;
    float* Ks = Qs + FA_QS;
    float* Vs = Ks + FA_KV;
    float* Ps = Vs + FA_KV;
    int bh = blockIdx.y, b = bh >> 4, h = bh & 15;
    int q0 = blockIdx.x * 128;
    int t = threadIdx.x;
    const float* Qg = Q + ((size_t)(b * LL + q0)) * ldq + h * DHH;
    const float* Kg = Kp + ((size_t)b * Lk) * ldk + h * DHH;
    const float* Vg = Vp + ((size_t)b * Lk) * ldv + h * DHH;
    uint32_t qs0 = (uint32_t)__cvta_generic_to_shared(Qs);
    uint32_t ks0 = (uint32_t)__cvta_generic_to_shared(Ks);
    uint32_t vs0 = (uint32_t)__cvta_generic_to_shared(Vs);
    {
        int row = t >> 1, segb = (t & 1) * 8;
        const float* qr = Qg + (size_t)row * ldq;
        #pragma unroll
        for (int j = 0; j < 8; j++)
            cp16(qs0 + (row * 68 + (segb + j) * 4) * 4, qr + (segb + j) * 4);
    }
    int kr = t >> 2, kcb = (t & 3) * 16;
    {
        const float* kg = Kg + (size_t)kr * ldk + kcb;
        const float* vg = Vg + (size_t)kr * ldv + kcb;
        uint32_t kb = ks0 + (kr * 68 + kcb) * 4;
        uint32_t vb = vs0 + (kr * 68 + kcb) * 4;
        #pragma unroll
        for (int j = 0; j < 4; j++) cp16(kb + j * 16, kg + j * 4);
        #pragma unroll
        for (int j = 0; j < 4; j++) cp16(vb + j * 16, vg + j * 4);
    }
    cpcommit();
    int warp = t >> 5, lane = t & 31, g = lane >> 2, c = lane & 3;
    int wr = warp * 16;
    float Oa[1][8][4] = {};
    float m0 = -INFINITY, m1 = -INFINITY, l0 = 0.f, l1 = 0.f;
    int niter = Lk / FA_N;
    for (int it = 0; it < niter; it++) {
        cpwait0();
        __syncthreads();
        float S[1][8][4] = {};
        mma_tile<1, 8, false, 68, 68, false, false>(Qs, Ks, wr, 0, g, c, S);
        mma_tile<1, 8, false, 68, 68, false, false>(Qs + 32, Ks + 32, wr, 0, g, c, S);
        float rm0 = -INFINITY, rm1 = -INFINITY;
        #pragma unroll
        for (int ni = 0; ni < 8; ni++) {
            #pragma unroll
            for (int j = 0; j < 4; j++) S[0][ni][j] *= scale;
            rm0 = fmaxf(rm0, fmaxf(S[0][ni][0], S[0][ni][1]));
            rm1 = fmaxf(rm1, fmaxf(S[0][ni][2], S[0][ni][3]));
        }
        rm0 = fmaxf(rm0, __shfl_xor_sync(0xffffffffu, rm0, 1));
        rm0 = fmaxf(rm0, __shfl_xor_sync(0xffffffffu, rm0, 2));
        rm1 = fmaxf(rm1, __shfl_xor_sync(0xffffffffu, rm1, 1));
        rm1 = fmaxf(rm1, __shfl_xor_sync(0xffffffffu, rm1, 2));
        float mn0 = fmaxf(m0, rm0), mn1 = fmaxf(m1, rm1);
        float a0 = __expf(m0 - mn0), a1 = __expf(m1 - mn1);
        float ps0 = 0.f, ps1 = 0.f;
        #pragma unroll
        for (int ni = 0; ni < 8; ni++) {
            float p0 = __expf(S[0][ni][0] - mn0);
            float p1 = __expf(S[0][ni][1] - mn0);
            float p2 = __expf(S[0][ni][2] - mn1);
            float p3 = __expf(S[0][ni][3] - mn1);
            ps0 += p0 + p1; ps1 += p2 + p3;
            *(float2*)&Ps[(wr + g) * 68 + ni * 8 + 2 * c] = make_float2(p0, p1);
            *(float2*)&Ps[(wr + g + 8) * 68 + ni * 8 + 2 * c] = make_float2(p2, p3);
        }
        ps0 += __shfl_xor_sync(0xffffffffu, ps0, 1);
        ps0 += __shfl_xor_sync(0xffffffffu, ps0, 2);
        ps1 += __shfl_xor_sync(0xffffffffu, ps1, 1);
        ps1 += __shfl_xor_sync(0xffffffffu, ps1, 2);
        l0 = l0 * a0 + ps0;
        l1 = l1 * a1 + ps1;
        m0 = mn0; m1 = mn1;
        #pragma unroll
        for (int ni = 0; ni < 8; ni++) {
            Oa[0][ni][0] *= a0; Oa[0][ni][1] *= a0;
            Oa[0][ni][2] *= a1; Oa[0][ni][3] *= a1;
        }
        __syncwarp();
        mma_tile<1, 8, true, 68, 68, true, false>(Ps, Vs, wr, 0, g, c, Oa);
        mma_tile<1, 8, true, 68, 68, true, false>(Ps + 32, Vs + 32 * 68, wr, 0, g, c, Oa);
        __syncthreads();
        if (it + 1 < niter) {
            const float* kg = Kg + (size_t)((it + 1) * FA_N + kr) * ldk + kcb;
            const float* vg = Vg + (size_t)((it + 1) * FA_N + kr) * ldv + kcb;
            uint32_t kb = ks0 + (kr * 68 + kcb) * 4;
            uint32_t vb = vs0 + (kr * 68 + kcb) * 4;
            #pragma unroll
            for (int j = 0; j < 4; j++) cp16(kb + j * 16, kg + j * 4);
            #pragma unroll
            for (int j = 0; j < 4; j++) cp16(vb + j * 16, vg + j * 4);
            cpcommit();
        }
    }
    float i0 = 1.f / l0, i1 = 1.f / l1;
    float* Og = O + ((size_t)(b * LL + q0 + wr)) * DD + h * DHH;
    #pragma unroll
    for (int ni = 0; ni < 8; ni++) {
        int cc = ni * 8 + 2 * c;
        *(float2*)(Og + (size_t)g * DD + cc) =
            make_float2(rnd_tf(Oa[0][ni][0] * i0), rnd_tf(Oa[0][ni][1] * i0));
        *(float2*)(Og + (size_t)(g + 8) * DD + cc) =
            make_float2(rnd_tf(Oa[0][ni][2] * i1), rnd_tf(Oa[0][ni][3] * i1));
    }
}

// ---------------- MoE routing ----------------
__global__ void moe_zero() {
    if (threadIdx.x < EE) g_cnt[threadIdx.x] = 0;
}

__global__ void __launch_bounds__(256) router_topk(const float* __restrict__ H,
                                                   const float* __restrict__ rw,
                                                   const float* __restrict__ rb) {
    int warp = (blockIdx.x * blockDim.x + threadIdx.x) >> 5;
    int lane = threadIdx.x & 31;
    if (warp >= NL) return;
    const float* h = H + (size_t)warp * DD;
    float logit[EE];
    #pragma unroll
    for (int e = 0; e < EE; e++) {
        const float* w = rw + (size_t)e * DD;
        float s = 0.f;
        for (int d = lane; d < DD; d += 32) s += h[d] * w[d];
        #pragma unroll
        for (int o = 16; o; o >>= 1) s += __shfl_xor_sync(0xffffffffu, s, o);
        logit[e] = s + rb[e];
    }
    if (lane == 0) {
        int i0 = 0; float m0 = logit[0];
        #pragma unroll
        for (int e = 1; e < EE; e++) if (logit[e] > m0) { m0 = logit[e]; i0 = e; }
        int i1 = -1; float m1 = -INFINITY;
        #pragma unroll
        for (int e = 0; e < EE; e++) if (e != i0 && logit[e] > m1) { m1 = logit[e]; i1 = e; }
        float z = expf(m1 - m0);
        float inv = 1.f / (1.f + z);
        g_idx[warp * 2] = i0;  g_idx[warp * 2 + 1] = i1;
        g_gate[warp * 2] = inv; g_gate[warp * 2 + 1] = z * inv;
        atomicAdd(&g_cnt[i0], 1);
        atomicAdd(&g_cnt[i1], 1);
    }
}

__global__ void moe_offsets() {
    if (threadIdx.x == 0) {
        int s = 0;
        for (int e = 0; e < EE; e++) { g_off[e] = s; s += g_cnt[e]; g_cur[e] = 0; }
    }
}

__global__ void __launch_bounds__(256) moe_assign() {
    int n = blockIdx.x * blockDim.x + threadIdx.x;
    if (n >= NL) return;
    #pragma unroll
    for (int k = 0; k < KKE; k++) {
        int e = g_idx[n * 2 + k];
        int pos = atomicAdd(&g_cur[e], 1);
        int slot = g_off[e] + pos;
        g_rowlist[slot] = n;
        g_pairslot[n * 2 + k] = slot;
    }
}

// ---------------- MoE grouped tf32 GEMM (fc1) ----------------
__global__ void __launch_bounds__(256, 2) moe_gemm_tf32(const float* __restrict__ A, int lda, int gather,
                                                        const float* __restrict__ W,
                                                        const float* __restrict__ bias,
                                                        int M, int Kd,
                                                        float* __restrict__ C, int ldc, int act) {
    extern __shared__ float sm[];
    int e = blockIdx.z;
    int count = g_cnt[e];
    int row0 = blockIdx.y * 128;
    if (row0 >= count) return;
    int base = g_off[e];
    const float* We = W + (size_t)e * M * Kd;
    const float* be = bias + (size_t)e * M;
    int col0 = blockIdx.x * 128;
    int t = threadIdx.x;
    int lrow = t >> 1, lcol = (t & 1) * 16;
    int arow = row0 + lrow;
    bool valid = arow < count;
    int src;
    if (gather) src = g_rowlist[base + (valid ? arow : 0)];
    else        src = base + (valid ? arow : 0);
    const float* Ag = A + (size_t)src * lda + lcol;
    const float* Wg = We + (size_t)(col0 + lrow) * Kd + lcol;
    uint32_t sm_u = (uint32_t)__cvta_generic_to_shared(sm);
    uint32_t as0 = sm_u + (lrow * 36 + lcol) * 4;
    uint32_t bs0 = sm_u + (TILE_AB + lrow * 36 + lcol) * 4;
    int warp = t >> 5, lane = t & 31, g = lane >> 2, c = lane & 3;
    int wm = (warp >> 2) * 64, wn = (warp & 3) * 32;
    uint32_t a_frag = sm_u + ((wm + (lane & 15)) * 36 + (lane >> 4) * 4) * 4;
    uint32_t b_frag = sm_u + (TILE_AB + (wn + ((lane >> 4) << 3) + (lane & 7)) * 36 + ((lane >> 3) & 1) * 4) * 4;
    float acc[4][4][4] = {};
    int KT = Kd >> 5;
    #pragma unroll
    for (int s = 0; s < 2; s++) {
        const float* a = Ag + s * 32;
        const float* w = Wg + s * 32;
        uint32_t so = (uint32_t)(s * STAGE_F * 4);
        #pragma unroll
        for (int i = 0; i < 4; i++) cp16p(as0 + so + i * 16, a + i * 4, valid);
        #pragma unroll
        for (int i = 0; i < 4; i++) cp16(bs0 + so + i * 16, w + i * 4);
        cpcommit();
    }
    int sl = 0;
    for (int kt = 0; kt < KT; kt++) {
        cpwait1();
        __syncthreads();
        if (kt + 2 < KT) {
            int sn = sl + 2; if (sn >= NST) sn -= NST;
            const float* a = Ag + (kt + 2) * 32;
            const float* w = Wg + (kt + 2) * 32;
            uint32_t so = (uint32_t)(sn * STAGE_F * 4);
            #pragma unroll
            for (int i = 0; i < 4; i++) cp16p(as0 + so + i * 16, a + i * 4, valid);
            #pragma unroll
            for (int i = 0; i < 4; i++) cp16(bs0 + so + i * 16, w + i * 4);
            cpcommit();
        }
        uint32_t so = (uint32_t)(sl * STAGE_F * 4);
        mma_slab(a_frag + so, b_frag + so, acc);
        if (++sl == NST) sl = 0;
    }
    #pragma unroll
    for (int mi = 0; mi < 4; mi++) {
        int r = row0 + wm + mi * 16 + g;
        #pragma unroll
        for (int ni = 0; ni < 4; ni++) {
            int cc = col0 + wn + ni * 8 + c * 2;
            float b0 = be[cc], b1 = be[cc + 1];
            if (r < count) {
                float v0 = acc[mi][ni][0] + b0, v1 = acc[mi][ni][1] + b1;
                if (act) { v0 = rnd_tf(gelu_exact(v0)); v1 = rnd_tf(gelu_exact(v1)); }
                *(float2*)(C + (size_t)(base + r) * ldc + cc) = make_float2(v0, v1);
            }
            if (r + 8 < count) {
                float v2 = acc[mi][ni][2] + b0, v3 = acc[mi][ni][3] + b1;
                if (act) { v2 = rnd_tf(gelu_exact(v2)); v3 = rnd_tf(gelu_exact(v3)); }
                *(float2*)(C + (size_t)(base + r + 8) * ldc + cc) = make_float2(v2, v3);
            }
        }
    }
}

// ---------------- MoE fc2 split-K ----------------
__global__ void __launch_bounds__(256, 2) moe_gemm_sk(const float* __restrict__ A, int lda,
                                                      const float* __restrict__ W,
                                                      const float* __restrict__ bias,
                                                      int M, int Kd,
                                                      float* __restrict__ part) {
    extern __shared__ float sm[];
    int e = blockIdx.z;
    int count = g_cnt[e];
    int rt = blockIdx.y & 15, kz = blockIdx.y >> 4;
    int row0 = rt * 128;
    if (row0 >= count) return;
    int Kh = Kd >> 1;
    int base = g_off[e];
    const float* We = W + (size_t)e * M * Kd;
    const float* be = bias + (size_t)e * M;
    int col0 = blockIdx.x * 128;
    int t = threadIdx.x;
    int lrow = t >> 1, lcol = (t & 1) * 16;
    int arow = row0 + lrow;
    bool valid = arow < count;
    int src = base + (valid ? arow : 0);
    const float* Ag = A + (size_t)src * lda + kz * Kh + lcol;
    const float* Wg = We + (size_t)(col0 + lrow) * Kd + kz * Kh + lcol;
    uint32_t sm_u = (uint32_t)__cvta_generic_to_shared(sm);
    uint32_t as0 = sm_u + (lrow * 36 + lcol) * 4;
    uint32_t bs0 = sm_u + (TILE_AB + lrow * 36 + lcol) * 4;
    int warp = t >> 5, lane = t & 31, g = lane >> 2, c = lane & 3;
    int wm = (warp >> 2) * 64, wn = (warp & 3) * 32;
    uint32_t a_frag = sm_u + ((wm + (lane & 15)) * 36 + (lane >> 4) * 4) * 4;
    uint32_t b_frag = sm_u + (TILE_AB + (wn + ((lane >> 4) << 3) + (lane & 7)) * 36 + ((lane >> 3) & 1) * 4) * 4;
    float acc[4][4][4] = {};
    int KT = Kh >> 5;
    #pragma unroll
    for (int s = 0; s < 2; s++) {
        const float* a = Ag + s * 32;
        const float* w = Wg + s * 32;
        uint32_t so = (uint32_t)(s * STAGE_F * 4);
        #pragma unroll
        for (int i = 0; i < 4; i++) cp16p(as0 + so + i * 16, a + i * 4, valid);
        #pragma unroll
        for (int i = 0; i < 4; i++) cp16(bs0 + so + i * 16, w + i * 4);
        cpcommit();
    }
    int sl = 0;
    for (int kt = 0; kt < KT; kt++) {
        cpwait1();
        __syncthreads();
        if (kt + 2 < KT) {
            int sn = sl + 2; if (sn >= NST) sn -= NST;
            const float* a = Ag + (kt + 2) * 32;
            const float* w = Wg + (kt + 2) * 32;
            uint32_t so = (uint32_t)(sn * STAGE_F * 4);
            #pragma unroll
            for (int i = 0; i < 4; i++) cp16p(as0 + so + i * 16, a + i * 4, valid);
            #pragma unroll
            for (int i = 0; i < 4; i++) cp16(bs0 + so + i * 16, w + i * 4);
            cpcommit();
        }
        uint32_t so = (uint32_t)(sl * STAGE_F * 4);
        mma_slab(a_frag + so, b_frag + so, acc);
        if (++sl == NST) sl = 0;
    }
    float* P = part + (size_t)kz * NL * KKE * DD;
    #pragma unroll
    for (int mi = 0; mi < 4; mi++) {
        int r = row0 + wm + mi * 16 + g;
        #pragma unroll
        for (int ni = 0; ni < 4; ni++) {
            int cc = col0 + wn + ni * 8 + c * 2;
            float b0 = (kz == 0) ? be[cc] : 0.f;
            float b1 = (kz == 0) ? be[cc + 1] : 0.f;
            if (r < count) {
                *(float2*)(P + (size_t)(base + r) * DD + cc) =
                    make_float2(acc[mi][ni][0] + b0, acc[mi][ni][1] + b1);
            }
            if (r + 8 < count) {
                *(float2*)(P + (size_t)(base + r + 8) * DD + cc) =
                    make_float2(acc[mi][ni][2] + b0, acc[mi][ni][3] + b1);
            }
        }
    }
}

// ---------------- final mix (reads fc2 partials directly; combine fused) ----------------
__global__ void __launch_bounds__(256) moe_mix(const float* __restrict__ x2,
                                               const float* __restrict__ part,
                                               float* __restrict__ out) {
    int i = blockIdx.x * 256 + threadIdx.x;
    int n = i >> 10;
    int d = i & 1023;
    float v = x2[i];
    const float* p1 = part + (size_t)NL * KKE * DD;
    int s0 = g_pairslot[n * 2], s1 = g_pairslot[n * 2 + 1];
    float e0 = part[(size_t)s0 * DD + d] + p1[(size_t)s0 * DD + d];
    float e1 = part[(size_t)s1 * DD + d] + p1[(size_t)s1 * DD + d];
    v += g_gate[n * 2] * e0 + g_gate[n * 2 + 1] * e1;
    out[i] = v;
}

// ---------------- launch ----------------
extern "C" void kernel_launch(void* const* d_in, const int* in_sizes, int n_in,
                              void* d_out, int out_size) {
    const float* latents    = (const float*)d_in[0];
    const float* tokens     = (const float*)d_in[1];
    const float* sa_ln_g    = (const float*)d_in[2];
    const float* sa_ln_b    = (const float*)d_in[3];
    const float* sa_in_w    = (const float*)d_in[4];
    const float* sa_in_b    = (const float*)d_in[5];
    const float* sa_out_w   = (const float*)d_in[6];
    const float* sa_out_b   = (const float*)d_in[7];
    const float* ca_q_ln_g  = (const float*)d_in[8];
    const float* ca_q_ln_b  = (const float*)d_in[9];
    const float* ca_kv_ln_g = (const float*)d_in[10];
    const float* ca_kv_ln_b = (const float*)d_in[11];
    const float* ca_in_w    = (const float*)d_in[12];
    const float* ca_in_b    = (const float*)d_in[13];
    const float* ca_out_w   = (const float*)d_in[14];
    const float* ca_out_b   = (const float*)d_in[15];
    const float* moe_ln_g   = (const float*)d_in[16];
    const float* moe_ln_b   = (const float*)d_in[17];
    const float* router_w   = (const float*)d_in[18];
    const float* router_b   = (const float*)d_in[19];
    const float* e_fc1_w    = (const float*)d_in[20];
    const float* e_fc1_b    = (const float*)d_in[21];
    const float* e_fc2_w    = (const float*)d_in[22];
    const float* e_fc2_b    = (const float*)d_in[23];
    float* out = (float*)d_out;

    static int s_init = 0;
    static cudaStream_t s2;
    static cudaEvent_t ev_fork, ev_join, ev_join2;
    if (!s_init) {
        cudaFuncSetAttribute(gemm_tf32, cudaFuncAttributeMaxDynamicSharedMemorySize, GEMM_SMEM);
        cudaFuncSetAttribute(gemm_sk, cudaFuncAttributeMaxDynamicSharedMemorySize, GEMM_SMEM);
        cudaFuncSetAttribute(moe_gemm_tf32, cudaFuncAttributeMaxDynamicSharedMemorySize, GEMM_SMEM);
        cudaFuncSetAttribute(moe_gemm_sk, cudaFuncAttributeMaxDynamicSharedMemorySize, GEMM_SMEM);
        cudaFuncSetAttribute(flash_tf32, cudaFuncAttributeMaxDynamicSharedMemorySize, FA_SMEM);
        cudaStreamCreateWithFlags(&s2, cudaStreamNonBlocking);
        cudaEventCreateWithFlags(&ev_fork, cudaEventDisableTiming);
        cudaEventCreateWithFlags(&ev_join, cudaEventDisableTiming);
        cudaEventCreateWithFlags(&ev_join2, cudaEventDisableTiming);
        s_init = 1;
    }

    float *p_lnq, *p_lnr, *p_lnt, *p_qkv, *p_q2, *p_kv, *p_attn, *p_x1, *p_x2, *p_h1;
    float *p_part, *p_part2;
    float *w_sain, *w_saout, *w_cain, *w_caout, *w_fc1, *w_fc2;
    cudaGetSymbolAddress((void**)&p_lnq,  g_lnq);
    cudaGetSymbolAddress((void**)&p_lnr,  g_lnr);
    cudaGetSymbolAddress((void**)&p_lnt,  g_lnt);
    cudaGetSymbolAddress((void**)&p_qkv,  g_qkv);
    cudaGetSymbolAddress((void**)&p_q2,   g_q2);
    cudaGetSymbolAddress((void**)&p_kv,   g_kv);
    cudaGetSymbolAddress((void**)&p_attn, g_attn);
    cudaGetSymbolAddress((void**)&p_x1,   g_x1);
    cudaGetSymbolAddress((void**)&p_x2,   g_x2);
    cudaGetSymbolAddress((void**)&p_h1,   g_h1);
    cudaGetSymbolAddress((void**)&p_part, g_part);
    cudaGetSymbolAddress((void**)&p_part2, g_part2);
    cudaGetSymbolAddress((void**)&w_sain,  g_w_sain);
    cudaGetSymbolAddress((void**)&w_saout, g_w_saout);
    cudaGetSymbolAddress((void**)&w_cain,  g_w_cain);
    cudaGetSymbolAddress((void**)&w_caout, g_w_caout);
    cudaGetSymbolAddress((void**)&w_fc1,   g_w_fc1);
    cudaGetSymbolAddress((void**)&w_fc2,   g_w_fc2);

    const float scale = 0.125f;

    // ===== fork: side stream rounds big weights, does token LN + KV GEMM =====
    cudaEventRecord(ev_fork, 0);
    cudaStreamWaitEvent(s2, ev_fork, 0);
    rnd_w4<<<(3 * DD * DD / 4 + 255) / 256, 256, 0, s2>>>(ca_in_w, w_cain, 3 * DD * DD / 4);
    ln_kernel<<<NT, 256, 0, s2>>>(tokens, ca_kv_ln_g, ca_kv_ln_b, p_lnt, nullptr);
    gemm_tf32<<<dim3(16, 64), 256, GEMM_SMEM, s2>>>(p_lnt, DD, w_cain + (size_t)DD * DD, DD,
                                                    p_kv, 2 * DD, ca_in_b + DD, nullptr, 0, DD, 1);
    cudaEventRecord(ev_join, s2);
    rnd_w4<<<(EE * DFFN * DD / 4 + 255) / 256, 256, 0, s2>>>(e_fc1_w, w_fc1, EE * DFFN * DD / 4);
    rnd_w4<<<(EE * DD * DFFN / 4 + 255) / 256, 256, 0, s2>>>(e_fc2_w, w_fc2, EE * DD * DFFN / 4);
    cudaEventRecord(ev_join2, s2);

    // ===== main stream: small weight rounds + SA chain =====
    rnd_w4<<<(3 * DD * DD / 4 + 255) / 256, 256>>>(sa_in_w, w_sain, 3 * DD * DD / 4);
    rnd_w4<<<(DD * DD / 4 + 255) / 256, 256>>>(sa_out_w, w_saout, DD * DD / 4);
    rnd_w4<<<(DD * DD / 4 + 255) / 256, 256>>>(ca_out_w, w_caout, DD * DD / 4);
    ln_kernel<<<NL, 256>>>(latents, sa_ln_g, sa_ln_b, p_lnq, nullptr);
    gemm_tf32<<<dim3(24, 16), 256, GEMM_SMEM>>>(p_lnq, DD, w_sain, DD, p_qkv, 3 * DD,
                                                sa_in_b, nullptr, 0, DD, 1);
    flash_tf32<<<dim3(4, BHN), 256, FA_SMEM>>>(p_qkv, 3 * DD, p_qkv + DD, 3 * DD,
                                               p_qkv + 2 * DD, 3 * DD, p_attn, LL, scale);
    gemm_sk<<<dim3(8, 16, 2), 256, GEMM_SMEM>>>(p_attn, DD, w_saout, DD, p_part, 512);
    // fused: x1 = combine + resid(latents); lnq = LN_ca_q(x1)
    combine_ln<<<NL, 256>>>(p_part, sa_out_b, latents, DD, p_x1, DD,
                            ca_q_ln_g, ca_q_ln_b, p_lnq, nullptr);

    // ===== Cross-attention (q side) =====
    cudaStreamWaitEvent(0, ev_join, 0);  // w_cain + KV ready
    gemm_sk<<<dim3(8, 16, 2), 256, GEMM_SMEM>>>(p_lnq, DD, w_cain, DD, p_part, 512);
    sk_combine<<<(NL * DD) / 256, 256>>>(p_part, ca_in_b, p_q2, DD, 1);

    flash_tf32<<<dim3(4, BHN), 256, FA_SMEM>>>(p_q2, DD, p_kv, 2 * DD,
                                               p_kv + DD, 2 * DD, p_attn, TT, scale);
    gemm_sk<<<dim3(8, 16, 2), 256, GEMM_SMEM>>>(p_attn, DD, w_caout, DD, p_part, 512);
    // fused: x2 = combine + resid(x1); lnq = LN_moe(x2), lnr = raw LN for router
    combine_ln<<<NL, 256>>>(p_part, ca_out_b, p_x1, DD, p_x2, DD,
                            moe_ln_g, moe_ln_b, p_lnq, p_lnr);

    // ===== MoE =====
    moe_zero<<<1, 32>>>();
    router_topk<<<NL / 8, 256>>>(p_lnr, router_w, router_b);
    moe_offsets<<<1, 1>>>();
    moe_assign<<<NL / 256, 256>>>();
    cudaStreamWaitEvent(0, ev_join2, 0);  // w_fc1/w_fc2 ready
    moe_gemm_tf32<<<dim3(DFFN / 128, 16, EE), 256, GEMM_SMEM>>>(p_lnq, DD, 1, w_fc1, e_fc1_b,
                                                                DFFN, DD, p_h1, DFFN, 1);
    moe_gemm_sk<<<dim3(DD / 128, 32, EE), 256, GEMM_SMEM>>>(p_h1, DFFN, w_fc2, e_fc2_b,
                                                            DD, DFFN, p_part2);
    moe_mix<<<(NL * DD) / 256, 256>>>(p_x2, p_part2, out);
}